// round 8
// baseline (speedup 1.0000x reference)
#include <cuda_runtime.h>
#include <cuda_bf16.h>
#include <cstdint>

// Problem constants (fixed by reference setup_inputs)
#define NTOK 16384
#define DM   1280
#define NH   16
#define HK   80
#define NSEGS 8
#define SEGL 2048

#define NEG_INF (__int_as_float(0xff800000))

// Scratch (allocation-free rule: __device__ globals)
__device__ float g_qkv[(size_t)NTOK * 3 * DM];            // [N][3*1280] fp32 (GEMM1 out)
__device__ __nv_bfloat16 g_ah[(size_t)NTOK * DM];         // GEMM A hi (hidden, then attn-out)
__device__ __nv_bfloat16 g_al[(size_t)NTOK * DM];         // GEMM A lo
__device__ __nv_bfloat16 g_bh[(size_t)3 * DM * DM];       // W^T hi [N][K]
__device__ __nv_bfloat16 g_bl[(size_t)3 * DM * DM];       // W^T lo [N][K]
__device__ __nv_bfloat16 g_qh[(size_t)NTOK * DM];         // q hi (rope'd, prescaled)
__device__ __nv_bfloat16 g_ql[(size_t)NTOK * DM];
__device__ __nv_bfloat16 g_kh[(size_t)NTOK * DM];         // k hi (rope'd)
__device__ __nv_bfloat16 g_kl[(size_t)NTOK * DM];
__device__ __nv_bfloat16 g_vh[(size_t)NTOK * DM];         // v hi
__device__ __nv_bfloat16 g_vl[(size_t)NTOK * DM];

// ---------------------------------------------------------------------------
// helpers
// ---------------------------------------------------------------------------
__device__ __forceinline__ uint32_t smem_u32(const void* p) {
    uint32_t a;
    asm("{ .reg .u64 t; cvta.to.shared.u64 t, %1; cvt.u32.u64 %0, t; }" : "=r"(a) : "l"(p));
    return a;
}
__device__ __forceinline__ void ldsm4(uint32_t* r, uint32_t addr) {
    asm volatile("ldmatrix.sync.aligned.m8n8.x4.shared.b16 {%0,%1,%2,%3}, [%4];"
                 : "=r"(r[0]), "=r"(r[1]), "=r"(r[2]), "=r"(r[3]) : "r"(addr));
}
__device__ __forceinline__ void ldsm4t(uint32_t* r, uint32_t addr) {
    asm volatile("ldmatrix.sync.aligned.m8n8.x4.trans.shared.b16 {%0,%1,%2,%3}, [%4];"
                 : "=r"(r[0]), "=r"(r[1]), "=r"(r[2]), "=r"(r[3]) : "r"(addr));
}
__device__ __forceinline__ void mma16816(float* d, const uint32_t* a, uint32_t b0, uint32_t b1) {
    asm volatile("mma.sync.aligned.m16n8k16.row.col.f32.bf16.bf16.f32 "
                 "{%0,%1,%2,%3}, {%4,%5,%6,%7}, {%8,%9}, {%0,%1,%2,%3};"
                 : "+f"(d[0]), "+f"(d[1]), "+f"(d[2]), "+f"(d[3])
                 : "r"(a[0]), "r"(a[1]), "r"(a[2]), "r"(a[3]), "r"(b0), "r"(b1));
}
__device__ __forceinline__ uint32_t cvt_bf2(float hi, float lo) {
    uint32_t d;
    asm("cvt.rn.bf16x2.f32 %0, %1, %2;" : "=r"(d) : "f"(hi), "f"(lo));
    return d;
}
__device__ __forceinline__ void cpa16(uint32_t dst, const void* src) {
    asm volatile("cp.async.cg.shared.global [%0], [%1], 16;" :: "r"(dst), "l"(src));
}
#define CP_COMMIT() asm volatile("cp.async.commit_group;")
#define CP_WAIT0()  asm volatile("cp.async.wait_group 0;")
#define CP_WAIT1()  asm volatile("cp.async.wait_group 1;")
// FMA-pipe exp2 for t <= 0 (clamped), ~3e-6 rel error
__device__ __forceinline__ float exp2p(float t) {
    t = fmaxf(t, -126.f);
    const float z = t + 12582912.f;
    const int n = __float_as_int(z) - 0x4B400000;
    const float f = t - (z - 12582912.f);
    float r = 1.3333558146e-3f;
    r = fmaf(r, f, 9.6181291076e-3f);
    r = fmaf(r, f, 5.5504108664e-2f);
    r = fmaf(r, f, 2.4022650695e-1f);
    r = fmaf(r, f, 6.9314718055e-1f);
    r = fmaf(r, f, 1.0f);
    return __int_as_float(__float_as_int(r) + (n << 23));
}
__device__ __forceinline__ void split_store(__nv_bfloat16* hp, __nv_bfloat16* lp,
                                            size_t o, float v) {
    const __nv_bfloat16 h = __float2bfloat16(v);
    hp[o] = h;
    lp[o] = __float2bfloat16(v - __bfloat162float(h));
}

// ---------------------------------------------------------------------------
// split: fp32 -> bf16 hi + bf16 lo, vectorized by 4
// ---------------------------------------------------------------------------
__global__ __launch_bounds__(256) void split_kernel(
    const float* __restrict__ in, __nv_bfloat16* __restrict__ hi,
    __nv_bfloat16* __restrict__ lo, int n4)
{
    const int i = blockIdx.x * blockDim.x + threadIdx.x;
    if (i >= n4) return;
    const float4 v = ((const float4*)in)[i];
    __nv_bfloat16 h0 = __float2bfloat16(v.x);
    __nv_bfloat16 h1 = __float2bfloat16(v.y);
    __nv_bfloat16 h2 = __float2bfloat16(v.z);
    __nv_bfloat16 h3 = __float2bfloat16(v.w);
    __nv_bfloat162 hp0 = {h0, h1}, hp1 = {h2, h3};
    __nv_bfloat162 lp0 = {__float2bfloat16(v.x - __bfloat162float(h0)),
                          __float2bfloat16(v.y - __bfloat162float(h1))};
    __nv_bfloat162 lp1 = {__float2bfloat16(v.z - __bfloat162float(h2)),
                          __float2bfloat16(v.w - __bfloat162float(h3))};
    ((__nv_bfloat162*)hi)[i * 2 + 0] = hp0;
    ((__nv_bfloat162*)hi)[i * 2 + 1] = hp1;
    ((__nv_bfloat162*)lo)[i * 2 + 0] = lp0;
    ((__nv_bfloat162*)lo)[i * 2 + 1] = lp1;
}

// ---------------------------------------------------------------------------
// transpose + split: W[K][N] row-major -> WT hi/lo [N][K] bf16
// ---------------------------------------------------------------------------
__global__ void transpose_split_kernel(
    const float* __restrict__ W, __nv_bfloat16* __restrict__ bh,
    __nv_bfloat16* __restrict__ bl, int Krows, int Ncols)
{
    __shared__ float t[32][33];
    const int bx = blockIdx.x * 32;
    const int by = blockIdx.y * 32;
    const int x = threadIdx.x, y = threadIdx.y;
#pragma unroll
    for (int i = 0; i < 32; i += 8)
        t[y + i][x] = W[(size_t)(by + y + i) * Ncols + bx + x];
    __syncthreads();
#pragma unroll
    for (int i = 0; i < 32; i += 8) {
        const float v = t[x][y + i];
        split_store(bh, bl, (size_t)(bx + y + i) * Krows + by + x, v);
    }
}

// ---------------------------------------------------------------------------
// fused RoPE + bf16 split: g_qkv -> qh/ql (prescaled), kh/kl, vh/vl
// ---------------------------------------------------------------------------
__global__ __launch_bounds__(256) void rope_split_kernel(
    const float* __restrict__ qkv, const float* __restrict__ cosNK,
    const float* __restrict__ sinNK,
    __nv_bfloat16* __restrict__ qh, __nv_bfloat16* __restrict__ ql,
    __nv_bfloat16* __restrict__ kh, __nv_bfloat16* __restrict__ kl,
    __nv_bfloat16* __restrict__ vh, __nv_bfloat16* __restrict__ vl)
{
    const int t = blockIdx.x * blockDim.x + threadIdx.x;
    if (t >= NTOK * NH * 40) return;
    const int j = t % 40;
    const int h = (t / 40) % NH;
    const int n = t / (40 * NH);

    const float c1 = cosNK[n * HK + j];
    const float s1 = sinNK[n * HK + j];
    const float c2 = cosNK[n * HK + j + 40];
    const float s2 = sinNK[n * HK + j + 40];

    const size_t ib = (size_t)n * (3 * DM) + h * HK;
    const size_t ob = (size_t)n * DM + h * HK;
    const float qs = 0.1118033988749895f * 1.4426950408889634f;  // scale * log2(e)

    {
        const float x1 = qkv[ib + j], x2 = qkv[ib + j + 40];
        split_store(qh, ql, ob + j,      (x1 * c1 - x2 * s1) * qs);
        split_store(qh, ql, ob + j + 40, (x2 * c2 + x1 * s2) * qs);
    }
    {
        const float x1 = qkv[ib + DM + j], x2 = qkv[ib + DM + j + 40];
        split_store(kh, kl, ob + j,      x1 * c1 - x2 * s1);
        split_store(kh, kl, ob + j + 40, x2 * c2 + x1 * s2);
    }
    {
        split_store(vh, vl, ob + j,      qkv[ib + 2 * DM + j]);
        split_store(vh, vl, ob + j + 40, qkv[ib + 2 * DM + j + 40]);
    }
}

// ---------------------------------------------------------------------------
// bf16 3-split tensor-core GEMM + bias, 3-stage cp.async pipeline
// ---------------------------------------------------------------------------
#define GP 40
#define BUFE (128 * GP)
#define NSTG 3
#define GSMEM (4 * NSTG * BUFE * 2)

__global__ __launch_bounds__(256) void gemm_mma(
    const __nv_bfloat16* __restrict__ Ah, const __nv_bfloat16* __restrict__ Al,
    const __nv_bfloat16* __restrict__ Bh, const __nv_bfloat16* __restrict__ Bl,
    const float* __restrict__ bias, float* __restrict__ C, int N, int Kd)
{
    extern __shared__ __nv_bfloat16 smb[];
    __nv_bfloat16* Ash = smb;
    __nv_bfloat16* Asl = Ash + NSTG * BUFE;
    __nv_bfloat16* Bsh = Asl + NSTG * BUFE;
    __nv_bfloat16* Bsl = Bsh + NSTG * BUFE;

    const int tid = threadIdx.x;
    const int lane = tid & 31;
    const int warp = tid >> 5;
    const int wm = warp >> 1;
    const int wn = warp & 1;
    const int m0 = blockIdx.y * 128;
    const int n0 = blockIdx.x * 128;

    const int r0 = tid >> 2;
    const int sg = (tid & 3) * 8;

    const __nv_bfloat16* pAh = Ah + (size_t)(m0 + r0) * Kd + sg;
    const __nv_bfloat16* pAl = Al + (size_t)(m0 + r0) * Kd + sg;
    const __nv_bfloat16* pBh = Bh + (size_t)(n0 + r0) * Kd + sg;
    const __nv_bfloat16* pBl = Bl + (size_t)(n0 + r0) * Kd + sg;
    const size_t rstep = (size_t)64 * Kd;

    const uint32_t uAsh = smem_u32(Ash);
    const uint32_t uAsl = smem_u32(Asl);
    const uint32_t uBsh = smem_u32(Bsh);
    const uint32_t uBsl = smem_u32(Bsl);

    float acc[2][8][4];
#pragma unroll
    for (int a = 0; a < 2; a++)
#pragma unroll
        for (int b = 0; b < 8; b++)
#pragma unroll
            for (int c = 0; c < 4; c++) acc[a][b][c] = 0.f;

    auto issue = [&](int k0, int stg) {
        const uint32_t o0 = (uint32_t)(stg * BUFE + r0 * GP + sg) * 2;
        const uint32_t o1 = (uint32_t)(stg * BUFE + (r0 + 64) * GP + sg) * 2;
        cpa16(uAsh + o0, pAh + k0);  cpa16(uAsh + o1, pAh + k0 + rstep);
        cpa16(uAsl + o0, pAl + k0);  cpa16(uAsl + o1, pAl + k0 + rstep);
        cpa16(uBsh + o0, pBh + k0);  cpa16(uBsh + o1, pBh + k0 + rstep);
        cpa16(uBsl + o0, pBl + k0);  cpa16(uBsl + o1, pBl + k0 + rstep);
        CP_COMMIT();
    };

    const uint32_t aoff = (uint32_t)((wm * 32 + (lane & 15)) * GP + ((lane >> 4) << 3)) * 2;
    const uint32_t boff = (uint32_t)((wn * 64 + (lane & 15)) * GP + ((lane >> 4) << 3)) * 2;

    const int NT = Kd >> 5;
    issue(0, 0);
    if (NT > 1) issue(32, 1);

    int stg = 0;
    for (int t = 0; t < NT; ++t) {
        CP_WAIT1();
        __syncthreads();
        if (t + 2 < NT) issue((t + 2) << 5, (stg + 2) % NSTG);

        const uint32_t bb = (uint32_t)(stg * BUFE * 2);
#pragma unroll
        for (int ks = 0; ks < 2; ++ks) {
            const uint32_t kso = (uint32_t)(ks * 16 * 2);
            uint32_t ah[2][4], al[2][4];
#pragma unroll
            for (int t2 = 0; t2 < 2; ++t2) {
                const uint32_t ad = bb + aoff + kso + (uint32_t)(t2 * 16 * GP * 2);
                ldsm4(ah[t2], uAsh + ad);
                ldsm4(al[t2], uAsl + ad);
            }
            uint32_t bh4[4][4], bl4[4][4];
#pragma unroll
            for (int g = 0; g < 4; ++g) {
                const uint32_t bd = bb + boff + kso + (uint32_t)(g * 16 * GP * 2);
                ldsm4(bh4[g], uBsh + bd);
                ldsm4(bl4[g], uBsl + bd);
            }
#pragma unroll
            for (int t2 = 0; t2 < 2; ++t2)
#pragma unroll
                for (int g = 0; g < 4; ++g)
#pragma unroll
                    for (int h = 0; h < 2; ++h) {
                        float* d = acc[t2][g * 2 + h];
                        mma16816(d, ah[t2], bh4[g][h], bh4[g][h + 2]);
                        mma16816(d, ah[t2], bl4[g][h], bl4[g][h + 2]);
                        mma16816(d, al[t2], bh4[g][h], bh4[g][h + 2]);
                    }
        }
        stg = (stg + 1) % NSTG;
    }

#pragma unroll
    for (int t2 = 0; t2 < 2; ++t2) {
        const int row = m0 + wm * 32 + t2 * 16 + (lane >> 2);
#pragma unroll
        for (int n8 = 0; n8 < 8; ++n8) {
            const int col = n0 + wn * 64 + n8 * 8 + (lane & 3) * 2;
            const float b0 = __ldg(bias + col);
            const float b1 = __ldg(bias + col + 1);
            float2 v0 = {acc[t2][n8][0] + b0, acc[t2][n8][1] + b1};
            float2 v1 = {acc[t2][n8][2] + b0, acc[t2][n8][3] + b1};
            *(float2*)(C + (size_t)row * N + col) = v0;
            *(float2*)(C + (size_t)(row + 8) * N + col) = v1;
        }
    }
}

// ---------------------------------------------------------------------------
// Tensor-core flash attention, 128-query tile, 8 warps, pre-split inputs,
// cp.async double-buffered K/V. Epilogue writes bf16 hi/lo for GEMM2.
// ---------------------------------------------------------------------------
#define AP 88
#define KVB (64 * AP)
#define QTB (128 * AP)
#define ATT_SMEM ((2 * QTB + 8 * KVB) * 2)

__global__ __launch_bounds__(256) void attn_mma(
    const __nv_bfloat16* __restrict__ qh, const __nv_bfloat16* __restrict__ ql,
    const __nv_bfloat16* __restrict__ kh, const __nv_bfloat16* __restrict__ kl,
    const __nv_bfloat16* __restrict__ vh, const __nv_bfloat16* __restrict__ vl,
    __nv_bfloat16* __restrict__ oh, __nv_bfloat16* __restrict__ ol)
{
    extern __shared__ __nv_bfloat16 smb2[];
    __nv_bfloat16* Qh = smb2;            // [128][AP]
    __nv_bfloat16* Ql = Qh + QTB;
    __nv_bfloat16* KV = Ql + QTB;        // [2 buf][4 arr][64][AP]

    const int tid = threadIdx.x;
    const int lane = tid & 31;
    const int warp = tid >> 5;
    const int qt = blockIdx.x, head = blockIdx.y, seg = blockIdx.z;
    const int n0 = seg * SEGL + qt * 128;

    const uint32_t uKV = smem_u32(KV);

    auto issueKV = [&](int kb, int buf) {
        const int nk = seg * SEGL + kb * 64;
        const uint32_t bofs = (uint32_t)(buf * 4 * KVB) * 2;
#pragma unroll
        for (int i = 0; i < 3; ++i) {
            const int idx = tid + i * 256;
            if (idx < 640) {
                const int r = idx / 10, c = idx % 10;
                const uint32_t d = bofs + (uint32_t)(r * AP + c * 8) * 2 + uKV;
                const size_t g = (size_t)(nk + r) * DM + head * HK + c * 8;
                cpa16(d + 0 * KVB * 2, kh + g);
                cpa16(d + 1 * KVB * 2, kl + g);
                cpa16(d + 2 * KVB * 2, vh + g);
                cpa16(d + 3 * KVB * 2, vl + g);
            }
        }
        CP_COMMIT();
    };

    issueKV(0, 0);

    // load Q tile (pre-scaled, pre-split): 128 rows x 10 16B-groups
#pragma unroll
    for (int i = 0; i < 5; ++i) {
        const int idx = tid + i * 256;
        const int r = idx / 10, c = idx % 10;
        const size_t g = (size_t)(n0 + r) * DM + head * HK + c * 8;
        *(uint4*)(Qh + r * AP + c * 8) = *(const uint4*)(qh + g);
        *(uint4*)(Ql + r * AP + c * 8) = *(const uint4*)(ql + g);
    }
    __syncthreads();

    uint32_t qfh[5][4], qfl[5][4];
    {
        const uint32_t uQh = smem_u32(Qh), uQl = smem_u32(Ql);
        const uint32_t qoff = (uint32_t)((warp * 16 + (lane & 15)) * AP + ((lane >> 4) << 3)) * 2;
#pragma unroll
        for (int ks = 0; ks < 5; ++ks) {
            const uint32_t ad = qoff + (uint32_t)(ks * 16 * 2);
            ldsm4(qfh[ks], uQh + ad);
            ldsm4(qfl[ks], uQl + ad);
        }
    }

    const uint32_t koff = (uint32_t)((lane & 15) * AP + ((lane >> 4) << 3)) * 2;
    const uint32_t voff = (uint32_t)((((lane & 7) + (((lane >> 3) & 1) << 3)) * AP) + ((lane >> 4) << 3)) * 2;

    float of[10][4];
#pragma unroll
    for (int t = 0; t < 10; t++)
#pragma unroll
        for (int j = 0; j < 4; j++) of[t][j] = 0.f;
    float m_a = -1e30f, m_b = -1e30f, l_a = 0.f, l_b = 0.f;

    for (int kb = 0; kb < SEGL / 64; ++kb) {
        CP_WAIT0();
        __syncthreads();
        if (kb + 1 < SEGL / 64) issueKV(kb + 1, (kb + 1) & 1);

        const uint32_t bb = (uint32_t)((kb & 1) * 4 * KVB) * 2;
        const uint32_t uKh = uKV + bb;
        const uint32_t uKl = uKh + KVB * 2;
        const uint32_t uVh = uKl + KVB * 2;
        const uint32_t uVl = uVh + KVB * 2;

        // ---- S = Q @ K^T (3-term) ----
        float s[8][4];
#pragma unroll
        for (int t = 0; t < 8; t++)
#pragma unroll
            for (int j = 0; j < 4; j++) s[t][j] = 0.f;

#pragma unroll
        for (int ks = 0; ks < 5; ++ks) {
#pragma unroll
            for (int g = 0; g < 4; ++g) {
                uint32_t kfh[4], kfl[4];
                const uint32_t ka = koff + (uint32_t)((g * 16 * AP + ks * 16) * 2);
                ldsm4(kfh, uKh + ka);
                ldsm4(kfl, uKl + ka);
#pragma unroll
                for (int h = 0; h < 2; ++h) {
                    float* d = s[2 * g + h];
                    mma16816(d, qfh[ks], kfh[h], kfh[h + 2]);
                    mma16816(d, qfh[ks], kfl[h], kfl[h + 2]);
                    mma16816(d, qfl[ks], kfh[h], kfh[h + 2]);
                }
            }
        }

        // ---- online softmax (exp2 domain) ----
        float rma = NEG_INF, rmb = NEG_INF;
#pragma unroll
        for (int t = 0; t < 8; t++) {
            rma = fmaxf(rma, fmaxf(s[t][0], s[t][1]));
            rmb = fmaxf(rmb, fmaxf(s[t][2], s[t][3]));
        }
        rma = fmaxf(rma, __shfl_xor_sync(0xffffffffu, rma, 1));
        rma = fmaxf(rma, __shfl_xor_sync(0xffffffffu, rma, 2));
        rmb = fmaxf(rmb, __shfl_xor_sync(0xffffffffu, rmb, 1));
        rmb = fmaxf(rmb, __shfl_xor_sync(0xffffffffu, rmb, 2));
        const float mna = fmaxf(m_a, rma), mnb = fmaxf(m_b, rmb);
        const float corra = exp2p(m_a - mna), corrb = exp2p(m_b - mnb);
        m_a = mna; m_b = mnb;

        float suma = 0.f, sumb = 0.f;
        uint32_t pha[8], phb[8], pla[8], plb[8];
#pragma unroll
        for (int t = 0; t < 8; t++) {
            const float p0 = exp2p(s[t][0] - m_a);
            const float p1 = exp2p(s[t][1] - m_a);
            const float p2 = exp2p(s[t][2] - m_b);
            const float p3 = exp2p(s[t][3] - m_b);
            suma += p0 + p1;
            sumb += p2 + p3;
            const uint32_t ha = cvt_bf2(p1, p0);
            const uint32_t hb = cvt_bf2(p3, p2);
            pha[t] = ha; phb[t] = hb;
            const float h0 = __int_as_float(ha << 16);
            const float h1 = __int_as_float(ha & 0xFFFF0000u);
            const float h2 = __int_as_float(hb << 16);
            const float h3 = __int_as_float(hb & 0xFFFF0000u);
            pla[t] = cvt_bf2(p1 - h1, p0 - h0);
            plb[t] = cvt_bf2(p3 - h3, p2 - h2);
        }
        suma += __shfl_xor_sync(0xffffffffu, suma, 1);
        suma += __shfl_xor_sync(0xffffffffu, suma, 2);
        sumb += __shfl_xor_sync(0xffffffffu, sumb, 1);
        sumb += __shfl_xor_sync(0xffffffffu, sumb, 2);
        l_a = l_a * corra + suma;
        l_b = l_b * corrb + sumb;
#pragma unroll
        for (int t = 0; t < 10; t++) {
            of[t][0] *= corra;
            of[t][1] *= corra;
            of[t][2] *= corrb;
            of[t][3] *= corrb;
        }

        // ---- O += P @ V (3-term) ----
#pragma unroll
        for (int ks = 0; ks < 4; ++ks) {
            const uint32_t ah2[4] = {pha[2 * ks], phb[2 * ks], pha[2 * ks + 1], phb[2 * ks + 1]};
            const uint32_t al2[4] = {pla[2 * ks], plb[2 * ks], pla[2 * ks + 1], plb[2 * ks + 1]};
#pragma unroll
            for (int g = 0; g < 5; ++g) {
                uint32_t vfh[4], vfl[4];
                const uint32_t va = voff + (uint32_t)((ks * 16 * AP + g * 16) * 2);
                ldsm4t(vfh, uVh + va);
                ldsm4t(vfl, uVl + va);
#pragma unroll
                for (int h = 0; h < 2; ++h) {
                    float* d = of[2 * g + h];
                    mma16816(d, ah2, vfh[2 * h], vfh[2 * h + 1]);
                    mma16816(d, ah2, vfl[2 * h], vfl[2 * h + 1]);
                    mma16816(d, al2, vfh[2 * h], vfh[2 * h + 1]);
                }
            }
        }
    }

    // ---- write normalized output as bf16 hi/lo (GEMM2 A operand) ----
    const float inva = 1.f / l_a, invb = 1.f / l_b;
    const int rowa = n0 + warp * 16 + (lane >> 2);
    const int rowb = rowa + 8;
#pragma unroll
    for (int t = 0; t < 10; t++) {
        const int col = head * HK + t * 8 + 2 * (lane & 3);
        const float a0 = of[t][0] * inva, a1 = of[t][1] * inva;
        const float b0 = of[t][2] * invb, b1 = of[t][3] * invb;
        const __nv_bfloat16 ah0 = __float2bfloat16(a0), ah1 = __float2bfloat16(a1);
        const __nv_bfloat16 bh0 = __float2bfloat16(b0), bh1 = __float2bfloat16(b1);
        __nv_bfloat162 vha = {ah0, ah1};
        __nv_bfloat162 vla = {__float2bfloat16(a0 - __bfloat162float(ah0)),
                              __float2bfloat16(a1 - __bfloat162float(ah1))};
        __nv_bfloat162 vhb = {bh0, bh1};
        __nv_bfloat162 vlb = {__float2bfloat16(b0 - __bfloat162float(bh0)),
                              __float2bfloat16(b1 - __bfloat162float(bh1))};
        *(__nv_bfloat162*)(oh + (size_t)rowa * DM + col) = vha;
        *(__nv_bfloat162*)(ol + (size_t)rowa * DM + col) = vla;
        *(__nv_bfloat162*)(oh + (size_t)rowb * DM + col) = vhb;
        *(__nv_bfloat162*)(ol + (size_t)rowb * DM + col) = vlb;
    }
}

// ---------------------------------------------------------------------------
// Launch
// ---------------------------------------------------------------------------
extern "C" void kernel_launch(void* const* d_in, const int* in_sizes, int n_in,
                              void* d_out, int out_size)
{
    const float* hidden = (const float*)d_in[0];
    const float* cosNK  = (const float*)d_in[1];
    const float* sinNK  = (const float*)d_in[2];
    const float* qkv_w  = (const float*)d_in[3];
    const float* qkv_b  = (const float*)d_in[4];
    const float* proj_w = (const float*)d_in[5];
    const float* proj_b = (const float*)d_in[6];
    float* out = (float*)d_out;

    float* qkv = nullptr;
    __nv_bfloat16 *ah, *al, *bh, *bl, *qh, *ql, *kh, *kl, *vh, *vl;
    cudaGetSymbolAddress((void**)&qkv, g_qkv);
    cudaGetSymbolAddress((void**)&ah,  g_ah);
    cudaGetSymbolAddress((void**)&al,  g_al);
    cudaGetSymbolAddress((void**)&bh,  g_bh);
    cudaGetSymbolAddress((void**)&bl,  g_bl);
    cudaGetSymbolAddress((void**)&qh,  g_qh);
    cudaGetSymbolAddress((void**)&ql,  g_ql);
    cudaGetSymbolAddress((void**)&kh,  g_kh);
    cudaGetSymbolAddress((void**)&kl,  g_kl);
    cudaGetSymbolAddress((void**)&vh,  g_vh);
    cudaGetSymbolAddress((void**)&vl,  g_vl);

    cudaFuncSetAttribute(gemm_mma, cudaFuncAttributeMaxDynamicSharedMemorySize, GSMEM);
    cudaFuncSetAttribute(attn_mma, cudaFuncAttributeMaxDynamicSharedMemorySize, ATT_SMEM);

    const int n4 = NTOK * DM / 4;

    // 1) prep GEMM1: split hidden, transpose+split qkv_w
    split_kernel<<<(n4 + 255) / 256, 256>>>(hidden, ah, al, n4);
    transpose_split_kernel<<<dim3(3 * DM / 32, DM / 32), dim3(32, 8)>>>(qkv_w, bh, bl, DM, 3 * DM);

    // 2) qkv = hidden @ qkv_w + qkv_b
    gemm_mma<<<dim3(3 * DM / 128, NTOK / 128), 256, GSMEM>>>(
        ah, al, bh, bl, qkv_b, qkv, 3 * DM, DM);

    // 3) fused RoPE + split to bf16 hi/lo
    {
        const int total = NTOK * NH * 40;
        rope_split_kernel<<<(total + 255) / 256, 256>>>(qkv, cosNK, sinNK,
                                                        qh, ql, kh, kl, vh, vl);
    }

    // 4) attention (tensor cores, 128-query tiles); writes GEMM2's A hi/lo
    attn_mma<<<dim3(SEGL / 128, NH, NSEGS), 256, ATT_SMEM>>>(
        qh, ql, kh, kl, vh, vl, ah, al);

    // 5) prep GEMM2 weights
    transpose_split_kernel<<<dim3(DM / 32, DM / 32), dim3(32, 8)>>>(proj_w, bh, bl, DM, DM);

    // 6) out = attn_out @ proj_w + proj_b
    gemm_mma<<<dim3(DM / 128, NTOK / 128), 256, GSMEM>>>(
        ah, al, bh, bl, proj_b, out, DM, DM);
}

// round 9
// speedup vs baseline: 1.0865x; 1.0865x over previous
#include <cuda_runtime.h>
#include <cuda_bf16.h>
#include <cstdint>

// Problem constants (fixed by reference setup_inputs)
#define NTOK 16384
#define DM   1280
#define NH   16
#define HK   80
#define NSEGS 8
#define SEGL 2048

#define NEG_INF (__int_as_float(0xff800000))

// Scratch (allocation-free rule: __device__ globals)
__device__ float g_qkv[(size_t)NTOK * 3 * DM];            // [N][3*1280] fp32 (GEMM1 out)
__device__ __nv_bfloat16 g_ah[(size_t)NTOK * DM];         // GEMM A hi (hidden, then attn-out)
__device__ __nv_bfloat16 g_al[(size_t)NTOK * DM];         // GEMM A lo
__device__ __nv_bfloat16 g_bh[(size_t)3 * DM * DM];       // W^T hi [N][K]
__device__ __nv_bfloat16 g_bl[(size_t)3 * DM * DM];       // W^T lo [N][K]
__device__ __nv_bfloat16 g_qh[(size_t)NTOK * DM];         // q hi (rope'd, prescaled)
__device__ __nv_bfloat16 g_ql[(size_t)NTOK * DM];
__device__ __nv_bfloat16 g_kh[(size_t)NTOK * DM];         // k hi (rope'd)
__device__ __nv_bfloat16 g_kl[(size_t)NTOK * DM];
__device__ __nv_bfloat16 g_vh[(size_t)NTOK * DM];         // v hi
__device__ __nv_bfloat16 g_vl[(size_t)NTOK * DM];

// ---------------------------------------------------------------------------
// helpers
// ---------------------------------------------------------------------------
__device__ __forceinline__ uint32_t smem_u32(const void* p) {
    uint32_t a;
    asm("{ .reg .u64 t; cvta.to.shared.u64 t, %1; cvt.u32.u64 %0, t; }" : "=r"(a) : "l"(p));
    return a;
}
__device__ __forceinline__ void ldsm4(uint32_t* r, uint32_t addr) {
    asm volatile("ldmatrix.sync.aligned.m8n8.x4.shared.b16 {%0,%1,%2,%3}, [%4];"
                 : "=r"(r[0]), "=r"(r[1]), "=r"(r[2]), "=r"(r[3]) : "r"(addr));
}
__device__ __forceinline__ void ldsm4t(uint32_t* r, uint32_t addr) {
    asm volatile("ldmatrix.sync.aligned.m8n8.x4.trans.shared.b16 {%0,%1,%2,%3}, [%4];"
                 : "=r"(r[0]), "=r"(r[1]), "=r"(r[2]), "=r"(r[3]) : "r"(addr));
}
__device__ __forceinline__ void mma16816(float* d, const uint32_t* a, uint32_t b0, uint32_t b1) {
    asm volatile("mma.sync.aligned.m16n8k16.row.col.f32.bf16.bf16.f32 "
                 "{%0,%1,%2,%3}, {%4,%5,%6,%7}, {%8,%9}, {%0,%1,%2,%3};"
                 : "+f"(d[0]), "+f"(d[1]), "+f"(d[2]), "+f"(d[3])
                 : "r"(a[0]), "r"(a[1]), "r"(a[2]), "r"(a[3]), "r"(b0), "r"(b1));
}
__device__ __forceinline__ uint32_t cvt_bf2(float hi, float lo) {
    uint32_t d;
    asm("cvt.rn.bf16x2.f32 %0, %1, %2;" : "=r"(d) : "f"(hi), "f"(lo));
    return d;
}
__device__ __forceinline__ void cpa16(uint32_t dst, const void* src) {
    asm volatile("cp.async.cg.shared.global [%0], [%1], 16;" :: "r"(dst), "l"(src));
}
#define CP_COMMIT() asm volatile("cp.async.commit_group;")
#define CP_WAIT0()  asm volatile("cp.async.wait_group 0;")
#define CP_WAIT1()  asm volatile("cp.async.wait_group 1;")
// FMA-pipe exp2 for t <= 0 (clamped), ~3e-6 rel error
__device__ __forceinline__ float exp2p(float t) {
    t = fmaxf(t, -126.f);
    const float z = t + 12582912.f;
    const int n = __float_as_int(z) - 0x4B400000;
    const float f = t - (z - 12582912.f);
    float r = 1.3333558146e-3f;
    r = fmaf(r, f, 9.6181291076e-3f);
    r = fmaf(r, f, 5.5504108664e-2f);
    r = fmaf(r, f, 2.4022650695e-1f);
    r = fmaf(r, f, 6.9314718055e-1f);
    r = fmaf(r, f, 1.0f);
    return __int_as_float(__float_as_int(r) + (n << 23));
}
__device__ __forceinline__ void split_store(__nv_bfloat16* hp, __nv_bfloat16* lp,
                                            size_t o, float v) {
    const __nv_bfloat16 h = __float2bfloat16(v);
    hp[o] = h;
    lp[o] = __float2bfloat16(v - __bfloat162float(h));
}

// ---------------------------------------------------------------------------
// split: fp32 -> bf16 hi + bf16 lo, vectorized by 4
// ---------------------------------------------------------------------------
__global__ __launch_bounds__(256) void split_kernel(
    const float* __restrict__ in, __nv_bfloat16* __restrict__ hi,
    __nv_bfloat16* __restrict__ lo, int n4)
{
    const int i = blockIdx.x * blockDim.x + threadIdx.x;
    if (i >= n4) return;
    const float4 v = ((const float4*)in)[i];
    __nv_bfloat16 h0 = __float2bfloat16(v.x);
    __nv_bfloat16 h1 = __float2bfloat16(v.y);
    __nv_bfloat16 h2 = __float2bfloat16(v.z);
    __nv_bfloat16 h3 = __float2bfloat16(v.w);
    __nv_bfloat162 hp0 = {h0, h1}, hp1 = {h2, h3};
    __nv_bfloat162 lp0 = {__float2bfloat16(v.x - __bfloat162float(h0)),
                          __float2bfloat16(v.y - __bfloat162float(h1))};
    __nv_bfloat162 lp1 = {__float2bfloat16(v.z - __bfloat162float(h2)),
                          __float2bfloat16(v.w - __bfloat162float(h3))};
    ((__nv_bfloat162*)hi)[i * 2 + 0] = hp0;
    ((__nv_bfloat162*)hi)[i * 2 + 1] = hp1;
    ((__nv_bfloat162*)lo)[i * 2 + 0] = lp0;
    ((__nv_bfloat162*)lo)[i * 2 + 1] = lp1;
}

// ---------------------------------------------------------------------------
// transpose + split: W[K][N] row-major -> WT hi/lo [N][K] bf16
// ---------------------------------------------------------------------------
__global__ void transpose_split_kernel(
    const float* __restrict__ W, __nv_bfloat16* __restrict__ bh,
    __nv_bfloat16* __restrict__ bl, int Krows, int Ncols)
{
    __shared__ float t[32][33];
    const int bx = blockIdx.x * 32;
    const int by = blockIdx.y * 32;
    const int x = threadIdx.x, y = threadIdx.y;
#pragma unroll
    for (int i = 0; i < 32; i += 8)
        t[y + i][x] = W[(size_t)(by + y + i) * Ncols + bx + x];
    __syncthreads();
#pragma unroll
    for (int i = 0; i < 32; i += 8) {
        const float v = t[x][y + i];
        split_store(bh, bl, (size_t)(bx + y + i) * Krows + by + x, v);
    }
}

// ---------------------------------------------------------------------------
// fused RoPE + bf16 split: g_qkv -> qh/ql (prescaled), kh/kl, vh/vl
// ---------------------------------------------------------------------------
__global__ __launch_bounds__(256) void rope_split_kernel(
    const float* __restrict__ qkv, const float* __restrict__ cosNK,
    const float* __restrict__ sinNK,
    __nv_bfloat16* __restrict__ qh, __nv_bfloat16* __restrict__ ql,
    __nv_bfloat16* __restrict__ kh, __nv_bfloat16* __restrict__ kl,
    __nv_bfloat16* __restrict__ vh, __nv_bfloat16* __restrict__ vl)
{
    const int t = blockIdx.x * blockDim.x + threadIdx.x;
    if (t >= NTOK * NH * 40) return;
    const int j = t % 40;
    const int h = (t / 40) % NH;
    const int n = t / (40 * NH);

    const float c1 = cosNK[n * HK + j];
    const float s1 = sinNK[n * HK + j];
    const float c2 = cosNK[n * HK + j + 40];
    const float s2 = sinNK[n * HK + j + 40];

    const size_t ib = (size_t)n * (3 * DM) + h * HK;
    const size_t ob = (size_t)n * DM + h * HK;
    const float qs = 0.1118033988749895f * 1.4426950408889634f;  // scale * log2(e)

    {
        const float x1 = qkv[ib + j], x2 = qkv[ib + j + 40];
        split_store(qh, ql, ob + j,      (x1 * c1 - x2 * s1) * qs);
        split_store(qh, ql, ob + j + 40, (x2 * c2 + x1 * s2) * qs);
    }
    {
        const float x1 = qkv[ib + DM + j], x2 = qkv[ib + DM + j + 40];
        split_store(kh, kl, ob + j,      x1 * c1 - x2 * s1);
        split_store(kh, kl, ob + j + 40, x2 * c2 + x1 * s2);
    }
    {
        split_store(vh, vl, ob + j,      qkv[ib + 2 * DM + j]);
        split_store(vh, vl, ob + j + 40, qkv[ib + 2 * DM + j + 40]);
    }
}

// ---------------------------------------------------------------------------
// bf16 3-split tensor-core GEMM + bias.
// 2-stage cp.async pipeline with issue-ahead + wait_group 1:
// 80KB smem -> 2 CTAs/SM, AND chunk t+1 loads overlap chunk t MMAs.
// ---------------------------------------------------------------------------
#define GP 40
#define BUFE (128 * GP)
#define GSMEM (8 * BUFE * 2)

__global__ __launch_bounds__(256) void gemm_mma(
    const __nv_bfloat16* __restrict__ Ah, const __nv_bfloat16* __restrict__ Al,
    const __nv_bfloat16* __restrict__ Bh, const __nv_bfloat16* __restrict__ Bl,
    const float* __restrict__ bias, float* __restrict__ C, int N, int Kd)
{
    extern __shared__ __nv_bfloat16 smb[];
    __nv_bfloat16* Ash = smb;
    __nv_bfloat16* Asl = Ash + 2 * BUFE;
    __nv_bfloat16* Bsh = Asl + 2 * BUFE;
    __nv_bfloat16* Bsl = Bsh + 2 * BUFE;

    const int tid = threadIdx.x;
    const int lane = tid & 31;
    const int warp = tid >> 5;
    const int wm = warp >> 1;
    const int wn = warp & 1;
    const int m0 = blockIdx.y * 128;
    const int n0 = blockIdx.x * 128;

    const int r0 = tid >> 2;
    const int sg = (tid & 3) * 8;

    const __nv_bfloat16* pAh = Ah + (size_t)(m0 + r0) * Kd + sg;
    const __nv_bfloat16* pAl = Al + (size_t)(m0 + r0) * Kd + sg;
    const __nv_bfloat16* pBh = Bh + (size_t)(n0 + r0) * Kd + sg;
    const __nv_bfloat16* pBl = Bl + (size_t)(n0 + r0) * Kd + sg;
    const size_t rstep = (size_t)64 * Kd;

    const uint32_t uAsh = smem_u32(Ash);
    const uint32_t uAsl = smem_u32(Asl);
    const uint32_t uBsh = smem_u32(Bsh);
    const uint32_t uBsl = smem_u32(Bsl);

    float acc[2][8][4];
#pragma unroll
    for (int a = 0; a < 2; a++)
#pragma unroll
        for (int b = 0; b < 8; b++)
#pragma unroll
            for (int c = 0; c < 4; c++) acc[a][b][c] = 0.f;

    auto issue = [&](int k0, int stg) {
        const uint32_t o0 = (uint32_t)(stg * BUFE + r0 * GP + sg) * 2;
        const uint32_t o1 = (uint32_t)(stg * BUFE + (r0 + 64) * GP + sg) * 2;
        cpa16(uAsh + o0, pAh + k0);  cpa16(uAsh + o1, pAh + k0 + rstep);
        cpa16(uAsl + o0, pAl + k0);  cpa16(uAsl + o1, pAl + k0 + rstep);
        cpa16(uBsh + o0, pBh + k0);  cpa16(uBsh + o1, pBh + k0 + rstep);
        cpa16(uBsl + o0, pBl + k0);  cpa16(uBsl + o1, pBl + k0 + rstep);
        CP_COMMIT();
    };

    const uint32_t aoff = (uint32_t)((wm * 32 + (lane & 15)) * GP + ((lane >> 4) << 3)) * 2;
    const uint32_t boff = (uint32_t)((wn * 64 + (lane & 15)) * GP + ((lane >> 4) << 3)) * 2;

    const int NT = Kd >> 5;
    issue(0, 0);

    for (int t = 0; t < NT; ++t) {
        // issue ahead, then wait for chunk t only (t+1 stays in flight)
        if (t + 1 < NT) {
            issue((t + 1) << 5, (t + 1) & 1);
            CP_WAIT1();
        } else {
            CP_WAIT0();
        }
        __syncthreads();

        const uint32_t bb = (uint32_t)((t & 1) * BUFE * 2);
#pragma unroll
        for (int ks = 0; ks < 2; ++ks) {
            const uint32_t kso = (uint32_t)(ks * 16 * 2);
            uint32_t ah[2][4], al[2][4];
#pragma unroll
            for (int t2 = 0; t2 < 2; ++t2) {
                const uint32_t ad = bb + aoff + kso + (uint32_t)(t2 * 16 * GP * 2);
                ldsm4(ah[t2], uAsh + ad);
                ldsm4(al[t2], uAsl + ad);
            }
            uint32_t bh4[4][4], bl4[4][4];
#pragma unroll
            for (int g = 0; g < 4; ++g) {
                const uint32_t bd = bb + boff + kso + (uint32_t)(g * 16 * GP * 2);
                ldsm4(bh4[g], uBsh + bd);
                ldsm4(bl4[g], uBsl + bd);
            }
#pragma unroll
            for (int t2 = 0; t2 < 2; ++t2)
#pragma unroll
                for (int g = 0; g < 4; ++g)
#pragma unroll
                    for (int h = 0; h < 2; ++h) {
                        float* d = acc[t2][g * 2 + h];
                        mma16816(d, ah[t2], bh4[g][h], bh4[g][h + 2]);
                        mma16816(d, ah[t2], bl4[g][h], bl4[g][h + 2]);
                        mma16816(d, al[t2], bh4[g][h], bh4[g][h + 2]);
                    }
        }
        // protect buffer (t&1) before iter t+1 issues chunk t+2 into it
        __syncthreads();
    }

#pragma unroll
    for (int t2 = 0; t2 < 2; ++t2) {
        const int row = m0 + wm * 32 + t2 * 16 + (lane >> 2);
#pragma unroll
        for (int n8 = 0; n8 < 8; ++n8) {
            const int col = n0 + wn * 64 + n8 * 8 + (lane & 3) * 2;
            const float b0 = __ldg(bias + col);
            const float b1 = __ldg(bias + col + 1);
            float2 v0 = {acc[t2][n8][0] + b0, acc[t2][n8][1] + b1};
            float2 v1 = {acc[t2][n8][2] + b0, acc[t2][n8][3] + b1};
            *(float2*)(C + (size_t)row * N + col) = v0;
            *(float2*)(C + (size_t)(row + 8) * N + col) = v1;
        }
    }
}

// ---------------------------------------------------------------------------
// Tensor-core flash attention, 128-query tile, 8 warps, pre-split inputs,
// cp.async double-buffered K/V. Epilogue writes bf16 hi/lo for GEMM2.
// ---------------------------------------------------------------------------
#define AP 88
#define KVB (64 * AP)
#define QTB (128 * AP)
#define ATT_SMEM ((2 * QTB + 8 * KVB) * 2)

__global__ __launch_bounds__(256) void attn_mma(
    const __nv_bfloat16* __restrict__ qh, const __nv_bfloat16* __restrict__ ql,
    const __nv_bfloat16* __restrict__ kh, const __nv_bfloat16* __restrict__ kl,
    const __nv_bfloat16* __restrict__ vh, const __nv_bfloat16* __restrict__ vl,
    __nv_bfloat16* __restrict__ oh, __nv_bfloat16* __restrict__ ol)
{
    extern __shared__ __nv_bfloat16 smb2[];
    __nv_bfloat16* Qh = smb2;            // [128][AP]
    __nv_bfloat16* Ql = Qh + QTB;
    __nv_bfloat16* KV = Ql + QTB;        // [2 buf][4 arr][64][AP]

    const int tid = threadIdx.x;
    const int lane = tid & 31;
    const int warp = tid >> 5;
    const int qt = blockIdx.x, head = blockIdx.y, seg = blockIdx.z;
    const int n0 = seg * SEGL + qt * 128;

    const uint32_t uKV = smem_u32(KV);

    auto issueKV = [&](int kb, int buf) {
        const int nk = seg * SEGL + kb * 64;
        const uint32_t bofs = (uint32_t)(buf * 4 * KVB) * 2;
#pragma unroll
        for (int i = 0; i < 3; ++i) {
            const int idx = tid + i * 256;
            if (idx < 640) {
                const int r = idx / 10, c = idx % 10;
                const uint32_t d = bofs + (uint32_t)(r * AP + c * 8) * 2 + uKV;
                const size_t g = (size_t)(nk + r) * DM + head * HK + c * 8;
                cpa16(d + 0 * KVB * 2, kh + g);
                cpa16(d + 1 * KVB * 2, kl + g);
                cpa16(d + 2 * KVB * 2, vh + g);
                cpa16(d + 3 * KVB * 2, vl + g);
            }
        }
        CP_COMMIT();
    };

    issueKV(0, 0);

    // load Q tile (pre-scaled, pre-split): 128 rows x 10 16B-groups
#pragma unroll
    for (int i = 0; i < 5; ++i) {
        const int idx = tid + i * 256;
        const int r = idx / 10, c = idx % 10;
        const size_t g = (size_t)(n0 + r) * DM + head * HK + c * 8;
        *(uint4*)(Qh + r * AP + c * 8) = *(const uint4*)(qh + g);
        *(uint4*)(Ql + r * AP + c * 8) = *(const uint4*)(ql + g);
    }
    __syncthreads();

    uint32_t qfh[5][4], qfl[5][4];
    {
        const uint32_t uQh = smem_u32(Qh), uQl = smem_u32(Ql);
        const uint32_t qoff = (uint32_t)((warp * 16 + (lane & 15)) * AP + ((lane >> 4) << 3)) * 2;
#pragma unroll
        for (int ks = 0; ks < 5; ++ks) {
            const uint32_t ad = qoff + (uint32_t)(ks * 16 * 2);
            ldsm4(qfh[ks], uQh + ad);
            ldsm4(qfl[ks], uQl + ad);
        }
    }

    const uint32_t koff = (uint32_t)((lane & 15) * AP + ((lane >> 4) << 3)) * 2;
    const uint32_t voff = (uint32_t)((((lane & 7) + (((lane >> 3) & 1) << 3)) * AP) + ((lane >> 4) << 3)) * 2;

    float of[10][4];
#pragma unroll
    for (int t = 0; t < 10; t++)
#pragma unroll
        for (int j = 0; j < 4; j++) of[t][j] = 0.f;
    float m_a = -1e30f, m_b = -1e30f, l_a = 0.f, l_b = 0.f;

    for (int kb = 0; kb < SEGL / 64; ++kb) {
        CP_WAIT0();
        __syncthreads();
        if (kb + 1 < SEGL / 64) issueKV(kb + 1, (kb + 1) & 1);

        const uint32_t bb = (uint32_t)((kb & 1) * 4 * KVB) * 2;
        const uint32_t uKh = uKV + bb;
        const uint32_t uKl = uKh + KVB * 2;
        const uint32_t uVh = uKl + KVB * 2;
        const uint32_t uVl = uVh + KVB * 2;

        // ---- S = Q @ K^T (3-term) ----
        float s[8][4];
#pragma unroll
        for (int t = 0; t < 8; t++)
#pragma unroll
            for (int j = 0; j < 4; j++) s[t][j] = 0.f;

#pragma unroll
        for (int ks = 0; ks < 5; ++ks) {
#pragma unroll
            for (int g = 0; g < 4; ++g) {
                uint32_t kfh[4], kfl[4];
                const uint32_t ka = koff + (uint32_t)((g * 16 * AP + ks * 16) * 2);
                ldsm4(kfh, uKh + ka);
                ldsm4(kfl, uKl + ka);
#pragma unroll
                for (int h = 0; h < 2; ++h) {
                    float* d = s[2 * g + h];
                    mma16816(d, qfh[ks], kfh[h], kfh[h + 2]);
                    mma16816(d, qfh[ks], kfl[h], kfl[h + 2]);
                    mma16816(d, qfl[ks], kfh[h], kfh[h + 2]);
                }
            }
        }

        // ---- online softmax (exp2 domain) ----
        float rma = NEG_INF, rmb = NEG_INF;
#pragma unroll
        for (int t = 0; t < 8; t++) {
            rma = fmaxf(rma, fmaxf(s[t][0], s[t][1]));
            rmb = fmaxf(rmb, fmaxf(s[t][2], s[t][3]));
        }
        rma = fmaxf(rma, __shfl_xor_sync(0xffffffffu, rma, 1));
        rma = fmaxf(rma, __shfl_xor_sync(0xffffffffu, rma, 2));
        rmb = fmaxf(rmb, __shfl_xor_sync(0xffffffffu, rmb, 1));
        rmb = fmaxf(rmb, __shfl_xor_sync(0xffffffffu, rmb, 2));
        const float mna = fmaxf(m_a, rma), mnb = fmaxf(m_b, rmb);
        const float corra = exp2p(m_a - mna), corrb = exp2p(m_b - mnb);
        m_a = mna; m_b = mnb;

        float suma = 0.f, sumb = 0.f;
        uint32_t pha[8], phb[8], pla[8], plb[8];
#pragma unroll
        for (int t = 0; t < 8; t++) {
            const float p0 = exp2p(s[t][0] - m_a);
            const float p1 = exp2p(s[t][1] - m_a);
            const float p2 = exp2p(s[t][2] - m_b);
            const float p3 = exp2p(s[t][3] - m_b);
            suma += p0 + p1;
            sumb += p2 + p3;
            const uint32_t ha = cvt_bf2(p1, p0);
            const uint32_t hb = cvt_bf2(p3, p2);
            pha[t] = ha; phb[t] = hb;
            const float h0 = __int_as_float(ha << 16);
            const float h1 = __int_as_float(ha & 0xFFFF0000u);
            const float h2 = __int_as_float(hb << 16);
            const float h3 = __int_as_float(hb & 0xFFFF0000u);
            pla[t] = cvt_bf2(p1 - h1, p0 - h0);
            plb[t] = cvt_bf2(p3 - h3, p2 - h2);
        }
        suma += __shfl_xor_sync(0xffffffffu, suma, 1);
        suma += __shfl_xor_sync(0xffffffffu, suma, 2);
        sumb += __shfl_xor_sync(0xffffffffu, sumb, 1);
        sumb += __shfl_xor_sync(0xffffffffu, sumb, 2);
        l_a = l_a * corra + suma;
        l_b = l_b * corrb + sumb;
#pragma unroll
        for (int t = 0; t < 10; t++) {
            of[t][0] *= corra;
            of[t][1] *= corra;
            of[t][2] *= corrb;
            of[t][3] *= corrb;
        }

        // ---- O += P @ V (3-term) ----
#pragma unroll
        for (int ks = 0; ks < 4; ++ks) {
            const uint32_t ah2[4] = {pha[2 * ks], phb[2 * ks], pha[2 * ks + 1], phb[2 * ks + 1]};
            const uint32_t al2[4] = {pla[2 * ks], plb[2 * ks], pla[2 * ks + 1], plb[2 * ks + 1]};
#pragma unroll
            for (int g = 0; g < 5; ++g) {
                uint32_t vfh[4], vfl[4];
                const uint32_t va = voff + (uint32_t)((ks * 16 * AP + g * 16) * 2);
                ldsm4t(vfh, uVh + va);
                ldsm4t(vfl, uVl + va);
#pragma unroll
                for (int h = 0; h < 2; ++h) {
                    float* d = of[2 * g + h];
                    mma16816(d, ah2, vfh[2 * h], vfh[2 * h + 1]);
                    mma16816(d, ah2, vfl[2 * h], vfl[2 * h + 1]);
                    mma16816(d, al2, vfh[2 * h], vfh[2 * h + 1]);
                }
            }
        }
    }

    // ---- write normalized output as bf16 hi/lo (GEMM2 A operand) ----
    const float inva = 1.f / l_a, invb = 1.f / l_b;
    const int rowa = n0 + warp * 16 + (lane >> 2);
    const int rowb = rowa + 8;
#pragma unroll
    for (int t = 0; t < 10; t++) {
        const int col = head * HK + t * 8 + 2 * (lane & 3);
        const float a0 = of[t][0] * inva, a1 = of[t][1] * inva;
        const float b0 = of[t][2] * invb, b1 = of[t][3] * invb;
        const __nv_bfloat16 ah0 = __float2bfloat16(a0), ah1 = __float2bfloat16(a1);
        const __nv_bfloat16 bh0 = __float2bfloat16(b0), bh1 = __float2bfloat16(b1);
        __nv_bfloat162 vha = {ah0, ah1};
        __nv_bfloat162 vla = {__float2bfloat16(a0 - __bfloat162float(ah0)),
                              __float2bfloat16(a1 - __bfloat162float(ah1))};
        __nv_bfloat162 vhb = {bh0, bh1};
        __nv_bfloat162 vlb = {__float2bfloat16(b0 - __bfloat162float(bh0)),
                              __float2bfloat16(b1 - __bfloat162float(bh1))};
        *(__nv_bfloat162*)(oh + (size_t)rowa * DM + col) = vha;
        *(__nv_bfloat162*)(ol + (size_t)rowa * DM + col) = vla;
        *(__nv_bfloat162*)(oh + (size_t)rowb * DM + col) = vhb;
        *(__nv_bfloat162*)(ol + (size_t)rowb * DM + col) = vlb;
    }
}

// ---------------------------------------------------------------------------
// Launch
// ---------------------------------------------------------------------------
extern "C" void kernel_launch(void* const* d_in, const int* in_sizes, int n_in,
                              void* d_out, int out_size)
{
    const float* hidden = (const float*)d_in[0];
    const float* cosNK  = (const float*)d_in[1];
    const float* sinNK  = (const float*)d_in[2];
    const float* qkv_w  = (const float*)d_in[3];
    const float* qkv_b  = (const float*)d_in[4];
    const float* proj_w = (const float*)d_in[5];
    const float* proj_b = (const float*)d_in[6];
    float* out = (float*)d_out;

    float* qkv = nullptr;
    __nv_bfloat16 *ah, *al, *bh, *bl, *qh, *ql, *kh, *kl, *vh, *vl;
    cudaGetSymbolAddress((void**)&qkv, g_qkv);
    cudaGetSymbolAddress((void**)&ah,  g_ah);
    cudaGetSymbolAddress((void**)&al,  g_al);
    cudaGetSymbolAddress((void**)&bh,  g_bh);
    cudaGetSymbolAddress((void**)&bl,  g_bl);
    cudaGetSymbolAddress((void**)&qh,  g_qh);
    cudaGetSymbolAddress((void**)&ql,  g_ql);
    cudaGetSymbolAddress((void**)&kh,  g_kh);
    cudaGetSymbolAddress((void**)&kl,  g_kl);
    cudaGetSymbolAddress((void**)&vh,  g_vh);
    cudaGetSymbolAddress((void**)&vl,  g_vl);

    cudaFuncSetAttribute(gemm_mma, cudaFuncAttributeMaxDynamicSharedMemorySize, GSMEM);
    cudaFuncSetAttribute(attn_mma, cudaFuncAttributeMaxDynamicSharedMemorySize, ATT_SMEM);

    const int n4 = NTOK * DM / 4;

    // 1) prep GEMM1: split hidden, transpose+split qkv_w
    split_kernel<<<(n4 + 255) / 256, 256>>>(hidden, ah, al, n4);
    transpose_split_kernel<<<dim3(3 * DM / 32, DM / 32), dim3(32, 8)>>>(qkv_w, bh, bl, DM, 3 * DM);

    // 2) qkv = hidden @ qkv_w + qkv_b
    gemm_mma<<<dim3(3 * DM / 128, NTOK / 128), 256, GSMEM>>>(
        ah, al, bh, bl, qkv_b, qkv, 3 * DM, DM);

    // 3) fused RoPE + split to bf16 hi/lo
    {
        const int total = NTOK * NH * 40;
        rope_split_kernel<<<(total + 255) / 256, 256>>>(qkv, cosNK, sinNK,
                                                        qh, ql, kh, kl, vh, vl);
    }

    // 4) attention (tensor cores, 128-query tiles); writes GEMM2's A hi/lo
    attn_mma<<<dim3(SEGL / 128, NH, NSEGS), 256, ATT_SMEM>>>(
        qh, ql, kh, kl, vh, vl, ah, al);

    // 5) prep GEMM2 weights
    transpose_split_kernel<<<dim3(DM / 32, DM / 32), dim3(32, 8)>>>(proj_w, bh, bl, DM, DM);

    // 6) out = attn_out @ proj_w + proj_b
    gemm_mma<<<dim3(DM / 128, NTOK / 128), 256, GSMEM>>>(
        ah, al, bh, bl, proj_b, out, DM, DM);
}

// round 10
// speedup vs baseline: 1.2851x; 1.1828x over previous
#include <cuda_runtime.h>
#include <cuda_bf16.h>
#include <cuda_fp16.h>
#include <cstdint>

// Problem constants (fixed by reference setup_inputs)
#define NTOK 16384
#define DM   1280
#define NH   16
#define HK   80
#define NSEGS 8
#define SEGL 2048

#define NEG_INF (__int_as_float(0xff800000))

// Scratch (allocation-free rule: __device__ globals)
__device__ float g_qkv[(size_t)NTOK * 3 * DM];            // [N][3*1280] fp32 (GEMM1 out)
__device__ __half g_ah[(size_t)NTOK * DM];                // GEMM A hi fp16 (hidden, then attn-out)
__device__ __half g_al[(size_t)NTOK * DM];                // GEMM A lo fp16
__device__ __half g_bh[(size_t)3 * DM * DM];              // W^T hi fp16 [N][K]
__device__ __nv_bfloat16 g_qh[(size_t)NTOK * DM];         // q hi (rope'd, prescaled)
__device__ __nv_bfloat16 g_ql[(size_t)NTOK * DM];
__device__ __nv_bfloat16 g_kh[(size_t)NTOK * DM];         // k hi (rope'd)
__device__ __nv_bfloat16 g_kl[(size_t)NTOK * DM];
__device__ __nv_bfloat16 g_vh[(size_t)NTOK * DM];         // v hi
__device__ __nv_bfloat16 g_vl[(size_t)NTOK * DM];

// ---------------------------------------------------------------------------
// helpers
// ---------------------------------------------------------------------------
__device__ __forceinline__ uint32_t smem_u32(const void* p) {
    uint32_t a;
    asm("{ .reg .u64 t; cvta.to.shared.u64 t, %1; cvt.u32.u64 %0, t; }" : "=r"(a) : "l"(p));
    return a;
}
__device__ __forceinline__ void ldsm4(uint32_t* r, uint32_t addr) {
    asm volatile("ldmatrix.sync.aligned.m8n8.x4.shared.b16 {%0,%1,%2,%3}, [%4];"
                 : "=r"(r[0]), "=r"(r[1]), "=r"(r[2]), "=r"(r[3]) : "r"(addr));
}
__device__ __forceinline__ void ldsm4t(uint32_t* r, uint32_t addr) {
    asm volatile("ldmatrix.sync.aligned.m8n8.x4.trans.shared.b16 {%0,%1,%2,%3}, [%4];"
                 : "=r"(r[0]), "=r"(r[1]), "=r"(r[2]), "=r"(r[3]) : "r"(addr));
}
// bf16 mma (attention)
__device__ __forceinline__ void mma16816(float* d, const uint32_t* a, uint32_t b0, uint32_t b1) {
    asm volatile("mma.sync.aligned.m16n8k16.row.col.f32.bf16.bf16.f32 "
                 "{%0,%1,%2,%3}, {%4,%5,%6,%7}, {%8,%9}, {%0,%1,%2,%3};"
                 : "+f"(d[0]), "+f"(d[1]), "+f"(d[2]), "+f"(d[3])
                 : "r"(a[0]), "r"(a[1]), "r"(a[2]), "r"(a[3]), "r"(b0), "r"(b1));
}
// fp16 mma (GEMMs)
__device__ __forceinline__ void mma16816h(float* d, const uint32_t* a, uint32_t b0, uint32_t b1) {
    asm volatile("mma.sync.aligned.m16n8k16.row.col.f32.f16.f16.f32 "
                 "{%0,%1,%2,%3}, {%4,%5,%6,%7}, {%8,%9}, {%0,%1,%2,%3};"
                 : "+f"(d[0]), "+f"(d[1]), "+f"(d[2]), "+f"(d[3])
                 : "r"(a[0]), "r"(a[1]), "r"(a[2]), "r"(a[3]), "r"(b0), "r"(b1));
}
__device__ __forceinline__ uint32_t cvt_bf2(float hi, float lo) {
    uint32_t d;
    asm("cvt.rn.bf16x2.f32 %0, %1, %2;" : "=r"(d) : "f"(hi), "f"(lo));
    return d;
}
__device__ __forceinline__ void cpa16(uint32_t dst, const void* src) {
    asm volatile("cp.async.cg.shared.global [%0], [%1], 16;" :: "r"(dst), "l"(src));
}
#define CP_COMMIT() asm volatile("cp.async.commit_group;")
#define CP_WAIT0()  asm volatile("cp.async.wait_group 0;")
#define CP_WAIT1()  asm volatile("cp.async.wait_group 1;")
// FMA-pipe exp2 for t <= 0 (clamped), ~3e-6 rel error
__device__ __forceinline__ float exp2p(float t) {
    t = fmaxf(t, -126.f);
    const float z = t + 12582912.f;
    const int n = __float_as_int(z) - 0x4B400000;
    const float f = t - (z - 12582912.f);
    float r = 1.3333558146e-3f;
    r = fmaf(r, f, 9.6181291076e-3f);
    r = fmaf(r, f, 5.5504108664e-2f);
    r = fmaf(r, f, 2.4022650695e-1f);
    r = fmaf(r, f, 6.9314718055e-1f);
    r = fmaf(r, f, 1.0f);
    return __int_as_float(__float_as_int(r) + (n << 23));
}
__device__ __forceinline__ void split_store(__nv_bfloat16* hp, __nv_bfloat16* lp,
                                            size_t o, float v) {
    const __nv_bfloat16 h = __float2bfloat16(v);
    hp[o] = h;
    lp[o] = __float2bfloat16(v - __bfloat162float(h));
}

// ---------------------------------------------------------------------------
// split fp32 -> fp16 hi + fp16 lo, vectorized by 4
// ---------------------------------------------------------------------------
__global__ __launch_bounds__(256) void split_kernel_h(
    const float* __restrict__ in, __half* __restrict__ hi,
    __half* __restrict__ lo, int n4)
{
    const int i = blockIdx.x * blockDim.x + threadIdx.x;
    if (i >= n4) return;
    const float4 v = ((const float4*)in)[i];
    const __half h0 = __float2half_rn(v.x);
    const __half h1 = __float2half_rn(v.y);
    const __half h2 = __float2half_rn(v.z);
    const __half h3 = __float2half_rn(v.w);
    __half2 hp0 = {h0, h1}, hp1 = {h2, h3};
    __half2 lp0 = {__float2half_rn(v.x - __half2float(h0)),
                   __float2half_rn(v.y - __half2float(h1))};
    __half2 lp1 = {__float2half_rn(v.z - __half2float(h2)),
                   __float2half_rn(v.w - __half2float(h3))};
    ((__half2*)hi)[i * 2 + 0] = hp0;
    ((__half2*)hi)[i * 2 + 1] = hp1;
    ((__half2*)lo)[i * 2 + 0] = lp0;
    ((__half2*)lo)[i * 2 + 1] = lp1;
}

// ---------------------------------------------------------------------------
// transpose (hi only): W[K][N] row-major -> WT hi [N][K] fp16
// ---------------------------------------------------------------------------
__global__ void transpose_h_kernel(
    const float* __restrict__ W, __half* __restrict__ bh, int Krows, int Ncols)
{
    __shared__ float t[32][33];
    const int bx = blockIdx.x * 32;
    const int by = blockIdx.y * 32;
    const int x = threadIdx.x, y = threadIdx.y;
#pragma unroll
    for (int i = 0; i < 32; i += 8)
        t[y + i][x] = W[(size_t)(by + y + i) * Ncols + bx + x];
    __syncthreads();
#pragma unroll
    for (int i = 0; i < 32; i += 8)
        bh[(size_t)(bx + y + i) * Krows + by + x] = __float2half_rn(t[x][y + i]);
}

// ---------------------------------------------------------------------------
// fused RoPE + bf16 split: g_qkv -> qh/ql (prescaled), kh/kl, vh/vl
// ---------------------------------------------------------------------------
__global__ __launch_bounds__(256) void rope_split_kernel(
    const float* __restrict__ qkv, const float* __restrict__ cosNK,
    const float* __restrict__ sinNK,
    __nv_bfloat16* __restrict__ qh, __nv_bfloat16* __restrict__ ql,
    __nv_bfloat16* __restrict__ kh, __nv_bfloat16* __restrict__ kl,
    __nv_bfloat16* __restrict__ vh, __nv_bfloat16* __restrict__ vl)
{
    const int t = blockIdx.x * blockDim.x + threadIdx.x;
    if (t >= NTOK * NH * 40) return;
    const int j = t % 40;
    const int h = (t / 40) % NH;
    const int n = t / (40 * NH);

    const float c1 = cosNK[n * HK + j];
    const float s1 = sinNK[n * HK + j];
    const float c2 = cosNK[n * HK + j + 40];
    const float s2 = sinNK[n * HK + j + 40];

    const size_t ib = (size_t)n * (3 * DM) + h * HK;
    const size_t ob = (size_t)n * DM + h * HK;
    const float qs = 0.1118033988749895f * 1.4426950408889634f;  // scale * log2(e)

    {
        const float x1 = qkv[ib + j], x2 = qkv[ib + j + 40];
        split_store(qh, ql, ob + j,      (x1 * c1 - x2 * s1) * qs);
        split_store(qh, ql, ob + j + 40, (x2 * c2 + x1 * s2) * qs);
    }
    {
        const float x1 = qkv[ib + DM + j], x2 = qkv[ib + DM + j + 40];
        split_store(kh, kl, ob + j,      x1 * c1 - x2 * s1);
        split_store(kh, kl, ob + j + 40, x2 * c2 + x1 * s2);
    }
    {
        split_store(vh, vl, ob + j,      qkv[ib + 2 * DM + j]);
        split_store(vh, vl, ob + j + 40, qkv[ib + 2 * DM + j + 40]);
    }
}

// ---------------------------------------------------------------------------
// fp16 2-term tensor-core GEMM + bias:  C = (Ah+Al) @ Bh^T + bias
// (drops A_hi*B_lo term; error ~3e-4 rel, within 1e-3 budget)
// 2-stage cp.async, issue-ahead + wait_group 1, 60KB smem -> 2 CTAs/SM.
// ---------------------------------------------------------------------------
#define GP 40
#define BUFE (128 * GP)
#define GSMEM (6 * BUFE * 2)

__global__ __launch_bounds__(256, 2) void gemm_mma(
    const __half* __restrict__ Ah, const __half* __restrict__ Al,
    const __half* __restrict__ Bh,
    const float* __restrict__ bias, float* __restrict__ C, int N, int Kd)
{
    extern __shared__ __half smb[];
    __half* Ash = smb;
    __half* Asl = Ash + 2 * BUFE;
    __half* Bsh = Asl + 2 * BUFE;

    const int tid = threadIdx.x;
    const int lane = tid & 31;
    const int warp = tid >> 5;
    const int wm = warp >> 1;
    const int wn = warp & 1;
    const int m0 = blockIdx.y * 128;
    const int n0 = blockIdx.x * 128;

    const int r0 = tid >> 2;
    const int sg = (tid & 3) * 8;

    const __half* pAh = Ah + (size_t)(m0 + r0) * Kd + sg;
    const __half* pAl = Al + (size_t)(m0 + r0) * Kd + sg;
    const __half* pBh = Bh + (size_t)(n0 + r0) * Kd + sg;
    const size_t rstep = (size_t)64 * Kd;

    const uint32_t uAsh = smem_u32(Ash);
    const uint32_t uAsl = smem_u32(Asl);
    const uint32_t uBsh = smem_u32(Bsh);

    float acc[2][8][4];
#pragma unroll
    for (int a = 0; a < 2; a++)
#pragma unroll
        for (int b = 0; b < 8; b++)
#pragma unroll
            for (int c = 0; c < 4; c++) acc[a][b][c] = 0.f;

    auto issue = [&](int k0, int stg) {
        const uint32_t o0 = (uint32_t)(stg * BUFE + r0 * GP + sg) * 2;
        const uint32_t o1 = (uint32_t)(stg * BUFE + (r0 + 64) * GP + sg) * 2;
        cpa16(uAsh + o0, pAh + k0);  cpa16(uAsh + o1, pAh + k0 + rstep);
        cpa16(uAsl + o0, pAl + k0);  cpa16(uAsl + o1, pAl + k0 + rstep);
        cpa16(uBsh + o0, pBh + k0);  cpa16(uBsh + o1, pBh + k0 + rstep);
        CP_COMMIT();
    };

    const uint32_t aoff = (uint32_t)((wm * 32 + (lane & 15)) * GP + ((lane >> 4) << 3)) * 2;
    const uint32_t boff = (uint32_t)((wn * 64 + (lane & 15)) * GP + ((lane >> 4) << 3)) * 2;

    const int NT = Kd >> 5;
    issue(0, 0);

    for (int t = 0; t < NT; ++t) {
        if (t + 1 < NT) {
            issue((t + 1) << 5, (t + 1) & 1);
            CP_WAIT1();
        } else {
            CP_WAIT0();
        }
        __syncthreads();

        const uint32_t bb = (uint32_t)((t & 1) * BUFE * 2);
#pragma unroll
        for (int ks = 0; ks < 2; ++ks) {
            const uint32_t kso = (uint32_t)(ks * 16 * 2);
            uint32_t ah[2][4], al[2][4];
#pragma unroll
            for (int t2 = 0; t2 < 2; ++t2) {
                const uint32_t ad = bb + aoff + kso + (uint32_t)(t2 * 16 * GP * 2);
                ldsm4(ah[t2], uAsh + ad);
                ldsm4(al[t2], uAsl + ad);
            }
            uint32_t bh4[4][4];
#pragma unroll
            for (int g = 0; g < 4; ++g) {
                const uint32_t bd = bb + boff + kso + (uint32_t)(g * 16 * GP * 2);
                ldsm4(bh4[g], uBsh + bd);
            }
#pragma unroll
            for (int t2 = 0; t2 < 2; ++t2)
#pragma unroll
                for (int g = 0; g < 4; ++g)
#pragma unroll
                    for (int h = 0; h < 2; ++h) {
                        float* d = acc[t2][g * 2 + h];
                        mma16816h(d, ah[t2], bh4[g][h], bh4[g][h + 2]);
                        mma16816h(d, al[t2], bh4[g][h], bh4[g][h + 2]);
                    }
        }
        __syncthreads();
    }

#pragma unroll
    for (int t2 = 0; t2 < 2; ++t2) {
        const int row = m0 + wm * 32 + t2 * 16 + (lane >> 2);
#pragma unroll
        for (int n8 = 0; n8 < 8; ++n8) {
            const int col = n0 + wn * 64 + n8 * 8 + (lane & 3) * 2;
            const float b0 = __ldg(bias + col);
            const float b1 = __ldg(bias + col + 1);
            float2 v0 = {acc[t2][n8][0] + b0, acc[t2][n8][1] + b1};
            float2 v1 = {acc[t2][n8][2] + b0, acc[t2][n8][3] + b1};
            *(float2*)(C + (size_t)row * N + col) = v0;
            *(float2*)(C + (size_t)(row + 8) * N + col) = v1;
        }
    }
}

// ---------------------------------------------------------------------------
// Tensor-core flash attention (bf16 3-term), 128-query tile, 8 warps,
// cp.async double-buffered K/V. Epilogue writes fp16 hi/lo for GEMM2.
// ---------------------------------------------------------------------------
#define AP 88
#define KVB (64 * AP)
#define QTB (128 * AP)
#define ATT_SMEM ((2 * QTB + 8 * KVB) * 2)

__global__ __launch_bounds__(256) void attn_mma(
    const __nv_bfloat16* __restrict__ qh, const __nv_bfloat16* __restrict__ ql,
    const __nv_bfloat16* __restrict__ kh, const __nv_bfloat16* __restrict__ kl,
    const __nv_bfloat16* __restrict__ vh, const __nv_bfloat16* __restrict__ vl,
    __half* __restrict__ oh, __half* __restrict__ ol)
{
    extern __shared__ __nv_bfloat16 smb2[];
    __nv_bfloat16* Qh = smb2;            // [128][AP]
    __nv_bfloat16* Ql = Qh + QTB;
    __nv_bfloat16* KV = Ql + QTB;        // [2 buf][4 arr][64][AP]

    const int tid = threadIdx.x;
    const int lane = tid & 31;
    const int warp = tid >> 5;
    const int qt = blockIdx.x, head = blockIdx.y, seg = blockIdx.z;
    const int n0 = seg * SEGL + qt * 128;

    const uint32_t uKV = smem_u32(KV);

    auto issueKV = [&](int kb, int buf) {
        const int nk = seg * SEGL + kb * 64;
        const uint32_t bofs = (uint32_t)(buf * 4 * KVB) * 2;
#pragma unroll
        for (int i = 0; i < 3; ++i) {
            const int idx = tid + i * 256;
            if (idx < 640) {
                const int r = idx / 10, c = idx % 10;
                const uint32_t d = bofs + (uint32_t)(r * AP + c * 8) * 2 + uKV;
                const size_t g = (size_t)(nk + r) * DM + head * HK + c * 8;
                cpa16(d + 0 * KVB * 2, kh + g);
                cpa16(d + 1 * KVB * 2, kl + g);
                cpa16(d + 2 * KVB * 2, vh + g);
                cpa16(d + 3 * KVB * 2, vl + g);
            }
        }
        CP_COMMIT();
    };

    issueKV(0, 0);

    // load Q tile (pre-scaled, pre-split): 128 rows x 10 16B-groups
#pragma unroll
    for (int i = 0; i < 5; ++i) {
        const int idx = tid + i * 256;
        const int r = idx / 10, c = idx % 10;
        const size_t g = (size_t)(n0 + r) * DM + head * HK + c * 8;
        *(uint4*)(Qh + r * AP + c * 8) = *(const uint4*)(qh + g);
        *(uint4*)(Ql + r * AP + c * 8) = *(const uint4*)(ql + g);
    }
    __syncthreads();

    uint32_t qfh[5][4], qfl[5][4];
    {
        const uint32_t uQh = smem_u32(Qh), uQl = smem_u32(Ql);
        const uint32_t qoff = (uint32_t)((warp * 16 + (lane & 15)) * AP + ((lane >> 4) << 3)) * 2;
#pragma unroll
        for (int ks = 0; ks < 5; ++ks) {
            const uint32_t ad = qoff + (uint32_t)(ks * 16 * 2);
            ldsm4(qfh[ks], uQh + ad);
            ldsm4(qfl[ks], uQl + ad);
        }
    }

    const uint32_t koff = (uint32_t)((lane & 15) * AP + ((lane >> 4) << 3)) * 2;
    const uint32_t voff = (uint32_t)((((lane & 7) + (((lane >> 3) & 1) << 3)) * AP) + ((lane >> 4) << 3)) * 2;

    float of[10][4];
#pragma unroll
    for (int t = 0; t < 10; t++)
#pragma unroll
        for (int j = 0; j < 4; j++) of[t][j] = 0.f;
    float m_a = -1e30f, m_b = -1e30f, l_a = 0.f, l_b = 0.f;

    for (int kb = 0; kb < SEGL / 64; ++kb) {
        CP_WAIT0();
        __syncthreads();
        if (kb + 1 < SEGL / 64) issueKV(kb + 1, (kb + 1) & 1);

        const uint32_t bb = (uint32_t)((kb & 1) * 4 * KVB) * 2;
        const uint32_t uKh = uKV + bb;
        const uint32_t uKl = uKh + KVB * 2;
        const uint32_t uVh = uKl + KVB * 2;
        const uint32_t uVl = uVh + KVB * 2;

        // ---- S = Q @ K^T (3-term) ----
        float s[8][4];
#pragma unroll
        for (int t = 0; t < 8; t++)
#pragma unroll
            for (int j = 0; j < 4; j++) s[t][j] = 0.f;

#pragma unroll
        for (int ks = 0; ks < 5; ++ks) {
#pragma unroll
            for (int g = 0; g < 4; ++g) {
                uint32_t kfh[4], kfl[4];
                const uint32_t ka = koff + (uint32_t)((g * 16 * AP + ks * 16) * 2);
                ldsm4(kfh, uKh + ka);
                ldsm4(kfl, uKl + ka);
#pragma unroll
                for (int h = 0; h < 2; ++h) {
                    float* d = s[2 * g + h];
                    mma16816(d, qfh[ks], kfh[h], kfh[h + 2]);
                    mma16816(d, qfh[ks], kfl[h], kfl[h + 2]);
                    mma16816(d, qfl[ks], kfh[h], kfh[h + 2]);
                }
            }
        }

        // ---- online softmax (exp2 domain) ----
        float rma = NEG_INF, rmb = NEG_INF;
#pragma unroll
        for (int t = 0; t < 8; t++) {
            rma = fmaxf(rma, fmaxf(s[t][0], s[t][1]));
            rmb = fmaxf(rmb, fmaxf(s[t][2], s[t][3]));
        }
        rma = fmaxf(rma, __shfl_xor_sync(0xffffffffu, rma, 1));
        rma = fmaxf(rma, __shfl_xor_sync(0xffffffffu, rma, 2));
        rmb = fmaxf(rmb, __shfl_xor_sync(0xffffffffu, rmb, 1));
        rmb = fmaxf(rmb, __shfl_xor_sync(0xffffffffu, rmb, 2));
        const float mna = fmaxf(m_a, rma), mnb = fmaxf(m_b, rmb);
        const float corra = exp2p(m_a - mna), corrb = exp2p(m_b - mnb);
        m_a = mna; m_b = mnb;

        float suma = 0.f, sumb = 0.f;
        uint32_t pha[8], phb[8], pla[8], plb[8];
#pragma unroll
        for (int t = 0; t < 8; t++) {
            const float p0 = exp2p(s[t][0] - m_a);
            const float p1 = exp2p(s[t][1] - m_a);
            const float p2 = exp2p(s[t][2] - m_b);
            const float p3 = exp2p(s[t][3] - m_b);
            suma += p0 + p1;
            sumb += p2 + p3;
            const uint32_t ha = cvt_bf2(p1, p0);
            const uint32_t hb = cvt_bf2(p3, p2);
            pha[t] = ha; phb[t] = hb;
            const float h0 = __int_as_float(ha << 16);
            const float h1 = __int_as_float(ha & 0xFFFF0000u);
            const float h2 = __int_as_float(hb << 16);
            const float h3 = __int_as_float(hb & 0xFFFF0000u);
            pla[t] = cvt_bf2(p1 - h1, p0 - h0);
            plb[t] = cvt_bf2(p3 - h3, p2 - h2);
        }
        suma += __shfl_xor_sync(0xffffffffu, suma, 1);
        suma += __shfl_xor_sync(0xffffffffu, suma, 2);
        sumb += __shfl_xor_sync(0xffffffffu, sumb, 1);
        sumb += __shfl_xor_sync(0xffffffffu, sumb, 2);
        l_a = l_a * corra + suma;
        l_b = l_b * corrb + sumb;
#pragma unroll
        for (int t = 0; t < 10; t++) {
            of[t][0] *= corra;
            of[t][1] *= corra;
            of[t][2] *= corrb;
            of[t][3] *= corrb;
        }

        // ---- O += P @ V (3-term) ----
#pragma unroll
        for (int ks = 0; ks < 4; ++ks) {
            const uint32_t ah2[4] = {pha[2 * ks], phb[2 * ks], pha[2 * ks + 1], phb[2 * ks + 1]};
            const uint32_t al2[4] = {pla[2 * ks], plb[2 * ks], pla[2 * ks + 1], plb[2 * ks + 1]};
#pragma unroll
            for (int g = 0; g < 5; ++g) {
                uint32_t vfh[4], vfl[4];
                const uint32_t va = voff + (uint32_t)((ks * 16 * AP + g * 16) * 2);
                ldsm4t(vfh, uVh + va);
                ldsm4t(vfl, uVl + va);
#pragma unroll
                for (int h = 0; h < 2; ++h) {
                    float* d = of[2 * g + h];
                    mma16816(d, ah2, vfh[2 * h], vfh[2 * h + 1]);
                    mma16816(d, ah2, vfl[2 * h], vfl[2 * h + 1]);
                    mma16816(d, al2, vfh[2 * h], vfh[2 * h + 1]);
                }
            }
        }
    }

    // ---- write normalized output as fp16 hi/lo (GEMM2 A operand) ----
    const float inva = 1.f / l_a, invb = 1.f / l_b;
    const int rowa = n0 + warp * 16 + (lane >> 2);
    const int rowb = rowa + 8;
#pragma unroll
    for (int t = 0; t < 10; t++) {
        const int col = head * HK + t * 8 + 2 * (lane & 3);
        const float a0 = of[t][0] * inva, a1 = of[t][1] * inva;
        const float b0 = of[t][2] * invb, b1 = of[t][3] * invb;
        const __half ah0 = __float2half_rn(a0), ah1 = __float2half_rn(a1);
        const __half bh0 = __float2half_rn(b0), bh1 = __float2half_rn(b1);
        __half2 vha = {ah0, ah1};
        __half2 vla = {__float2half_rn(a0 - __half2float(ah0)),
                       __float2half_rn(a1 - __half2float(ah1))};
        __half2 vhb = {bh0, bh1};
        __half2 vlb = {__float2half_rn(b0 - __half2float(bh0)),
                       __float2half_rn(b1 - __half2float(bh1))};
        *(__half2*)(oh + (size_t)rowa * DM + col) = vha;
        *(__half2*)(ol + (size_t)rowa * DM + col) = vla;
        *(__half2*)(oh + (size_t)rowb * DM + col) = vhb;
        *(__half2*)(ol + (size_t)rowb * DM + col) = vlb;
    }
}

// ---------------------------------------------------------------------------
// Launch
// ---------------------------------------------------------------------------
extern "C" void kernel_launch(void* const* d_in, const int* in_sizes, int n_in,
                              void* d_out, int out_size)
{
    const float* hidden = (const float*)d_in[0];
    const float* cosNK  = (const float*)d_in[1];
    const float* sinNK  = (const float*)d_in[2];
    const float* qkv_w  = (const float*)d_in[3];
    const float* qkv_b  = (const float*)d_in[4];
    const float* proj_w = (const float*)d_in[5];
    const float* proj_b = (const float*)d_in[6];
    float* out = (float*)d_out;

    float* qkv = nullptr;
    __half *ah, *al, *bh;
    __nv_bfloat16 *qh, *ql, *kh, *kl, *vh, *vl;
    cudaGetSymbolAddress((void**)&qkv, g_qkv);
    cudaGetSymbolAddress((void**)&ah,  g_ah);
    cudaGetSymbolAddress((void**)&al,  g_al);
    cudaGetSymbolAddress((void**)&bh,  g_bh);
    cudaGetSymbolAddress((void**)&qh,  g_qh);
    cudaGetSymbolAddress((void**)&ql,  g_ql);
    cudaGetSymbolAddress((void**)&kh,  g_kh);
    cudaGetSymbolAddress((void**)&kl,  g_kl);
    cudaGetSymbolAddress((void**)&vh,  g_vh);
    cudaGetSymbolAddress((void**)&vl,  g_vl);

    cudaFuncSetAttribute(gemm_mma, cudaFuncAttributeMaxDynamicSharedMemorySize, GSMEM);
    cudaFuncSetAttribute(attn_mma, cudaFuncAttributeMaxDynamicSharedMemorySize, ATT_SMEM);

    const int n4 = NTOK * DM / 4;

    // 1) prep GEMM1: split hidden (fp16), transpose qkv_w (fp16 hi)
    split_kernel_h<<<(n4 + 255) / 256, 256>>>(hidden, ah, al, n4);
    transpose_h_kernel<<<dim3(3 * DM / 32, DM / 32), dim3(32, 8)>>>(qkv_w, bh, DM, 3 * DM);

    // 2) qkv = hidden @ qkv_w + qkv_b   (fp16 2-term)
    gemm_mma<<<dim3(3 * DM / 128, NTOK / 128), 256, GSMEM>>>(
        ah, al, bh, qkv_b, qkv, 3 * DM, DM);

    // 3) fused RoPE + bf16 split for attention
    {
        const int total = NTOK * NH * 40;
        rope_split_kernel<<<(total + 255) / 256, 256>>>(qkv, cosNK, sinNK,
                                                        qh, ql, kh, kl, vh, vl);
    }

    // 4) attention (bf16 3-term); writes GEMM2's A hi/lo (fp16)
    attn_mma<<<dim3(SEGL / 128, NH, NSEGS), 256, ATT_SMEM>>>(
        qh, ql, kh, kl, vh, vl, ah, al);

    // 5) prep GEMM2 weights (fp16 hi)
    transpose_h_kernel<<<dim3(DM / 32, DM / 32), dim3(32, 8)>>>(proj_w, bh, DM, DM);

    // 6) out = attn_out @ proj_w + proj_b  (fp16 2-term)
    gemm_mma<<<dim3(DM / 128, NTOK / 128), 256, GSMEM>>>(
        ah, al, bh, proj_b, out, DM, DM);
}

// round 11
// speedup vs baseline: 1.4905x; 1.1598x over previous
#include <cuda_runtime.h>
#include <cuda_fp16.h>
#include <cstdint>

// Problem constants (fixed by reference setup_inputs)
#define NTOK 16384
#define DM   1280
#define NH   16
#define HK   80
#define NSEGS 8
#define SEGL 2048

#define NEG_INF (__int_as_float(0xff800000))

// Scratch (allocation-free rule: __device__ globals)
__device__ float g_qkv[(size_t)NTOK * 3 * DM];            // [N][3*1280] fp32 (GEMM1 out)
__device__ __half g_ah[(size_t)NTOK * DM];                // GEMM A hi fp16 (hidden, then attn-out)
__device__ __half g_al[(size_t)NTOK * DM];                // GEMM A lo fp16
__device__ __half g_bh[(size_t)3 * DM * DM];              // W^T hi fp16 [N][K]
__device__ __half g_qh[(size_t)NTOK * DM];                // q hi (rope'd, prescaled)
__device__ __half g_ql[(size_t)NTOK * DM];                // q lo
__device__ __half g_kh[(size_t)NTOK * DM];                // k (rope'd, fp16)
__device__ __half g_vh[(size_t)NTOK * DM];                // v (fp16)

// ---------------------------------------------------------------------------
// helpers
// ---------------------------------------------------------------------------
__device__ __forceinline__ uint32_t smem_u32(const void* p) {
    uint32_t a;
    asm("{ .reg .u64 t; cvta.to.shared.u64 t, %1; cvt.u32.u64 %0, t; }" : "=r"(a) : "l"(p));
    return a;
}
__device__ __forceinline__ void ldsm4(uint32_t* r, uint32_t addr) {
    asm volatile("ldmatrix.sync.aligned.m8n8.x4.shared.b16 {%0,%1,%2,%3}, [%4];"
                 : "=r"(r[0]), "=r"(r[1]), "=r"(r[2]), "=r"(r[3]) : "r"(addr));
}
__device__ __forceinline__ void ldsm4t(uint32_t* r, uint32_t addr) {
    asm volatile("ldmatrix.sync.aligned.m8n8.x4.trans.shared.b16 {%0,%1,%2,%3}, [%4];"
                 : "=r"(r[0]), "=r"(r[1]), "=r"(r[2]), "=r"(r[3]) : "r"(addr));
}
// fp16 mma
__device__ __forceinline__ void mma16816h(float* d, const uint32_t* a, uint32_t b0, uint32_t b1) {
    asm volatile("mma.sync.aligned.m16n8k16.row.col.f32.f16.f16.f32 "
                 "{%0,%1,%2,%3}, {%4,%5,%6,%7}, {%8,%9}, {%0,%1,%2,%3};"
                 : "+f"(d[0]), "+f"(d[1]), "+f"(d[2]), "+f"(d[3])
                 : "r"(a[0]), "r"(a[1]), "r"(a[2]), "r"(a[3]), "r"(b0), "r"(b1));
}
__device__ __forceinline__ uint32_t pack_h2(__half lo, __half hi) {
    __half2 v = {lo, hi};
    return *(uint32_t*)&v;
}
__device__ __forceinline__ void cpa16(uint32_t dst, const void* src) {
    asm volatile("cp.async.cg.shared.global [%0], [%1], 16;" :: "r"(dst), "l"(src));
}
#define CP_COMMIT() asm volatile("cp.async.commit_group;")
#define CP_WAIT0()  asm volatile("cp.async.wait_group 0;")
#define CP_WAIT1()  asm volatile("cp.async.wait_group 1;")
// FMA-pipe exp2 for t <= 0 (clamped), ~3e-6 rel error
__device__ __forceinline__ float exp2p(float t) {
    t = fmaxf(t, -126.f);
    const float z = t + 12582912.f;
    const int n = __float_as_int(z) - 0x4B400000;
    const float f = t - (z - 12582912.f);
    float r = 1.3333558146e-3f;
    r = fmaf(r, f, 9.6181291076e-3f);
    r = fmaf(r, f, 5.5504108664e-2f);
    r = fmaf(r, f, 2.4022650695e-1f);
    r = fmaf(r, f, 6.9314718055e-1f);
    r = fmaf(r, f, 1.0f);
    return __int_as_float(__float_as_int(r) + (n << 23));
}
__device__ __forceinline__ void split_store_h(__half* hp, __half* lp, size_t o, float v) {
    const __half h = __float2half_rn(v);
    hp[o] = h;
    lp[o] = __float2half_rn(v - __half2float(h));
}

// ---------------------------------------------------------------------------
// split fp32 -> fp16 hi + fp16 lo, vectorized by 4
// ---------------------------------------------------------------------------
__global__ __launch_bounds__(256) void split_kernel_h(
    const float* __restrict__ in, __half* __restrict__ hi,
    __half* __restrict__ lo, int n4)
{
    const int i = blockIdx.x * blockDim.x + threadIdx.x;
    if (i >= n4) return;
    const float4 v = ((const float4*)in)[i];
    const __half h0 = __float2half_rn(v.x);
    const __half h1 = __float2half_rn(v.y);
    const __half h2 = __float2half_rn(v.z);
    const __half h3 = __float2half_rn(v.w);
    __half2 hp0 = {h0, h1}, hp1 = {h2, h3};
    __half2 lp0 = {__float2half_rn(v.x - __half2float(h0)),
                   __float2half_rn(v.y - __half2float(h1))};
    __half2 lp1 = {__float2half_rn(v.z - __half2float(h2)),
                   __float2half_rn(v.w - __half2float(h3))};
    ((__half2*)hi)[i * 2 + 0] = hp0;
    ((__half2*)hi)[i * 2 + 1] = hp1;
    ((__half2*)lo)[i * 2 + 0] = lp0;
    ((__half2*)lo)[i * 2 + 1] = lp1;
}

// ---------------------------------------------------------------------------
// transpose (hi only): W[K][N] row-major -> WT hi [N][K] fp16
// ---------------------------------------------------------------------------
__global__ void transpose_h_kernel(
    const float* __restrict__ W, __half* __restrict__ bh, int Krows, int Ncols)
{
    __shared__ float t[32][33];
    const int bx = blockIdx.x * 32;
    const int by = blockIdx.y * 32;
    const int x = threadIdx.x, y = threadIdx.y;
#pragma unroll
    for (int i = 0; i < 32; i += 8)
        t[y + i][x] = W[(size_t)(by + y + i) * Ncols + bx + x];
    __syncthreads();
#pragma unroll
    for (int i = 0; i < 32; i += 8)
        bh[(size_t)(bx + y + i) * Krows + by + x] = __float2half_rn(t[x][y + i]);
}

// ---------------------------------------------------------------------------
// fused RoPE + fp16 convert: g_qkv -> q hi/lo (prescaled), k, v
// ---------------------------------------------------------------------------
__global__ __launch_bounds__(256) void rope_split_kernel(
    const float* __restrict__ qkv, const float* __restrict__ cosNK,
    const float* __restrict__ sinNK,
    __half* __restrict__ qh, __half* __restrict__ ql,
    __half* __restrict__ kh, __half* __restrict__ vh)
{
    const int t = blockIdx.x * blockDim.x + threadIdx.x;
    if (t >= NTOK * NH * 40) return;
    const int j = t % 40;
    const int h = (t / 40) % NH;
    const int n = t / (40 * NH);

    const float c1 = cosNK[n * HK + j];
    const float s1 = sinNK[n * HK + j];
    const float c2 = cosNK[n * HK + j + 40];
    const float s2 = sinNK[n * HK + j + 40];

    const size_t ib = (size_t)n * (3 * DM) + h * HK;
    const size_t ob = (size_t)n * DM + h * HK;
    const float qs = 0.1118033988749895f * 1.4426950408889634f;  // scale * log2(e)

    {
        const float x1 = qkv[ib + j], x2 = qkv[ib + j + 40];
        split_store_h(qh, ql, ob + j,      (x1 * c1 - x2 * s1) * qs);
        split_store_h(qh, ql, ob + j + 40, (x2 * c2 + x1 * s2) * qs);
    }
    {
        const float x1 = qkv[ib + DM + j], x2 = qkv[ib + DM + j + 40];
        kh[ob + j]      = __float2half_rn(x1 * c1 - x2 * s1);
        kh[ob + j + 40] = __float2half_rn(x2 * c2 + x1 * s2);
    }
    {
        vh[ob + j]      = __float2half_rn(qkv[ib + 2 * DM + j]);
        vh[ob + j + 40] = __float2half_rn(qkv[ib + 2 * DM + j + 40]);
    }
}

// ---------------------------------------------------------------------------
// fp16 2-term tensor-core GEMM + bias:  C = (Ah+Al) @ Bh^T + bias
// 2-stage cp.async, issue-ahead + wait_group 1, 60KB smem -> 2 CTAs/SM.
// ---------------------------------------------------------------------------
#define GP 40
#define BUFE (128 * GP)
#define GSMEM (6 * BUFE * 2)

__global__ __launch_bounds__(256, 2) void gemm_mma(
    const __half* __restrict__ Ah, const __half* __restrict__ Al,
    const __half* __restrict__ Bh,
    const float* __restrict__ bias, float* __restrict__ C, int N, int Kd)
{
    extern __shared__ __half smb[];
    __half* Ash = smb;
    __half* Asl = Ash + 2 * BUFE;
    __half* Bsh = Asl + 2 * BUFE;

    const int tid = threadIdx.x;
    const int lane = tid & 31;
    const int warp = tid >> 5;
    const int wm = warp >> 1;
    const int wn = warp & 1;
    const int m0 = blockIdx.y * 128;
    const int n0 = blockIdx.x * 128;

    const int r0 = tid >> 2;
    const int sg = (tid & 3) * 8;

    const __half* pAh = Ah + (size_t)(m0 + r0) * Kd + sg;
    const __half* pAl = Al + (size_t)(m0 + r0) * Kd + sg;
    const __half* pBh = Bh + (size_t)(n0 + r0) * Kd + sg;
    const size_t rstep = (size_t)64 * Kd;

    const uint32_t uAsh = smem_u32(Ash);
    const uint32_t uAsl = smem_u32(Asl);
    const uint32_t uBsh = smem_u32(Bsh);

    float acc[2][8][4];
#pragma unroll
    for (int a = 0; a < 2; a++)
#pragma unroll
        for (int b = 0; b < 8; b++)
#pragma unroll
            for (int c = 0; c < 4; c++) acc[a][b][c] = 0.f;

    auto issue = [&](int k0, int stg) {
        const uint32_t o0 = (uint32_t)(stg * BUFE + r0 * GP + sg) * 2;
        const uint32_t o1 = (uint32_t)(stg * BUFE + (r0 + 64) * GP + sg) * 2;
        cpa16(uAsh + o0, pAh + k0);  cpa16(uAsh + o1, pAh + k0 + rstep);
        cpa16(uAsl + o0, pAl + k0);  cpa16(uAsl + o1, pAl + k0 + rstep);
        cpa16(uBsh + o0, pBh + k0);  cpa16(uBsh + o1, pBh + k0 + rstep);
        CP_COMMIT();
    };

    const uint32_t aoff = (uint32_t)((wm * 32 + (lane & 15)) * GP + ((lane >> 4) << 3)) * 2;
    const uint32_t boff = (uint32_t)((wn * 64 + (lane & 15)) * GP + ((lane >> 4) << 3)) * 2;

    const int NT = Kd >> 5;
    issue(0, 0);

    for (int t = 0; t < NT; ++t) {
        if (t + 1 < NT) {
            issue((t + 1) << 5, (t + 1) & 1);
            CP_WAIT1();
        } else {
            CP_WAIT0();
        }
        __syncthreads();

        const uint32_t bb = (uint32_t)((t & 1) * BUFE * 2);
#pragma unroll
        for (int ks = 0; ks < 2; ++ks) {
            const uint32_t kso = (uint32_t)(ks * 16 * 2);
            uint32_t ah[2][4], al[2][4];
#pragma unroll
            for (int t2 = 0; t2 < 2; ++t2) {
                const uint32_t ad = bb + aoff + kso + (uint32_t)(t2 * 16 * GP * 2);
                ldsm4(ah[t2], uAsh + ad);
                ldsm4(al[t2], uAsl + ad);
            }
            uint32_t bh4[4][4];
#pragma unroll
            for (int g = 0; g < 4; ++g) {
                const uint32_t bd = bb + boff + kso + (uint32_t)(g * 16 * GP * 2);
                ldsm4(bh4[g], uBsh + bd);
            }
#pragma unroll
            for (int t2 = 0; t2 < 2; ++t2)
#pragma unroll
                for (int g = 0; g < 4; ++g)
#pragma unroll
                    for (int h = 0; h < 2; ++h) {
                        float* d = acc[t2][g * 2 + h];
                        mma16816h(d, ah[t2], bh4[g][h], bh4[g][h + 2]);
                        mma16816h(d, al[t2], bh4[g][h], bh4[g][h + 2]);
                    }
        }
        __syncthreads();
    }

#pragma unroll
    for (int t2 = 0; t2 < 2; ++t2) {
        const int row = m0 + wm * 32 + t2 * 16 + (lane >> 2);
#pragma unroll
        for (int n8 = 0; n8 < 8; ++n8) {
            const int col = n0 + wn * 64 + n8 * 8 + (lane & 3) * 2;
            const float b0 = __ldg(bias + col);
            const float b1 = __ldg(bias + col + 1);
            float2 v0 = {acc[t2][n8][0] + b0, acc[t2][n8][1] + b1};
            float2 v1 = {acc[t2][n8][2] + b0, acc[t2][n8][3] + b1};
            *(float2*)(C + (size_t)row * N + col) = v0;
            *(float2*)(C + (size_t)(row + 8) * N + col) = v1;
        }
    }
}

// ---------------------------------------------------------------------------
// Tensor-core flash attention, fp16 2-term:
//   S = (qh+ql) @ kh^T  (exact in q; error = q·(k-kh))
//   O = (ph+pl) @ vh    (exact in p; error = p·(v-vh))
// 128-query tile, 8 warps, cp.async double-buffered K/V (one array each).
// Epilogue writes fp16 hi/lo for GEMM2.
// ---------------------------------------------------------------------------
#define AP 88
#define KVB (64 * AP)
#define QTB (128 * AP)
#define ATT_SMEM ((2 * QTB + 4 * KVB) * 2)

__global__ __launch_bounds__(256) void attn_mma(
    const __half* __restrict__ qh, const __half* __restrict__ ql,
    const __half* __restrict__ kh, const __half* __restrict__ vh,
    __half* __restrict__ oh, __half* __restrict__ ol)
{
    extern __shared__ __half smb2[];
    __half* Qh = smb2;            // [128][AP]
    __half* Ql = Qh + QTB;
    __half* KV = Ql + QTB;        // [2 buf][2 arr][64][AP]  arr: K, V

    const int tid = threadIdx.x;
    const int lane = tid & 31;
    const int warp = tid >> 5;
    const int qt = blockIdx.x, head = blockIdx.y, seg = blockIdx.z;
    const int n0 = seg * SEGL + qt * 128;

    const uint32_t uKV = smem_u32(KV);

    auto issueKV = [&](int kb, int buf) {
        const int nk = seg * SEGL + kb * 64;
        const uint32_t bofs = (uint32_t)(buf * 2 * KVB) * 2;
#pragma unroll
        for (int i = 0; i < 3; ++i) {
            const int idx = tid + i * 256;
            if (idx < 640) {
                const int r = idx / 10, c = idx % 10;
                const uint32_t d = bofs + (uint32_t)(r * AP + c * 8) * 2 + uKV;
                const size_t g = (size_t)(nk + r) * DM + head * HK + c * 8;
                cpa16(d + 0 * KVB * 2, kh + g);
                cpa16(d + 1 * KVB * 2, vh + g);
            }
        }
        CP_COMMIT();
    };

    issueKV(0, 0);

    // load Q tile (pre-scaled, pre-split): 128 rows x 10 16B-groups
#pragma unroll
    for (int i = 0; i < 5; ++i) {
        const int idx = tid + i * 256;
        const int r = idx / 10, c = idx % 10;
        const size_t g = (size_t)(n0 + r) * DM + head * HK + c * 8;
        *(uint4*)(Qh + r * AP + c * 8) = *(const uint4*)(qh + g);
        *(uint4*)(Ql + r * AP + c * 8) = *(const uint4*)(ql + g);
    }
    __syncthreads();

    uint32_t qfh[5][4], qfl[5][4];
    {
        const uint32_t uQh = smem_u32(Qh), uQl = smem_u32(Ql);
        const uint32_t qoff = (uint32_t)((warp * 16 + (lane & 15)) * AP + ((lane >> 4) << 3)) * 2;
#pragma unroll
        for (int ks = 0; ks < 5; ++ks) {
            const uint32_t ad = qoff + (uint32_t)(ks * 16 * 2);
            ldsm4(qfh[ks], uQh + ad);
            ldsm4(qfl[ks], uQl + ad);
        }
    }

    const uint32_t koff = (uint32_t)((lane & 15) * AP + ((lane >> 4) << 3)) * 2;
    const uint32_t voff = (uint32_t)((((lane & 7) + (((lane >> 3) & 1) << 3)) * AP) + ((lane >> 4) << 3)) * 2;

    float of[10][4];
#pragma unroll
    for (int t = 0; t < 10; t++)
#pragma unroll
        for (int j = 0; j < 4; j++) of[t][j] = 0.f;
    float m_a = -1e30f, m_b = -1e30f, l_a = 0.f, l_b = 0.f;

    for (int kb = 0; kb < SEGL / 64; ++kb) {
        CP_WAIT0();
        __syncthreads();
        if (kb + 1 < SEGL / 64) issueKV(kb + 1, (kb + 1) & 1);

        const uint32_t bb = (uint32_t)((kb & 1) * 2 * KVB) * 2;
        const uint32_t uKh = uKV + bb;
        const uint32_t uVh = uKh + KVB * 2;

        // ---- S = Q @ K^T (2-term: qh·kh + ql·kh) ----
        float s[8][4];
#pragma unroll
        for (int t = 0; t < 8; t++)
#pragma unroll
            for (int j = 0; j < 4; j++) s[t][j] = 0.f;

#pragma unroll
        for (int ks = 0; ks < 5; ++ks) {
#pragma unroll
            for (int g = 0; g < 4; ++g) {
                uint32_t kf[4];
                const uint32_t ka = koff + (uint32_t)((g * 16 * AP + ks * 16) * 2);
                ldsm4(kf, uKh + ka);
#pragma unroll
                for (int h = 0; h < 2; ++h) {
                    float* d = s[2 * g + h];
                    mma16816h(d, qfh[ks], kf[h], kf[h + 2]);
                    mma16816h(d, qfl[ks], kf[h], kf[h + 2]);
                }
            }
        }

        // ---- online softmax (exp2 domain) ----
        float rma = NEG_INF, rmb = NEG_INF;
#pragma unroll
        for (int t = 0; t < 8; t++) {
            rma = fmaxf(rma, fmaxf(s[t][0], s[t][1]));
            rmb = fmaxf(rmb, fmaxf(s[t][2], s[t][3]));
        }
        rma = fmaxf(rma, __shfl_xor_sync(0xffffffffu, rma, 1));
        rma = fmaxf(rma, __shfl_xor_sync(0xffffffffu, rma, 2));
        rmb = fmaxf(rmb, __shfl_xor_sync(0xffffffffu, rmb, 1));
        rmb = fmaxf(rmb, __shfl_xor_sync(0xffffffffu, rmb, 2));
        const float mna = fmaxf(m_a, rma), mnb = fmaxf(m_b, rmb);
        const float corra = exp2p(m_a - mna), corrb = exp2p(m_b - mnb);
        m_a = mna; m_b = mnb;

        float suma = 0.f, sumb = 0.f;
        uint32_t pha[8], phb[8], pla[8], plb[8];
#pragma unroll
        for (int t = 0; t < 8; t++) {
            const float p0 = exp2p(s[t][0] - m_a);
            const float p1 = exp2p(s[t][1] - m_a);
            const float p2 = exp2p(s[t][2] - m_b);
            const float p3 = exp2p(s[t][3] - m_b);
            suma += p0 + p1;
            sumb += p2 + p3;
            const __half h0 = __float2half_rn(p0), h1 = __float2half_rn(p1);
            const __half h2 = __float2half_rn(p2), h3 = __float2half_rn(p3);
            pha[t] = pack_h2(h0, h1);
            phb[t] = pack_h2(h2, h3);
            pla[t] = pack_h2(__float2half_rn(p0 - __half2float(h0)),
                             __float2half_rn(p1 - __half2float(h1)));
            plb[t] = pack_h2(__float2half_rn(p2 - __half2float(h2)),
                             __float2half_rn(p3 - __half2float(h3)));
        }
        suma += __shfl_xor_sync(0xffffffffu, suma, 1);
        suma += __shfl_xor_sync(0xffffffffu, suma, 2);
        sumb += __shfl_xor_sync(0xffffffffu, sumb, 1);
        sumb += __shfl_xor_sync(0xffffffffu, sumb, 2);
        l_a = l_a * corra + suma;
        l_b = l_b * corrb + sumb;
#pragma unroll
        for (int t = 0; t < 10; t++) {
            of[t][0] *= corra;
            of[t][1] *= corra;
            of[t][2] *= corrb;
            of[t][3] *= corrb;
        }

        // ---- O += P @ V (2-term: ph·vh + pl·vh) ----
#pragma unroll
        for (int ks = 0; ks < 4; ++ks) {
            const uint32_t ah2[4] = {pha[2 * ks], phb[2 * ks], pha[2 * ks + 1], phb[2 * ks + 1]};
            const uint32_t al2[4] = {pla[2 * ks], plb[2 * ks], pla[2 * ks + 1], plb[2 * ks + 1]};
#pragma unroll
            for (int g = 0; g < 5; ++g) {
                uint32_t vf[4];
                const uint32_t va = voff + (uint32_t)((ks * 16 * AP + g * 16) * 2);
                ldsm4t(vf, uVh + va);
#pragma unroll
                for (int h = 0; h < 2; ++h) {
                    float* d = of[2 * g + h];
                    mma16816h(d, ah2, vf[2 * h], vf[2 * h + 1]);
                    mma16816h(d, al2, vf[2 * h], vf[2 * h + 1]);
                }
            }
        }
    }

    // ---- write normalized output as fp16 hi/lo (GEMM2 A operand) ----
    const float inva = 1.f / l_a, invb = 1.f / l_b;
    const int rowa = n0 + warp * 16 + (lane >> 2);
    const int rowb = rowa + 8;
#pragma unroll
    for (int t = 0; t < 10; t++) {
        const int col = head * HK + t * 8 + 2 * (lane & 3);
        const float a0 = of[t][0] * inva, a1 = of[t][1] * inva;
        const float b0 = of[t][2] * invb, b1 = of[t][3] * invb;
        const __half ah0 = __float2half_rn(a0), ah1 = __float2half_rn(a1);
        const __half bh0 = __float2half_rn(b0), bh1 = __float2half_rn(b1);
        __half2 vha = {ah0, ah1};
        __half2 vla = {__float2half_rn(a0 - __half2float(ah0)),
                       __float2half_rn(a1 - __half2float(ah1))};
        __half2 vhb = {bh0, bh1};
        __half2 vlb = {__float2half_rn(b0 - __half2float(bh0)),
                       __float2half_rn(b1 - __half2float(bh1))};
        *(__half2*)(oh + (size_t)rowa * DM + col) = vha;
        *(__half2*)(ol + (size_t)rowa * DM + col) = vla;
        *(__half2*)(oh + (size_t)rowb * DM + col) = vhb;
        *(__half2*)(ol + (size_t)rowb * DM + col) = vlb;
    }
}

// ---------------------------------------------------------------------------
// Launch
// ---------------------------------------------------------------------------
extern "C" void kernel_launch(void* const* d_in, const int* in_sizes, int n_in,
                              void* d_out, int out_size)
{
    const float* hidden = (const float*)d_in[0];
    const float* cosNK  = (const float*)d_in[1];
    const float* sinNK  = (const float*)d_in[2];
    const float* qkv_w  = (const float*)d_in[3];
    const float* qkv_b  = (const float*)d_in[4];
    const float* proj_w = (const float*)d_in[5];
    const float* proj_b = (const float*)d_in[6];
    float* out = (float*)d_out;

    float* qkv = nullptr;
    __half *ah, *al, *bh, *qh, *ql, *kh, *vh;
    cudaGetSymbolAddress((void**)&qkv, g_qkv);
    cudaGetSymbolAddress((void**)&ah,  g_ah);
    cudaGetSymbolAddress((void**)&al,  g_al);
    cudaGetSymbolAddress((void**)&bh,  g_bh);
    cudaGetSymbolAddress((void**)&qh,  g_qh);
    cudaGetSymbolAddress((void**)&ql,  g_ql);
    cudaGetSymbolAddress((void**)&kh,  g_kh);
    cudaGetSymbolAddress((void**)&vh,  g_vh);

    cudaFuncSetAttribute(gemm_mma, cudaFuncAttributeMaxDynamicSharedMemorySize, GSMEM);
    cudaFuncSetAttribute(attn_mma, cudaFuncAttributeMaxDynamicSharedMemorySize, ATT_SMEM);

    const int n4 = NTOK * DM / 4;

    // 1) prep GEMM1: split hidden (fp16), transpose qkv_w (fp16 hi)
    split_kernel_h<<<(n4 + 255) / 256, 256>>>(hidden, ah, al, n4);
    transpose_h_kernel<<<dim3(3 * DM / 32, DM / 32), dim3(32, 8)>>>(qkv_w, bh, DM, 3 * DM);

    // 2) qkv = hidden @ qkv_w + qkv_b   (fp16 2-term)
    gemm_mma<<<dim3(3 * DM / 128, NTOK / 128), 256, GSMEM>>>(
        ah, al, bh, qkv_b, qkv, 3 * DM, DM);

    // 3) fused RoPE + fp16 convert for attention
    {
        const int total = NTOK * NH * 40;
        rope_split_kernel<<<(total + 255) / 256, 256>>>(qkv, cosNK, sinNK,
                                                        qh, ql, kh, vh);
    }

    // 4) attention (fp16 2-term); writes GEMM2's A hi/lo (fp16)
    attn_mma<<<dim3(SEGL / 128, NH, NSEGS), 256, ATT_SMEM>>>(
        qh, ql, kh, vh, ah, al);

    // 5) prep GEMM2 weights (fp16 hi)
    transpose_h_kernel<<<dim3(DM / 32, DM / 32), dim3(32, 8)>>>(proj_w, bh, DM, DM);

    // 6) out = attn_out @ proj_w + proj_b  (fp16 2-term)
    gemm_mma<<<dim3(DM / 128, NTOK / 128), 256, GSMEM>>>(
        ah, al, bh, proj_b, out, DM, DM);
}

// round 12
// speedup vs baseline: 1.9764x; 1.3260x over previous
#include <cuda_runtime.h>
#include <cuda_fp16.h>
#include <cstdint>

// Problem constants (fixed by reference setup_inputs)
#define NTOK 16384
#define DM   1280
#define NH   16
#define HK   80
#define NSEGS 8
#define SEGL 2048

#define NEG_INF (__int_as_float(0xff800000))

// Scratch (allocation-free rule: __device__ globals)
__device__ float g_qkv[(size_t)NTOK * 3 * DM];            // [N][3*1280] fp32 (GEMM1 out)
__device__ __half g_ah[(size_t)NTOK * DM];                // GEMM A fp16 (hidden, then attn-out)
__device__ __half g_bh[(size_t)3 * DM * DM];              // W^T fp16 [N][K]
__device__ __half g_qh[(size_t)NTOK * DM];                // q hi (rope'd, prescaled)
__device__ __half g_ql[(size_t)NTOK * DM];                // q lo
__device__ __half g_kh[(size_t)NTOK * DM];                // k (rope'd, fp16)
__device__ __half g_vh[(size_t)NTOK * DM];                // v (fp16)

// ---------------------------------------------------------------------------
// helpers
// ---------------------------------------------------------------------------
__device__ __forceinline__ uint32_t smem_u32(const void* p) {
    uint32_t a;
    asm("{ .reg .u64 t; cvta.to.shared.u64 t, %1; cvt.u32.u64 %0, t; }" : "=r"(a) : "l"(p));
    return a;
}
__device__ __forceinline__ void ldsm4(uint32_t* r, uint32_t addr) {
    asm volatile("ldmatrix.sync.aligned.m8n8.x4.shared.b16 {%0,%1,%2,%3}, [%4];"
                 : "=r"(r[0]), "=r"(r[1]), "=r"(r[2]), "=r"(r[3]) : "r"(addr));
}
__device__ __forceinline__ void ldsm4t(uint32_t* r, uint32_t addr) {
    asm volatile("ldmatrix.sync.aligned.m8n8.x4.trans.shared.b16 {%0,%1,%2,%3}, [%4];"
                 : "=r"(r[0]), "=r"(r[1]), "=r"(r[2]), "=r"(r[3]) : "r"(addr));
}
// fp16 mma
__device__ __forceinline__ void mma16816h(float* d, const uint32_t* a, uint32_t b0, uint32_t b1) {
    asm volatile("mma.sync.aligned.m16n8k16.row.col.f32.f16.f16.f32 "
                 "{%0,%1,%2,%3}, {%4,%5,%6,%7}, {%8,%9}, {%0,%1,%2,%3};"
                 : "+f"(d[0]), "+f"(d[1]), "+f"(d[2]), "+f"(d[3])
                 : "r"(a[0]), "r"(a[1]), "r"(a[2]), "r"(a[3]), "r"(b0), "r"(b1));
}
__device__ __forceinline__ uint32_t pack_h2(__half lo, __half hi) {
    __half2 v = {lo, hi};
    return *(uint32_t*)&v;
}
__device__ __forceinline__ void cpa16(uint32_t dst, const void* src) {
    asm volatile("cp.async.cg.shared.global [%0], [%1], 16;" :: "r"(dst), "l"(src));
}
#define CP_COMMIT() asm volatile("cp.async.commit_group;")
#define CP_WAIT0()  asm volatile("cp.async.wait_group 0;")
#define CP_WAIT1()  asm volatile("cp.async.wait_group 1;")
// FMA-pipe exp2 for t <= 0 (clamped), ~3e-6 rel error
__device__ __forceinline__ float exp2p(float t) {
    t = fmaxf(t, -126.f);
    const float z = t + 12582912.f;
    const int n = __float_as_int(z) - 0x4B400000;
    const float f = t - (z - 12582912.f);
    float r = 1.3333558146e-3f;
    r = fmaf(r, f, 9.6181291076e-3f);
    r = fmaf(r, f, 5.5504108664e-2f);
    r = fmaf(r, f, 2.4022650695e-1f);
    r = fmaf(r, f, 6.9314718055e-1f);
    r = fmaf(r, f, 1.0f);
    return __int_as_float(__float_as_int(r) + (n << 23));
}
__device__ __forceinline__ void split_store_h(__half* hp, __half* lp, size_t o, float v) {
    const __half h = __float2half_rn(v);
    hp[o] = h;
    lp[o] = __float2half_rn(v - __half2float(h));
}

// ---------------------------------------------------------------------------
// convert fp32 -> fp16, vectorized by 4
// ---------------------------------------------------------------------------
__global__ __launch_bounds__(256) void cvt_h_kernel(
    const float* __restrict__ in, __half* __restrict__ hi, int n4)
{
    const int i = blockIdx.x * blockDim.x + threadIdx.x;
    if (i >= n4) return;
    const float4 v = ((const float4*)in)[i];
    __half2 hp0 = {__float2half_rn(v.x), __float2half_rn(v.y)};
    __half2 hp1 = {__float2half_rn(v.z), __float2half_rn(v.w)};
    ((__half2*)hi)[i * 2 + 0] = hp0;
    ((__half2*)hi)[i * 2 + 1] = hp1;
}

// ---------------------------------------------------------------------------
// transpose: W[K][N] row-major -> WT [N][K] fp16
// ---------------------------------------------------------------------------
__global__ void transpose_h_kernel(
    const float* __restrict__ W, __half* __restrict__ bh, int Krows, int Ncols)
{
    __shared__ float t[32][33];
    const int bx = blockIdx.x * 32;
    const int by = blockIdx.y * 32;
    const int x = threadIdx.x, y = threadIdx.y;
#pragma unroll
    for (int i = 0; i < 32; i += 8)
        t[y + i][x] = W[(size_t)(by + y + i) * Ncols + bx + x];
    __syncthreads();
#pragma unroll
    for (int i = 0; i < 32; i += 8)
        bh[(size_t)(bx + y + i) * Krows + by + x] = __float2half_rn(t[x][y + i]);
}

// ---------------------------------------------------------------------------
// fused RoPE + fp16 convert: g_qkv -> q hi/lo (prescaled), k, v
// ---------------------------------------------------------------------------
__global__ __launch_bounds__(256) void rope_split_kernel(
    const float* __restrict__ qkv, const float* __restrict__ cosNK,
    const float* __restrict__ sinNK,
    __half* __restrict__ qh, __half* __restrict__ ql,
    __half* __restrict__ kh, __half* __restrict__ vh)
{
    const int t = blockIdx.x * blockDim.x + threadIdx.x;
    if (t >= NTOK * NH * 40) return;
    const int j = t % 40;
    const int h = (t / 40) % NH;
    const int n = t / (40 * NH);

    const float c1 = cosNK[n * HK + j];
    const float s1 = sinNK[n * HK + j];
    const float c2 = cosNK[n * HK + j + 40];
    const float s2 = sinNK[n * HK + j + 40];

    const size_t ib = (size_t)n * (3 * DM) + h * HK;
    const size_t ob = (size_t)n * DM + h * HK;
    const float qs = 0.1118033988749895f * 1.4426950408889634f;  // scale * log2(e)

    {
        const float x1 = qkv[ib + j], x2 = qkv[ib + j + 40];
        split_store_h(qh, ql, ob + j,      (x1 * c1 - x2 * s1) * qs);
        split_store_h(qh, ql, ob + j + 40, (x2 * c2 + x1 * s2) * qs);
    }
    {
        const float x1 = qkv[ib + DM + j], x2 = qkv[ib + DM + j + 40];
        kh[ob + j]      = __float2half_rn(x1 * c1 - x2 * s1);
        kh[ob + j + 40] = __float2half_rn(x2 * c2 + x1 * s2);
    }
    {
        vh[ob + j]      = __float2half_rn(qkv[ib + 2 * DM + j]);
        vh[ob + j + 40] = __float2half_rn(qkv[ib + 2 * DM + j + 40]);
    }
}

// ---------------------------------------------------------------------------
// fp16 1-term tensor-core GEMM + bias:  C = Ah @ Bh^T + bias
// 2-stage cp.async, issue-ahead + wait_group 1, 40KB smem.
// ---------------------------------------------------------------------------
#define GP 40
#define BUFE (128 * GP)
#define GSMEM (4 * BUFE * 2)

__global__ __launch_bounds__(256, 2) void gemm_mma(
    const __half* __restrict__ Ah, const __half* __restrict__ Bh,
    const float* __restrict__ bias, float* __restrict__ C, int N, int Kd)
{
    extern __shared__ __half smb[];
    __half* Ash = smb;
    __half* Bsh = Ash + 2 * BUFE;

    const int tid = threadIdx.x;
    const int lane = tid & 31;
    const int warp = tid >> 5;
    const int wm = warp >> 1;
    const int wn = warp & 1;
    const int m0 = blockIdx.y * 128;
    const int n0 = blockIdx.x * 128;

    const int r0 = tid >> 2;
    const int sg = (tid & 3) * 8;

    const __half* pAh = Ah + (size_t)(m0 + r0) * Kd + sg;
    const __half* pBh = Bh + (size_t)(n0 + r0) * Kd + sg;
    const size_t rstep = (size_t)64 * Kd;

    const uint32_t uAsh = smem_u32(Ash);
    const uint32_t uBsh = smem_u32(Bsh);

    float acc[2][8][4];
#pragma unroll
    for (int a = 0; a < 2; a++)
#pragma unroll
        for (int b = 0; b < 8; b++)
#pragma unroll
            for (int c = 0; c < 4; c++) acc[a][b][c] = 0.f;

    auto issue = [&](int k0, int stg) {
        const uint32_t o0 = (uint32_t)(stg * BUFE + r0 * GP + sg) * 2;
        const uint32_t o1 = (uint32_t)(stg * BUFE + (r0 + 64) * GP + sg) * 2;
        cpa16(uAsh + o0, pAh + k0);  cpa16(uAsh + o1, pAh + k0 + rstep);
        cpa16(uBsh + o0, pBh + k0);  cpa16(uBsh + o1, pBh + k0 + rstep);
        CP_COMMIT();
    };

    const uint32_t aoff = (uint32_t)((wm * 32 + (lane & 15)) * GP + ((lane >> 4) << 3)) * 2;
    const uint32_t boff = (uint32_t)((wn * 64 + (lane & 15)) * GP + ((lane >> 4) << 3)) * 2;

    const int NT = Kd >> 5;
    issue(0, 0);

    for (int t = 0; t < NT; ++t) {
        if (t + 1 < NT) {
            issue((t + 1) << 5, (t + 1) & 1);
            CP_WAIT1();
        } else {
            CP_WAIT0();
        }
        __syncthreads();

        const uint32_t bb = (uint32_t)((t & 1) * BUFE * 2);
#pragma unroll
        for (int ks = 0; ks < 2; ++ks) {
            const uint32_t kso = (uint32_t)(ks * 16 * 2);
            uint32_t ah[2][4];
#pragma unroll
            for (int t2 = 0; t2 < 2; ++t2) {
                const uint32_t ad = bb + aoff + kso + (uint32_t)(t2 * 16 * GP * 2);
                ldsm4(ah[t2], uAsh + ad);
            }
            uint32_t bh4[4][4];
#pragma unroll
            for (int g = 0; g < 4; ++g) {
                const uint32_t bd = bb + boff + kso + (uint32_t)(g * 16 * GP * 2);
                ldsm4(bh4[g], uBsh + bd);
            }
#pragma unroll
            for (int t2 = 0; t2 < 2; ++t2)
#pragma unroll
                for (int g = 0; g < 4; ++g)
#pragma unroll
                    for (int h = 0; h < 2; ++h)
                        mma16816h(acc[t2][g * 2 + h], ah[t2], bh4[g][h], bh4[g][h + 2]);
        }
        __syncthreads();
    }

#pragma unroll
    for (int t2 = 0; t2 < 2; ++t2) {
        const int row = m0 + wm * 32 + t2 * 16 + (lane >> 2);
#pragma unroll
        for (int n8 = 0; n8 < 8; ++n8) {
            const int col = n0 + wn * 64 + n8 * 8 + (lane & 3) * 2;
            const float b0 = __ldg(bias + col);
            const float b1 = __ldg(bias + col + 1);
            float2 v0 = {acc[t2][n8][0] + b0, acc[t2][n8][1] + b1};
            float2 v1 = {acc[t2][n8][2] + b0, acc[t2][n8][3] + b1};
            *(float2*)(C + (size_t)row * N + col) = v0;
            *(float2*)(C + (size_t)(row + 8) * N + col) = v1;
        }
    }
}

// ---------------------------------------------------------------------------
// Tensor-core flash attention, fp16 2-term:
//   S = (qh+ql) @ kh^T ;  O = (ph+pl) @ vh
// 128-query tile, 8 warps, cp.async double-buffered K/V.
// Epilogue writes fp16 (GEMM2 A operand, 1-term).
// ---------------------------------------------------------------------------
#define AP 88
#define KVB (64 * AP)
#define QTB (128 * AP)
#define ATT_SMEM ((2 * QTB + 4 * KVB) * 2)

__global__ __launch_bounds__(256) void attn_mma(
    const __half* __restrict__ qh, const __half* __restrict__ ql,
    const __half* __restrict__ kh, const __half* __restrict__ vh,
    __half* __restrict__ oh)
{
    extern __shared__ __half smb2[];
    __half* Qh = smb2;            // [128][AP]
    __half* Ql = Qh + QTB;
    __half* KV = Ql + QTB;        // [2 buf][2 arr][64][AP]  arr: K, V

    const int tid = threadIdx.x;
    const int lane = tid & 31;
    const int warp = tid >> 5;
    const int qt = blockIdx.x, head = blockIdx.y, seg = blockIdx.z;
    const int n0 = seg * SEGL + qt * 128;

    const uint32_t uKV = smem_u32(KV);

    auto issueKV = [&](int kb, int buf) {
        const int nk = seg * SEGL + kb * 64;
        const uint32_t bofs = (uint32_t)(buf * 2 * KVB) * 2;
#pragma unroll
        for (int i = 0; i < 3; ++i) {
            const int idx = tid + i * 256;
            if (idx < 640) {
                const int r = idx / 10, c = idx % 10;
                const uint32_t d = bofs + (uint32_t)(r * AP + c * 8) * 2 + uKV;
                const size_t g = (size_t)(nk + r) * DM + head * HK + c * 8;
                cpa16(d + 0 * KVB * 2, kh + g);
                cpa16(d + 1 * KVB * 2, vh + g);
            }
        }
        CP_COMMIT();
    };

    issueKV(0, 0);

    // load Q tile (pre-scaled, pre-split): 128 rows x 10 16B-groups
#pragma unroll
    for (int i = 0; i < 5; ++i) {
        const int idx = tid + i * 256;
        const int r = idx / 10, c = idx % 10;
        const size_t g = (size_t)(n0 + r) * DM + head * HK + c * 8;
        *(uint4*)(Qh + r * AP + c * 8) = *(const uint4*)(qh + g);
        *(uint4*)(Ql + r * AP + c * 8) = *(const uint4*)(ql + g);
    }
    __syncthreads();

    uint32_t qfh[5][4], qfl[5][4];
    {
        const uint32_t uQh = smem_u32(Qh), uQl = smem_u32(Ql);
        const uint32_t qoff = (uint32_t)((warp * 16 + (lane & 15)) * AP + ((lane >> 4) << 3)) * 2;
#pragma unroll
        for (int ks = 0; ks < 5; ++ks) {
            const uint32_t ad = qoff + (uint32_t)(ks * 16 * 2);
            ldsm4(qfh[ks], uQh + ad);
            ldsm4(qfl[ks], uQl + ad);
        }
    }

    const uint32_t koff = (uint32_t)((lane & 15) * AP + ((lane >> 4) << 3)) * 2;
    const uint32_t voff = (uint32_t)((((lane & 7) + (((lane >> 3) & 1) << 3)) * AP) + ((lane >> 4) << 3)) * 2;

    float of[10][4];
#pragma unroll
    for (int t = 0; t < 10; t++)
#pragma unroll
        for (int j = 0; j < 4; j++) of[t][j] = 0.f;
    float m_a = -1e30f, m_b = -1e30f, l_a = 0.f, l_b = 0.f;

    for (int kb = 0; kb < SEGL / 64; ++kb) {
        CP_WAIT0();
        __syncthreads();
        if (kb + 1 < SEGL / 64) issueKV(kb + 1, (kb + 1) & 1);

        const uint32_t bb = (uint32_t)((kb & 1) * 2 * KVB) * 2;
        const uint32_t uKh = uKV + bb;
        const uint32_t uVh = uKh + KVB * 2;

        // ---- S = Q @ K^T (2-term) ----
        float s[8][4];
#pragma unroll
        for (int t = 0; t < 8; t++)
#pragma unroll
            for (int j = 0; j < 4; j++) s[t][j] = 0.f;

#pragma unroll
        for (int ks = 0; ks < 5; ++ks) {
#pragma unroll
            for (int g = 0; g < 4; ++g) {
                uint32_t kf[4];
                const uint32_t ka = koff + (uint32_t)((g * 16 * AP + ks * 16) * 2);
                ldsm4(kf, uKh + ka);
#pragma unroll
                for (int h = 0; h < 2; ++h) {
                    float* d = s[2 * g + h];
                    mma16816h(d, qfh[ks], kf[h], kf[h + 2]);
                    mma16816h(d, qfl[ks], kf[h], kf[h + 2]);
                }
            }
        }

        // ---- online softmax (exp2 domain) ----
        float rma = NEG_INF, rmb = NEG_INF;
#pragma unroll
        for (int t = 0; t < 8; t++) {
            rma = fmaxf(rma, fmaxf(s[t][0], s[t][1]));
            rmb = fmaxf(rmb, fmaxf(s[t][2], s[t][3]));
        }
        rma = fmaxf(rma, __shfl_xor_sync(0xffffffffu, rma, 1));
        rma = fmaxf(rma, __shfl_xor_sync(0xffffffffu, rma, 2));
        rmb = fmaxf(rmb, __shfl_xor_sync(0xffffffffu, rmb, 1));
        rmb = fmaxf(rmb, __shfl_xor_sync(0xffffffffu, rmb, 2));
        const float mna = fmaxf(m_a, rma), mnb = fmaxf(m_b, rmb);
        const float corra = exp2p(m_a - mna), corrb = exp2p(m_b - mnb);
        m_a = mna; m_b = mnb;

        float suma = 0.f, sumb = 0.f;
        uint32_t pha[8], phb[8], pla[8], plb[8];
#pragma unroll
        for (int t = 0; t < 8; t++) {
            const float p0 = exp2p(s[t][0] - m_a);
            const float p1 = exp2p(s[t][1] - m_a);
            const float p2 = exp2p(s[t][2] - m_b);
            const float p3 = exp2p(s[t][3] - m_b);
            suma += p0 + p1;
            sumb += p2 + p3;
            const __half h0 = __float2half_rn(p0), h1 = __float2half_rn(p1);
            const __half h2 = __float2half_rn(p2), h3 = __float2half_rn(p3);
            pha[t] = pack_h2(h0, h1);
            phb[t] = pack_h2(h2, h3);
            pla[t] = pack_h2(__float2half_rn(p0 - __half2float(h0)),
                             __float2half_rn(p1 - __half2float(h1)));
            plb[t] = pack_h2(__float2half_rn(p2 - __half2float(h2)),
                             __float2half_rn(p3 - __half2float(h3)));
        }
        suma += __shfl_xor_sync(0xffffffffu, suma, 1);
        suma += __shfl_xor_sync(0xffffffffu, suma, 2);
        sumb += __shfl_xor_sync(0xffffffffu, sumb, 1);
        sumb += __shfl_xor_sync(0xffffffffu, sumb, 2);
        l_a = l_a * corra + suma;
        l_b = l_b * corrb + sumb;
#pragma unroll
        for (int t = 0; t < 10; t++) {
            of[t][0] *= corra;
            of[t][1] *= corra;
            of[t][2] *= corrb;
            of[t][3] *= corrb;
        }

        // ---- O += P @ V (2-term) ----
#pragma unroll
        for (int ks = 0; ks < 4; ++ks) {
            const uint32_t ah2[4] = {pha[2 * ks], phb[2 * ks], pha[2 * ks + 1], phb[2 * ks + 1]};
            const uint32_t al2[4] = {pla[2 * ks], plb[2 * ks], pla[2 * ks + 1], plb[2 * ks + 1]};
#pragma unroll
            for (int g = 0; g < 5; ++g) {
                uint32_t vf[4];
                const uint32_t va = voff + (uint32_t)((ks * 16 * AP + g * 16) * 2);
                ldsm4t(vf, uVh + va);
#pragma unroll
                for (int h = 0; h < 2; ++h) {
                    float* d = of[2 * g + h];
                    mma16816h(d, ah2, vf[2 * h], vf[2 * h + 1]);
                    mma16816h(d, al2, vf[2 * h], vf[2 * h + 1]);
                }
            }
        }
    }

    // ---- write normalized output as fp16 (GEMM2 A operand) ----
    const float inva = 1.f / l_a, invb = 1.f / l_b;
    const int rowa = n0 + warp * 16 + (lane >> 2);
    const int rowb = rowa + 8;
#pragma unroll
    for (int t = 0; t < 10; t++) {
        const int col = head * HK + t * 8 + 2 * (lane & 3);
        __half2 vha = {__float2half_rn(of[t][0] * inva), __float2half_rn(of[t][1] * inva)};
        __half2 vhb = {__float2half_rn(of[t][2] * invb), __float2half_rn(of[t][3] * invb)};
        *(__half2*)(oh + (size_t)rowa * DM + col) = vha;
        *(__half2*)(oh + (size_t)rowb * DM + col) = vhb;
    }
}

// ---------------------------------------------------------------------------
// Launch
// ---------------------------------------------------------------------------
extern "C" void kernel_launch(void* const* d_in, const int* in_sizes, int n_in,
                              void* d_out, int out_size)
{
    const float* hidden = (const float*)d_in[0];
    const float* cosNK  = (const float*)d_in[1];
    const float* sinNK  = (const float*)d_in[2];
    const float* qkv_w  = (const float*)d_in[3];
    const float* qkv_b  = (const float*)d_in[4];
    const float* proj_w = (const float*)d_in[5];
    const float* proj_b = (const float*)d_in[6];
    float* out = (float*)d_out;

    float* qkv = nullptr;
    __half *ah, *bh, *qh, *ql, *kh, *vh;
    cudaGetSymbolAddress((void**)&qkv, g_qkv);
    cudaGetSymbolAddress((void**)&ah,  g_ah);
    cudaGetSymbolAddress((void**)&bh,  g_bh);
    cudaGetSymbolAddress((void**)&qh,  g_qh);
    cudaGetSymbolAddress((void**)&ql,  g_ql);
    cudaGetSymbolAddress((void**)&kh,  g_kh);
    cudaGetSymbolAddress((void**)&vh,  g_vh);

    cudaFuncSetAttribute(gemm_mma, cudaFuncAttributeMaxDynamicSharedMemorySize, GSMEM);
    cudaFuncSetAttribute(attn_mma, cudaFuncAttributeMaxDynamicSharedMemorySize, ATT_SMEM);

    const int n4 = NTOK * DM / 4;

    // 1) prep GEMM1: convert hidden (fp16), transpose qkv_w (fp16)
    cvt_h_kernel<<<(n4 + 255) / 256, 256>>>(hidden, ah, n4);
    transpose_h_kernel<<<dim3(3 * DM / 32, DM / 32), dim3(32, 8)>>>(qkv_w, bh, DM, 3 * DM);

    // 2) qkv = hidden @ qkv_w + qkv_b   (fp16 1-term)
    gemm_mma<<<dim3(3 * DM / 128, NTOK / 128), 256, GSMEM>>>(
        ah, bh, qkv_b, qkv, 3 * DM, DM);

    // 3) fused RoPE + fp16 convert for attention
    {
        const int total = NTOK * NH * 40;
        rope_split_kernel<<<(total + 255) / 256, 256>>>(qkv, cosNK, sinNK,
                                                        qh, ql, kh, vh);
    }

    // 4) attention (fp16 2-term); writes GEMM2's A (fp16)
    attn_mma<<<dim3(SEGL / 128, NH, NSEGS), 256, ATT_SMEM>>>(
        qh, ql, kh, vh, ah);

    // 5) prep GEMM2 weights (fp16)
    transpose_h_kernel<<<dim3(DM / 32, DM / 32), dim3(32, 8)>>>(proj_w, bh, DM, DM);

    // 6) out = attn_out @ proj_w + proj_b  (fp16 1-term)
    gemm_mma<<<dim3(DM / 128, NTOK / 128), 256, GSMEM>>>(
        ah, bh, proj_b, out, DM, DM);
}

// round 13
// speedup vs baseline: 2.3188x; 1.1733x over previous
#include <cuda_runtime.h>
#include <cuda_fp16.h>
#include <cstdint>

// Problem constants (fixed by reference setup_inputs)
#define NTOK 16384
#define DM   1280
#define NH   16
#define HK   80
#define NSEGS 8
#define SEGL 2048

#define NEG_INF (__int_as_float(0xff800000))

// Scratch (allocation-free rule: __device__ globals)
__device__ float g_qkv[(size_t)NTOK * 3 * DM];            // [N][3*1280] fp32 (GEMM1 out)
__device__ __half g_ah[(size_t)NTOK * DM];                // GEMM A fp16 (hidden, then attn-out)
__device__ __half g_bh[(size_t)3 * DM * DM];              // W^T fp16 [N][K]
__device__ __half g_qh[(size_t)NTOK * DM];                // q (rope'd, prescaled, fp16)
__device__ __half g_kh[(size_t)NTOK * DM];                // k (rope'd, fp16)
__device__ __half g_vh[(size_t)NTOK * DM];                // v (fp16)

// ---------------------------------------------------------------------------
// helpers
// ---------------------------------------------------------------------------
__device__ __forceinline__ uint32_t smem_u32(const void* p) {
    uint32_t a;
    asm("{ .reg .u64 t; cvta.to.shared.u64 t, %1; cvt.u32.u64 %0, t; }" : "=r"(a) : "l"(p));
    return a;
}
__device__ __forceinline__ void ldsm4(uint32_t* r, uint32_t addr) {
    asm volatile("ldmatrix.sync.aligned.m8n8.x4.shared.b16 {%0,%1,%2,%3}, [%4];"
                 : "=r"(r[0]), "=r"(r[1]), "=r"(r[2]), "=r"(r[3]) : "r"(addr));
}
__device__ __forceinline__ void ldsm4t(uint32_t* r, uint32_t addr) {
    asm volatile("ldmatrix.sync.aligned.m8n8.x4.trans.shared.b16 {%0,%1,%2,%3}, [%4];"
                 : "=r"(r[0]), "=r"(r[1]), "=r"(r[2]), "=r"(r[3]) : "r"(addr));
}
// fp16 mma
__device__ __forceinline__ void mma16816h(float* d, const uint32_t* a, uint32_t b0, uint32_t b1) {
    asm volatile("mma.sync.aligned.m16n8k16.row.col.f32.f16.f16.f32 "
                 "{%0,%1,%2,%3}, {%4,%5,%6,%7}, {%8,%9}, {%0,%1,%2,%3};"
                 : "+f"(d[0]), "+f"(d[1]), "+f"(d[2]), "+f"(d[3])
                 : "r"(a[0]), "r"(a[1]), "r"(a[2]), "r"(a[3]), "r"(b0), "r"(b1));
}
__device__ __forceinline__ uint32_t pack_h2(__half lo, __half hi) {
    __half2 v = {lo, hi};
    return *(uint32_t*)&v;
}
__device__ __forceinline__ void cpa16(uint32_t dst, const void* src) {
    asm volatile("cp.async.cg.shared.global [%0], [%1], 16;" :: "r"(dst), "l"(src));
}
#define CP_COMMIT() asm volatile("cp.async.commit_group;")
#define CP_WAIT0()  asm volatile("cp.async.wait_group 0;")
#define CP_WAIT1()  asm volatile("cp.async.wait_group 1;")
// FMA-pipe exp2 for t <= 0 (clamped), ~3e-6 rel error
__device__ __forceinline__ float exp2p(float t) {
    t = fmaxf(t, -126.f);
    const float z = t + 12582912.f;
    const int n = __float_as_int(z) - 0x4B400000;
    const float f = t - (z - 12582912.f);
    float r = 1.3333558146e-3f;
    r = fmaf(r, f, 9.6181291076e-3f);
    r = fmaf(r, f, 5.5504108664e-2f);
    r = fmaf(r, f, 2.4022650695e-1f);
    r = fmaf(r, f, 6.9314718055e-1f);
    r = fmaf(r, f, 1.0f);
    return __int_as_float(__float_as_int(r) + (n << 23));
}

// ---------------------------------------------------------------------------
// convert fp32 -> fp16, vectorized by 4
// ---------------------------------------------------------------------------
__global__ __launch_bounds__(256) void cvt_h_kernel(
    const float* __restrict__ in, __half* __restrict__ hi, int n4)
{
    const int i = blockIdx.x * blockDim.x + threadIdx.x;
    if (i >= n4) return;
    const float4 v = ((const float4*)in)[i];
    __half2 hp0 = {__float2half_rn(v.x), __float2half_rn(v.y)};
    __half2 hp1 = {__float2half_rn(v.z), __float2half_rn(v.w)};
    ((__half2*)hi)[i * 2 + 0] = hp0;
    ((__half2*)hi)[i * 2 + 1] = hp1;
}

// ---------------------------------------------------------------------------
// transpose: W[K][N] row-major -> WT [N][K] fp16
// ---------------------------------------------------------------------------
__global__ void transpose_h_kernel(
    const float* __restrict__ W, __half* __restrict__ bh, int Krows, int Ncols)
{
    __shared__ float t[32][33];
    const int bx = blockIdx.x * 32;
    const int by = blockIdx.y * 32;
    const int x = threadIdx.x, y = threadIdx.y;
#pragma unroll
    for (int i = 0; i < 32; i += 8)
        t[y + i][x] = W[(size_t)(by + y + i) * Ncols + bx + x];
    __syncthreads();
#pragma unroll
    for (int i = 0; i < 32; i += 8)
        bh[(size_t)(bx + y + i) * Krows + by + x] = __float2half_rn(t[x][y + i]);
}

// ---------------------------------------------------------------------------
// fused RoPE + fp16 convert: g_qkv -> q (prescaled), k, v   (all fp16)
// ---------------------------------------------------------------------------
__global__ __launch_bounds__(256) void rope_split_kernel(
    const float* __restrict__ qkv, const float* __restrict__ cosNK,
    const float* __restrict__ sinNK,
    __half* __restrict__ qh, __half* __restrict__ kh, __half* __restrict__ vh)
{
    const int t = blockIdx.x * blockDim.x + threadIdx.x;
    if (t >= NTOK * NH * 40) return;
    const int j = t % 40;
    const int h = (t / 40) % NH;
    const int n = t / (40 * NH);

    const float c1 = cosNK[n * HK + j];
    const float s1 = sinNK[n * HK + j];
    const float c2 = cosNK[n * HK + j + 40];
    const float s2 = sinNK[n * HK + j + 40];

    const size_t ib = (size_t)n * (3 * DM) + h * HK;
    const size_t ob = (size_t)n * DM + h * HK;
    const float qs = 0.1118033988749895f * 1.4426950408889634f;  // scale * log2(e)

    {
        const float x1 = qkv[ib + j], x2 = qkv[ib + j + 40];
        qh[ob + j]      = __float2half_rn((x1 * c1 - x2 * s1) * qs);
        qh[ob + j + 40] = __float2half_rn((x2 * c2 + x1 * s2) * qs);
    }
    {
        const float x1 = qkv[ib + DM + j], x2 = qkv[ib + DM + j + 40];
        kh[ob + j]      = __float2half_rn(x1 * c1 - x2 * s1);
        kh[ob + j + 40] = __float2half_rn(x2 * c2 + x1 * s2);
    }
    {
        vh[ob + j]      = __float2half_rn(qkv[ib + 2 * DM + j]);
        vh[ob + j + 40] = __float2half_rn(qkv[ib + 2 * DM + j + 40]);
    }
}

// ---------------------------------------------------------------------------
// fp16 1-term tensor-core GEMM + bias:  C = Ah @ Bh^T + bias
// 2-stage cp.async, issue-ahead + wait_group 1, 40KB smem.
// ---------------------------------------------------------------------------
#define GP 40
#define BUFE (128 * GP)
#define GSMEM (4 * BUFE * 2)

__global__ __launch_bounds__(256, 2) void gemm_mma(
    const __half* __restrict__ Ah, const __half* __restrict__ Bh,
    const float* __restrict__ bias, float* __restrict__ C, int N, int Kd)
{
    extern __shared__ __half smb[];
    __half* Ash = smb;
    __half* Bsh = Ash + 2 * BUFE;

    const int tid = threadIdx.x;
    const int lane = tid & 31;
    const int warp = tid >> 5;
    const int wm = warp >> 1;
    const int wn = warp & 1;
    const int m0 = blockIdx.y * 128;
    const int n0 = blockIdx.x * 128;

    const int r0 = tid >> 2;
    const int sg = (tid & 3) * 8;

    const __half* pAh = Ah + (size_t)(m0 + r0) * Kd + sg;
    const __half* pBh = Bh + (size_t)(n0 + r0) * Kd + sg;
    const size_t rstep = (size_t)64 * Kd;

    const uint32_t uAsh = smem_u32(Ash);
    const uint32_t uBsh = smem_u32(Bsh);

    float acc[2][8][4];
#pragma unroll
    for (int a = 0; a < 2; a++)
#pragma unroll
        for (int b = 0; b < 8; b++)
#pragma unroll
            for (int c = 0; c < 4; c++) acc[a][b][c] = 0.f;

    auto issue = [&](int k0, int stg) {
        const uint32_t o0 = (uint32_t)(stg * BUFE + r0 * GP + sg) * 2;
        const uint32_t o1 = (uint32_t)(stg * BUFE + (r0 + 64) * GP + sg) * 2;
        cpa16(uAsh + o0, pAh + k0);  cpa16(uAsh + o1, pAh + k0 + rstep);
        cpa16(uBsh + o0, pBh + k0);  cpa16(uBsh + o1, pBh + k0 + rstep);
        CP_COMMIT();
    };

    const uint32_t aoff = (uint32_t)((wm * 32 + (lane & 15)) * GP + ((lane >> 4) << 3)) * 2;
    const uint32_t boff = (uint32_t)((wn * 64 + (lane & 15)) * GP + ((lane >> 4) << 3)) * 2;

    const int NT = Kd >> 5;
    issue(0, 0);

    for (int t = 0; t < NT; ++t) {
        if (t + 1 < NT) {
            issue((t + 1) << 5, (t + 1) & 1);
            CP_WAIT1();
        } else {
            CP_WAIT0();
        }
        __syncthreads();

        const uint32_t bb = (uint32_t)((t & 1) * BUFE * 2);
#pragma unroll
        for (int ks = 0; ks < 2; ++ks) {
            const uint32_t kso = (uint32_t)(ks * 16 * 2);
            uint32_t ah[2][4];
#pragma unroll
            for (int t2 = 0; t2 < 2; ++t2) {
                const uint32_t ad = bb + aoff + kso + (uint32_t)(t2 * 16 * GP * 2);
                ldsm4(ah[t2], uAsh + ad);
            }
            uint32_t bh4[4][4];
#pragma unroll
            for (int g = 0; g < 4; ++g) {
                const uint32_t bd = bb + boff + kso + (uint32_t)(g * 16 * GP * 2);
                ldsm4(bh4[g], uBsh + bd);
            }
#pragma unroll
            for (int t2 = 0; t2 < 2; ++t2)
#pragma unroll
                for (int g = 0; g < 4; ++g)
#pragma unroll
                    for (int h = 0; h < 2; ++h)
                        mma16816h(acc[t2][g * 2 + h], ah[t2], bh4[g][h], bh4[g][h + 2]);
        }
        __syncthreads();
    }

#pragma unroll
    for (int t2 = 0; t2 < 2; ++t2) {
        const int row = m0 + wm * 32 + t2 * 16 + (lane >> 2);
#pragma unroll
        for (int n8 = 0; n8 < 8; ++n8) {
            const int col = n0 + wn * 64 + n8 * 8 + (lane & 3) * 2;
            const float b0 = __ldg(bias + col);
            const float b1 = __ldg(bias + col + 1);
            float2 v0 = {acc[t2][n8][0] + b0, acc[t2][n8][1] + b1};
            float2 v1 = {acc[t2][n8][2] + b0, acc[t2][n8][3] + b1};
            *(float2*)(C + (size_t)row * N + col) = v0;
            *(float2*)(C + (size_t)(row + 8) * N + col) = v1;
        }
    }
}

// ---------------------------------------------------------------------------
// Tensor-core flash attention, fp16 1-term:
//   S = q @ k^T ;  O = p @ v   (all fp16 operands, fp32 accum)
// 128-query tile, 8 warps, cp.async double-buffered K/V.
// Epilogue writes fp16 (GEMM2 A operand).
// ---------------------------------------------------------------------------
#define AP 88
#define KVB (64 * AP)
#define QTB (128 * AP)
#define ATT_SMEM ((QTB + 4 * KVB) * 2)

__global__ __launch_bounds__(256) void attn_mma(
    const __half* __restrict__ qh, const __half* __restrict__ kh,
    const __half* __restrict__ vh, __half* __restrict__ oh)
{
    extern __shared__ __half smb2[];
    __half* Qh = smb2;            // [128][AP]
    __half* KV = Qh + QTB;        // [2 buf][2 arr][64][AP]  arr: K, V

    const int tid = threadIdx.x;
    const int lane = tid & 31;
    const int warp = tid >> 5;
    const int qt = blockIdx.x, head = blockIdx.y, seg = blockIdx.z;
    const int n0 = seg * SEGL + qt * 128;

    const uint32_t uKV = smem_u32(KV);

    auto issueKV = [&](int kb, int buf) {
        const int nk = seg * SEGL + kb * 64;
        const uint32_t bofs = (uint32_t)(buf * 2 * KVB) * 2;
#pragma unroll
        for (int i = 0; i < 3; ++i) {
            const int idx = tid + i * 256;
            if (idx < 640) {
                const int r = idx / 10, c = idx % 10;
                const uint32_t d = bofs + (uint32_t)(r * AP + c * 8) * 2 + uKV;
                const size_t g = (size_t)(nk + r) * DM + head * HK + c * 8;
                cpa16(d + 0 * KVB * 2, kh + g);
                cpa16(d + 1 * KVB * 2, vh + g);
            }
        }
        CP_COMMIT();
    };

    issueKV(0, 0);

    // load Q tile (pre-scaled fp16): 128 rows x 10 16B-groups
#pragma unroll
    for (int i = 0; i < 5; ++i) {
        const int idx = tid + i * 256;
        const int r = idx / 10, c = idx % 10;
        const size_t g = (size_t)(n0 + r) * DM + head * HK + c * 8;
        *(uint4*)(Qh + r * AP + c * 8) = *(const uint4*)(qh + g);
    }
    __syncthreads();

    uint32_t qf[5][4];
    {
        const uint32_t uQh = smem_u32(Qh);
        const uint32_t qoff = (uint32_t)((warp * 16 + (lane & 15)) * AP + ((lane >> 4) << 3)) * 2;
#pragma unroll
        for (int ks = 0; ks < 5; ++ks)
            ldsm4(qf[ks], uQh + qoff + (uint32_t)(ks * 16 * 2));
    }

    const uint32_t koff = (uint32_t)((lane & 15) * AP + ((lane >> 4) << 3)) * 2;
    const uint32_t voff = (uint32_t)((((lane & 7) + (((lane >> 3) & 1) << 3)) * AP) + ((lane >> 4) << 3)) * 2;

    float of[10][4];
#pragma unroll
    for (int t = 0; t < 10; t++)
#pragma unroll
        for (int j = 0; j < 4; j++) of[t][j] = 0.f;
    float m_a = -1e30f, m_b = -1e30f, l_a = 0.f, l_b = 0.f;

    for (int kb = 0; kb < SEGL / 64; ++kb) {
        CP_WAIT0();
        __syncthreads();
        if (kb + 1 < SEGL / 64) issueKV(kb + 1, (kb + 1) & 1);

        const uint32_t bb = (uint32_t)((kb & 1) * 2 * KVB) * 2;
        const uint32_t uKh = uKV + bb;
        const uint32_t uVh = uKh + KVB * 2;

        // ---- S = Q @ K^T (1-term fp16) ----
        float s[8][4];
#pragma unroll
        for (int t = 0; t < 8; t++)
#pragma unroll
            for (int j = 0; j < 4; j++) s[t][j] = 0.f;

#pragma unroll
        for (int ks = 0; ks < 5; ++ks) {
#pragma unroll
            for (int g = 0; g < 4; ++g) {
                uint32_t kf[4];
                const uint32_t ka = koff + (uint32_t)((g * 16 * AP + ks * 16) * 2);
                ldsm4(kf, uKh + ka);
#pragma unroll
                for (int h = 0; h < 2; ++h)
                    mma16816h(s[2 * g + h], qf[ks], kf[h], kf[h + 2]);
            }
        }

        // ---- online softmax (exp2 domain) ----
        float rma = NEG_INF, rmb = NEG_INF;
#pragma unroll
        for (int t = 0; t < 8; t++) {
            rma = fmaxf(rma, fmaxf(s[t][0], s[t][1]));
            rmb = fmaxf(rmb, fmaxf(s[t][2], s[t][3]));
        }
        rma = fmaxf(rma, __shfl_xor_sync(0xffffffffu, rma, 1));
        rma = fmaxf(rma, __shfl_xor_sync(0xffffffffu, rma, 2));
        rmb = fmaxf(rmb, __shfl_xor_sync(0xffffffffu, rmb, 1));
        rmb = fmaxf(rmb, __shfl_xor_sync(0xffffffffu, rmb, 2));
        const float mna = fmaxf(m_a, rma), mnb = fmaxf(m_b, rmb);
        const float corra = exp2p(m_a - mna), corrb = exp2p(m_b - mnb);
        m_a = mna; m_b = mnb;

        float suma = 0.f, sumb = 0.f;
        uint32_t pha[8], phb[8];
#pragma unroll
        for (int t = 0; t < 8; t++) {
            const float p0 = exp2p(s[t][0] - m_a);
            const float p1 = exp2p(s[t][1] - m_a);
            const float p2 = exp2p(s[t][2] - m_b);
            const float p3 = exp2p(s[t][3] - m_b);
            suma += p0 + p1;
            sumb += p2 + p3;
            pha[t] = pack_h2(__float2half_rn(p0), __float2half_rn(p1));
            phb[t] = pack_h2(__float2half_rn(p2), __float2half_rn(p3));
        }
        suma += __shfl_xor_sync(0xffffffffu, suma, 1);
        suma += __shfl_xor_sync(0xffffffffu, suma, 2);
        sumb += __shfl_xor_sync(0xffffffffu, sumb, 1);
        sumb += __shfl_xor_sync(0xffffffffu, sumb, 2);
        l_a = l_a * corra + suma;
        l_b = l_b * corrb + sumb;
#pragma unroll
        for (int t = 0; t < 10; t++) {
            of[t][0] *= corra;
            of[t][1] *= corra;
            of[t][2] *= corrb;
            of[t][3] *= corrb;
        }

        // ---- O += P @ V (1-term fp16) ----
#pragma unroll
        for (int ks = 0; ks < 4; ++ks) {
            const uint32_t ah2[4] = {pha[2 * ks], phb[2 * ks], pha[2 * ks + 1], phb[2 * ks + 1]};
#pragma unroll
            for (int g = 0; g < 5; ++g) {
                uint32_t vf[4];
                const uint32_t va = voff + (uint32_t)((ks * 16 * AP + g * 16) * 2);
                ldsm4t(vf, uVh + va);
#pragma unroll
                for (int h = 0; h < 2; ++h)
                    mma16816h(of[2 * g + h], ah2, vf[2 * h], vf[2 * h + 1]);
            }
        }
    }

    // ---- write normalized output as fp16 (GEMM2 A operand) ----
    const float inva = 1.f / l_a, invb = 1.f / l_b;
    const int rowa = n0 + warp * 16 + (lane >> 2);
    const int rowb = rowa + 8;
#pragma unroll
    for (int t = 0; t < 10; t++) {
        const int col = head * HK + t * 8 + 2 * (lane & 3);
        __half2 vha = {__float2half_rn(of[t][0] * inva), __float2half_rn(of[t][1] * inva)};
        __half2 vhb = {__float2half_rn(of[t][2] * invb), __float2half_rn(of[t][3] * invb)};
        *(__half2*)(oh + (size_t)rowa * DM + col) = vha;
        *(__half2*)(oh + (size_t)rowb * DM + col) = vhb;
    }
}

// ---------------------------------------------------------------------------
// Launch
// ---------------------------------------------------------------------------
extern "C" void kernel_launch(void* const* d_in, const int* in_sizes, int n_in,
                              void* d_out, int out_size)
{
    const float* hidden = (const float*)d_in[0];
    const float* cosNK  = (const float*)d_in[1];
    const float* sinNK  = (const float*)d_in[2];
    const float* qkv_w  = (const float*)d_in[3];
    const float* qkv_b  = (const float*)d_in[4];
    const float* proj_w = (const float*)d_in[5];
    const float* proj_b = (const float*)d_in[6];
    float* out = (float*)d_out;

    float* qkv = nullptr;
    __half *ah, *bh, *qh, *kh, *vh;
    cudaGetSymbolAddress((void**)&qkv, g_qkv);
    cudaGetSymbolAddress((void**)&ah,  g_ah);
    cudaGetSymbolAddress((void**)&bh,  g_bh);
    cudaGetSymbolAddress((void**)&qh,  g_qh);
    cudaGetSymbolAddress((void**)&kh,  g_kh);
    cudaGetSymbolAddress((void**)&vh,  g_vh);

    cudaFuncSetAttribute(gemm_mma, cudaFuncAttributeMaxDynamicSharedMemorySize, GSMEM);
    cudaFuncSetAttribute(attn_mma, cudaFuncAttributeMaxDynamicSharedMemorySize, ATT_SMEM);

    const int n4 = NTOK * DM / 4;

    // 1) prep GEMM1: convert hidden (fp16), transpose qkv_w (fp16)
    cvt_h_kernel<<<(n4 + 255) / 256, 256>>>(hidden, ah, n4);
    transpose_h_kernel<<<dim3(3 * DM / 32, DM / 32), dim3(32, 8)>>>(qkv_w, bh, DM, 3 * DM);

    // 2) qkv = hidden @ qkv_w + qkv_b   (fp16 1-term)
    gemm_mma<<<dim3(3 * DM / 128, NTOK / 128), 256, GSMEM>>>(
        ah, bh, qkv_b, qkv, 3 * DM, DM);

    // 3) fused RoPE + fp16 convert for attention
    {
        const int total = NTOK * NH * 40;
        rope_split_kernel<<<(total + 255) / 256, 256>>>(qkv, cosNK, sinNK, qh, kh, vh);
    }

    // 4) attention (fp16 1-term); writes GEMM2's A (fp16)
    attn_mma<<<dim3(SEGL / 128, NH, NSEGS), 256, ATT_SMEM>>>(qh, kh, vh, ah);

    // 5) prep GEMM2 weights (fp16)
    transpose_h_kernel<<<dim3(DM / 32, DM / 32), dim3(32, 8)>>>(proj_w, bh, DM, DM);

    // 6) out = attn_out @ proj_w + proj_b  (fp16 1-term)
    gemm_mma<<<dim3(DM / 128, NTOK / 128), 256, GSMEM>>>(
        ah, bh, proj_b, out, DM, DM);
}

// round 14
// speedup vs baseline: 2.3780x; 1.0255x over previous
#include <cuda_runtime.h>
#include <cuda_fp16.h>
#include <cstdint>

// Problem constants (fixed by reference setup_inputs)
#define NTOK 16384
#define DM   1280
#define NH   16
#define HK   80
#define NSEGS 8
#define SEGL 2048

#define NEG_INF (__int_as_float(0xff800000))

// Scratch (allocation-free rule: __device__ globals)
__device__ __half g_ah[(size_t)NTOK * DM];                // GEMM A fp16 (hidden, then attn-out)
__device__ __half g_bh[(size_t)3 * DM * DM];              // W^T fp16 [N][K]
__device__ __half g_qh[(size_t)NTOK * DM];                // q (rope'd, prescaled, PERMUTED cols)
__device__ __half g_kh[(size_t)NTOK * DM];                // k (rope'd, PERMUTED cols)
__device__ __half g_vh[(size_t)NTOK * DM];                // v (natural cols)

// ---------------------------------------------------------------------------
// helpers
// ---------------------------------------------------------------------------
__device__ __forceinline__ uint32_t smem_u32(const void* p) {
    uint32_t a;
    asm("{ .reg .u64 t; cvta.to.shared.u64 t, %1; cvt.u32.u64 %0, t; }" : "=r"(a) : "l"(p));
    return a;
}
__device__ __forceinline__ void ldsm4(uint32_t* r, uint32_t addr) {
    asm volatile("ldmatrix.sync.aligned.m8n8.x4.shared.b16 {%0,%1,%2,%3}, [%4];"
                 : "=r"(r[0]), "=r"(r[1]), "=r"(r[2]), "=r"(r[3]) : "r"(addr));
}
__device__ __forceinline__ void ldsm4t(uint32_t* r, uint32_t addr) {
    asm volatile("ldmatrix.sync.aligned.m8n8.x4.trans.shared.b16 {%0,%1,%2,%3}, [%4];"
                 : "=r"(r[0]), "=r"(r[1]), "=r"(r[2]), "=r"(r[3]) : "r"(addr));
}
// fp16 mma
__device__ __forceinline__ void mma16816h(float* d, const uint32_t* a, uint32_t b0, uint32_t b1) {
    asm volatile("mma.sync.aligned.m16n8k16.row.col.f32.f16.f16.f32 "
                 "{%0,%1,%2,%3}, {%4,%5,%6,%7}, {%8,%9}, {%0,%1,%2,%3};"
                 : "+f"(d[0]), "+f"(d[1]), "+f"(d[2]), "+f"(d[3])
                 : "r"(a[0]), "r"(a[1]), "r"(a[2]), "r"(a[3]), "r"(b0), "r"(b1));
}
__device__ __forceinline__ uint32_t pack_h2(__half lo, __half hi) {
    __half2 v = {lo, hi};
    return *(uint32_t*)&v;
}
__device__ __forceinline__ void cpa16(uint32_t dst, const void* src) {
    asm volatile("cp.async.cg.shared.global [%0], [%1], 16;" :: "r"(dst), "l"(src));
}
#define CP_COMMIT() asm volatile("cp.async.commit_group;")
#define CP_WAIT0()  asm volatile("cp.async.wait_group 0;")
#define CP_WAIT1()  asm volatile("cp.async.wait_group 1;")
// FMA-pipe exp2 for t <= 0 (clamped), ~3e-6 rel error
__device__ __forceinline__ float exp2p(float t) {
    t = fmaxf(t, -126.f);
    const float z = t + 12582912.f;
    const int n = __float_as_int(z) - 0x4B400000;
    const float f = t - (z - 12582912.f);
    float r = 1.3333558146e-3f;
    r = fmaf(r, f, 9.6181291076e-3f);
    r = fmaf(r, f, 5.5504108664e-2f);
    r = fmaf(r, f, 2.4022650695e-1f);
    r = fmaf(r, f, 6.9314718055e-1f);
    r = fmaf(r, f, 1.0f);
    return __int_as_float(__float_as_int(r) + (n << 23));
}

// ---------------------------------------------------------------------------
// convert fp32 -> fp16, vectorized by 4
// ---------------------------------------------------------------------------
__global__ __launch_bounds__(256) void cvt_h_kernel(
    const float* __restrict__ in, __half* __restrict__ hi, int n4)
{
    const int i = blockIdx.x * blockDim.x + threadIdx.x;
    if (i >= n4) return;
    const float4 v = ((const float4*)in)[i];
    __half2 hp0 = {__float2half_rn(v.x), __float2half_rn(v.y)};
    __half2 hp1 = {__float2half_rn(v.z), __float2half_rn(v.w)};
    ((__half2*)hi)[i * 2 + 0] = hp0;
    ((__half2*)hi)[i * 2 + 1] = hp1;
}

// ---------------------------------------------------------------------------
// transpose: W[K][N] row-major -> WT [N][K] fp16.
// If permute!=0 (qkv weights): q/k output rows (orig < 2560) are remapped so
// RoPE pair (j, j+40) lands at adjacent permuted rows (2j, 2j+1) per head.
// ---------------------------------------------------------------------------
__global__ void transpose_h_kernel(
    const float* __restrict__ W, __half* __restrict__ bh, int Krows, int Ncols,
    int permute)
{
    __shared__ float t[32][33];
    const int bx = blockIdx.x * 32;
    const int by = blockIdx.y * 32;
    const int x = threadIdx.x, y = threadIdx.y;
#pragma unroll
    for (int i = 0; i < 32; i += 8)
        t[y + i][x] = W[(size_t)(by + y + i) * Ncols + bx + x];
    __syncthreads();
#pragma unroll
    for (int i = 0; i < 32; i += 8) {
        int r = bx + y + i;   // original output-feature index
        if (permute && r < 2 * DM) {
            const int head = r / HK;
            const int jp = r % HK;
            const int p = (jp < 40) ? (2 * jp) : (2 * (jp - 40) + 1);
            r = head * HK + p;
        }
        bh[(size_t)r * Krows + by + x] = __float2half_rn(t[x][y + i]);
    }
}

// ---------------------------------------------------------------------------
// GEMM mainloop (shared): fp16 1-term C = Ah @ Bh^T, 2-stage cp.async.
// Two kernels differ only in epilogue.
// ---------------------------------------------------------------------------
#define GP 40
#define BUFE (128 * GP)
#define GSMEM (4 * BUFE * 2)

#define GEMM_MAINLOOP(ACC)                                                       \
    const int tid = threadIdx.x;                                                 \
    const int lane = tid & 31;                                                   \
    const int warp = tid >> 5;                                                   \
    const int wm = warp >> 1;                                                    \
    const int wn = warp & 1;                                                     \
    const int m0 = blockIdx.y * 128;                                             \
    const int n0 = blockIdx.x * 128;                                             \
    const int r0 = tid >> 2;                                                     \
    const int sg = (tid & 3) * 8;                                                \
    const __half* pAh = Ah + (size_t)(m0 + r0) * Kd + sg;                        \
    const __half* pBh = Bh + (size_t)(n0 + r0) * Kd + sg;                        \
    const size_t rstep = (size_t)64 * Kd;                                        \
    const uint32_t uAsh = smem_u32(Ash);                                         \
    const uint32_t uBsh = smem_u32(Bsh);                                         \
    auto issue = [&](int k0, int stg) {                                          \
        const uint32_t o0 = (uint32_t)(stg * BUFE + r0 * GP + sg) * 2;           \
        const uint32_t o1 = (uint32_t)(stg * BUFE + (r0 + 64) * GP + sg) * 2;    \
        cpa16(uAsh + o0, pAh + k0);  cpa16(uAsh + o1, pAh + k0 + rstep);         \
        cpa16(uBsh + o0, pBh + k0);  cpa16(uBsh + o1, pBh + k0 + rstep);         \
        CP_COMMIT();                                                             \
    };                                                                           \
    const uint32_t aoff = (uint32_t)((wm * 32 + (lane & 15)) * GP + ((lane >> 4) << 3)) * 2; \
    const uint32_t boff = (uint32_t)((wn * 64 + (lane & 15)) * GP + ((lane >> 4) << 3)) * 2; \
    const int NT = Kd >> 5;                                                      \
    issue(0, 0);                                                                 \
    for (int t = 0; t < NT; ++t) {                                               \
        if (t + 1 < NT) { issue((t + 1) << 5, (t + 1) & 1); CP_WAIT1(); }        \
        else            { CP_WAIT0(); }                                          \
        __syncthreads();                                                         \
        const uint32_t bb = (uint32_t)((t & 1) * BUFE * 2);                      \
        _Pragma("unroll")                                                        \
        for (int ks = 0; ks < 2; ++ks) {                                         \
            const uint32_t kso = (uint32_t)(ks * 16 * 2);                        \
            uint32_t ahf[2][4];                                                  \
            _Pragma("unroll")                                                    \
            for (int t2 = 0; t2 < 2; ++t2)                                       \
                ldsm4(ahf[t2], uAsh + bb + aoff + kso + (uint32_t)(t2 * 16 * GP * 2)); \
            uint32_t bh4[4][4];                                                  \
            _Pragma("unroll")                                                    \
            for (int g = 0; g < 4; ++g)                                          \
                ldsm4(bh4[g], uBsh + bb + boff + kso + (uint32_t)(g * 16 * GP * 2)); \
            _Pragma("unroll")                                                    \
            for (int t2 = 0; t2 < 2; ++t2)                                       \
                _Pragma("unroll")                                                \
                for (int g = 0; g < 4; ++g)                                      \
                    _Pragma("unroll")                                            \
                    for (int h = 0; h < 2; ++h)                                  \
                        mma16816h(ACC[t2][g * 2 + h], ahf[t2], bh4[g][h], bh4[g][h + 2]); \
        }                                                                        \
        __syncthreads();                                                         \
    }

// GEMM2: fp32 out + bias
__global__ __launch_bounds__(256, 2) void gemm_mma(
    const __half* __restrict__ Ah, const __half* __restrict__ Bh,
    const float* __restrict__ bias, float* __restrict__ C, int N, int Kd)
{
    extern __shared__ __half smb[];
    __half* Ash = smb;
    __half* Bsh = Ash + 2 * BUFE;

    float acc[2][8][4];
#pragma unroll
    for (int a = 0; a < 2; a++)
#pragma unroll
        for (int b = 0; b < 8; b++)
#pragma unroll
            for (int c = 0; c < 4; c++) acc[a][b][c] = 0.f;

    GEMM_MAINLOOP(acc)

#pragma unroll
    for (int t2 = 0; t2 < 2; ++t2) {
        const int row = m0 + wm * 32 + t2 * 16 + (lane >> 2);
#pragma unroll
        for (int n8 = 0; n8 < 8; ++n8) {
            const int col = n0 + wn * 64 + n8 * 8 + (lane & 3) * 2;
            const float b0 = __ldg(bias + col);
            const float b1 = __ldg(bias + col + 1);
            float2 v0 = {acc[t2][n8][0] + b0, acc[t2][n8][1] + b1};
            float2 v1 = {acc[t2][n8][2] + b0, acc[t2][n8][3] + b1};
            *(float2*)(C + (size_t)row * N + col) = v0;
            *(float2*)(C + (size_t)(row + 8) * N + col) = v1;
        }
    }
}

// GEMM1: fused bias + RoPE + fp16 store to q (prescaled, permuted) / k / v.
// Weight columns for q/k are pre-permuted so each even/odd column pair is a
// RoPE rotation pair sharing one (cos, sin). N fixed = 3840.
__global__ __launch_bounds__(256, 2) void gemm_qkv(
    const __half* __restrict__ Ah, const __half* __restrict__ Bh,
    const float* __restrict__ bias,
    const float* __restrict__ cosNK, const float* __restrict__ sinNK,
    __half* __restrict__ qh, __half* __restrict__ kh, __half* __restrict__ vh,
    int Kd)
{
    extern __shared__ __half smb[];
    __half* Ash = smb;
    __half* Bsh = Ash + 2 * BUFE;

    float acc[2][8][4];
#pragma unroll
    for (int a = 0; a < 2; a++)
#pragma unroll
        for (int b = 0; b < 8; b++)
#pragma unroll
            for (int c = 0; c < 4; c++) acc[a][b][c] = 0.f;

    GEMM_MAINLOOP(acc)

    const float qs = 0.1118033988749895f * 1.4426950408889634f;  // scale*log2e
    const int region = n0 / DM;   // uniform per CTA (DM multiple of 128)

#pragma unroll
    for (int t2 = 0; t2 < 2; ++t2) {
        const int rowa = m0 + wm * 32 + t2 * 16 + (lane >> 2);
        const int rowb = rowa + 8;
#pragma unroll
        for (int n8 = 0; n8 < 8; ++n8) {
            const int c0 = n0 + wn * 64 + n8 * 8 + (lane & 3) * 2;
            const int pc = c0 - region * DM;      // col within region (even)
            if (region == 2) {
                // V: natural order, just bias + fp16
                const float b0 = __ldg(bias + c0);
                const float b1 = __ldg(bias + c0 + 1);
                __half2 va = {__float2half_rn(acc[t2][n8][0] + b0),
                              __float2half_rn(acc[t2][n8][1] + b1)};
                __half2 vb = {__float2half_rn(acc[t2][n8][2] + b0),
                              __float2half_rn(acc[t2][n8][3] + b1)};
                *(__half2*)(vh + (size_t)rowa * DM + pc) = va;
                *(__half2*)(vh + (size_t)rowb * DM + pc) = vb;
            } else {
                // Q or K: pair (pc, pc+1) = original (j, j+40); cos[j]==cos[j+40]
                const int head = pc / HK;
                const int j = (pc % HK) >> 1;
                const int orig0 = region * DM + head * HK + j;
                const float b0 = __ldg(bias + orig0);
                const float b1 = __ldg(bias + orig0 + 40);
                const float ca = __ldg(cosNK + rowa * HK + j);
                const float sa = __ldg(sinNK + rowa * HK + j);
                const float cb = __ldg(cosNK + rowb * HK + j);
                const float sb = __ldg(sinNK + rowb * HK + j);
                float x0 = acc[t2][n8][0] + b0, x1 = acc[t2][n8][1] + b1;
                float y0 = acc[t2][n8][2] + b0, y1 = acc[t2][n8][3] + b1;
                float o0a = x0 * ca - x1 * sa, o1a = x1 * ca + x0 * sa;
                float o0b = y0 * cb - y1 * sb, o1b = y1 * cb + y0 * sb;
                __half* dst = (region == 0) ? qh : kh;
                if (region == 0) { o0a *= qs; o1a *= qs; o0b *= qs; o1b *= qs; }
                __half2 va = {__float2half_rn(o0a), __float2half_rn(o1a)};
                __half2 vb = {__float2half_rn(o0b), __float2half_rn(o1b)};
                *(__half2*)(dst + (size_t)rowa * DM + pc) = va;
                *(__half2*)(dst + (size_t)rowb * DM + pc) = vb;
            }
        }
    }
}

// ---------------------------------------------------------------------------
// Tensor-core flash attention, fp16 1-term:
//   S = q @ k^T ;  O = p @ v   (all fp16 operands, fp32 accum)
// 128-query tile, 8 warps, cp.async double-buffered K/V.
// Epilogue writes fp16 (GEMM2 A operand).
// ---------------------------------------------------------------------------
#define AP 88
#define KVB (64 * AP)
#define QTB (128 * AP)
#define ATT_SMEM ((QTB + 4 * KVB) * 2)

__global__ __launch_bounds__(256) void attn_mma(
    const __half* __restrict__ qh, const __half* __restrict__ kh,
    const __half* __restrict__ vh, __half* __restrict__ oh)
{
    extern __shared__ __half smb2[];
    __half* Qh = smb2;            // [128][AP]
    __half* KV = Qh + QTB;        // [2 buf][2 arr][64][AP]  arr: K, V

    const int tid = threadIdx.x;
    const int lane = tid & 31;
    const int warp = tid >> 5;
    const int qt = blockIdx.x, head = blockIdx.y, seg = blockIdx.z;
    const int n0 = seg * SEGL + qt * 128;

    const uint32_t uKV = smem_u32(KV);

    auto issueKV = [&](int kb, int buf) {
        const int nk = seg * SEGL + kb * 64;
        const uint32_t bofs = (uint32_t)(buf * 2 * KVB) * 2;
#pragma unroll
        for (int i = 0; i < 3; ++i) {
            const int idx = tid + i * 256;
            if (idx < 640) {
                const int r = idx / 10, c = idx % 10;
                const uint32_t d = bofs + (uint32_t)(r * AP + c * 8) * 2 + uKV;
                const size_t g = (size_t)(nk + r) * DM + head * HK + c * 8;
                cpa16(d + 0 * KVB * 2, kh + g);
                cpa16(d + 1 * KVB * 2, vh + g);
            }
        }
        CP_COMMIT();
    };

    issueKV(0, 0);

    // load Q tile (pre-scaled fp16): 128 rows x 10 16B-groups
#pragma unroll
    for (int i = 0; i < 5; ++i) {
        const int idx = tid + i * 256;
        const int r = idx / 10, c = idx % 10;
        const size_t g = (size_t)(n0 + r) * DM + head * HK + c * 8;
        *(uint4*)(Qh + r * AP + c * 8) = *(const uint4*)(qh + g);
    }
    __syncthreads();

    uint32_t qf[5][4];
    {
        const uint32_t uQh = smem_u32(Qh);
        const uint32_t qoff = (uint32_t)((warp * 16 + (lane & 15)) * AP + ((lane >> 4) << 3)) * 2;
#pragma unroll
        for (int ks = 0; ks < 5; ++ks)
            ldsm4(qf[ks], uQh + qoff + (uint32_t)(ks * 16 * 2));
    }

    const uint32_t koff = (uint32_t)((lane & 15) * AP + ((lane >> 4) << 3)) * 2;
    const uint32_t voff = (uint32_t)((((lane & 7) + (((lane >> 3) & 1) << 3)) * AP) + ((lane >> 4) << 3)) * 2;

    float of[10][4];
#pragma unroll
    for (int t = 0; t < 10; t++)
#pragma unroll
        for (int j = 0; j < 4; j++) of[t][j] = 0.f;
    float m_a = -1e30f, m_b = -1e30f, l_a = 0.f, l_b = 0.f;

    for (int kb = 0; kb < SEGL / 64; ++kb) {
        CP_WAIT0();
        __syncthreads();
        if (kb + 1 < SEGL / 64) issueKV(kb + 1, (kb + 1) & 1);

        const uint32_t bb = (uint32_t)((kb & 1) * 2 * KVB) * 2;
        const uint32_t uKh = uKV + bb;
        const uint32_t uVh = uKh + KVB * 2;

        // ---- S = Q @ K^T (1-term fp16) ----
        float s[8][4];
#pragma unroll
        for (int t = 0; t < 8; t++)
#pragma unroll
            for (int j = 0; j < 4; j++) s[t][j] = 0.f;

#pragma unroll
        for (int ks = 0; ks < 5; ++ks) {
#pragma unroll
            for (int g = 0; g < 4; ++g) {
                uint32_t kf[4];
                const uint32_t ka = koff + (uint32_t)((g * 16 * AP + ks * 16) * 2);
                ldsm4(kf, uKh + ka);
#pragma unroll
                for (int h = 0; h < 2; ++h)
                    mma16816h(s[2 * g + h], qf[ks], kf[h], kf[h + 2]);
            }
        }

        // ---- online softmax (exp2 domain) ----
        float rma = NEG_INF, rmb = NEG_INF;
#pragma unroll
        for (int t = 0; t < 8; t++) {
            rma = fmaxf(rma, fmaxf(s[t][0], s[t][1]));
            rmb = fmaxf(rmb, fmaxf(s[t][2], s[t][3]));
        }
        rma = fmaxf(rma, __shfl_xor_sync(0xffffffffu, rma, 1));
        rma = fmaxf(rma, __shfl_xor_sync(0xffffffffu, rma, 2));
        rmb = fmaxf(rmb, __shfl_xor_sync(0xffffffffu, rmb, 1));
        rmb = fmaxf(rmb, __shfl_xor_sync(0xffffffffu, rmb, 2));
        const float mna = fmaxf(m_a, rma), mnb = fmaxf(m_b, rmb);
        const float corra = exp2p(m_a - mna), corrb = exp2p(m_b - mnb);
        m_a = mna; m_b = mnb;

        float suma = 0.f, sumb = 0.f;
        uint32_t pha[8], phb[8];
#pragma unroll
        for (int t = 0; t < 8; t++) {
            const float p0 = exp2p(s[t][0] - m_a);
            const float p1 = exp2p(s[t][1] - m_a);
            const float p2 = exp2p(s[t][2] - m_b);
            const float p3 = exp2p(s[t][3] - m_b);
            suma += p0 + p1;
            sumb += p2 + p3;
            pha[t] = pack_h2(__float2half_rn(p0), __float2half_rn(p1));
            phb[t] = pack_h2(__float2half_rn(p2), __float2half_rn(p3));
        }
        suma += __shfl_xor_sync(0xffffffffu, suma, 1);
        suma += __shfl_xor_sync(0xffffffffu, suma, 2);
        sumb += __shfl_xor_sync(0xffffffffu, sumb, 1);
        sumb += __shfl_xor_sync(0xffffffffu, sumb, 2);
        l_a = l_a * corra + suma;
        l_b = l_b * corrb + sumb;
#pragma unroll
        for (int t = 0; t < 10; t++) {
            of[t][0] *= corra;
            of[t][1] *= corra;
            of[t][2] *= corrb;
            of[t][3] *= corrb;
        }

        // ---- O += P @ V (1-term fp16) ----
#pragma unroll
        for (int ks = 0; ks < 4; ++ks) {
            const uint32_t ah2[4] = {pha[2 * ks], phb[2 * ks], pha[2 * ks + 1], phb[2 * ks + 1]};
#pragma unroll
            for (int g = 0; g < 5; ++g) {
                uint32_t vf[4];
                const uint32_t va = voff + (uint32_t)((ks * 16 * AP + g * 16) * 2);
                ldsm4t(vf, uVh + va);
#pragma unroll
                for (int h = 0; h < 2; ++h)
                    mma16816h(of[2 * g + h], ah2, vf[2 * h], vf[2 * h + 1]);
            }
        }
    }

    // ---- write normalized output as fp16 (GEMM2 A operand) ----
    const float inva = 1.f / l_a, invb = 1.f / l_b;
    const int rowa = n0 + warp * 16 + (lane >> 2);
    const int rowb = rowa + 8;
#pragma unroll
    for (int t = 0; t < 10; t++) {
        const int col = head * HK + t * 8 + 2 * (lane & 3);
        __half2 vha = {__float2half_rn(of[t][0] * inva), __float2half_rn(of[t][1] * inva)};
        __half2 vhb = {__float2half_rn(of[t][2] * invb), __float2half_rn(of[t][3] * invb)};
        *(__half2*)(oh + (size_t)rowa * DM + col) = vha;
        *(__half2*)(oh + (size_t)rowb * DM + col) = vhb;
    }
}

// ---------------------------------------------------------------------------
// Launch
// ---------------------------------------------------------------------------
extern "C" void kernel_launch(void* const* d_in, const int* in_sizes, int n_in,
                              void* d_out, int out_size)
{
    const float* hidden = (const float*)d_in[0];
    const float* cosNK  = (const float*)d_in[1];
    const float* sinNK  = (const float*)d_in[2];
    const float* qkv_w  = (const float*)d_in[3];
    const float* qkv_b  = (const float*)d_in[4];
    const float* proj_w = (const float*)d_in[5];
    const float* proj_b = (const float*)d_in[6];
    float* out = (float*)d_out;

    __half *ah, *bh, *qh, *kh, *vh;
    cudaGetSymbolAddress((void**)&ah,  g_ah);
    cudaGetSymbolAddress((void**)&bh,  g_bh);
    cudaGetSymbolAddress((void**)&qh,  g_qh);
    cudaGetSymbolAddress((void**)&kh,  g_kh);
    cudaGetSymbolAddress((void**)&vh,  g_vh);

    cudaFuncSetAttribute(gemm_mma, cudaFuncAttributeMaxDynamicSharedMemorySize, GSMEM);
    cudaFuncSetAttribute(gemm_qkv, cudaFuncAttributeMaxDynamicSharedMemorySize, GSMEM);
    cudaFuncSetAttribute(attn_mma, cudaFuncAttributeMaxDynamicSharedMemorySize, ATT_SMEM);

    const int n4 = NTOK * DM / 4;

    // 1) prep GEMM1: convert hidden (fp16), transpose+permute qkv_w (fp16)
    cvt_h_kernel<<<(n4 + 255) / 256, 256>>>(hidden, ah, n4);
    transpose_h_kernel<<<dim3(3 * DM / 32, DM / 32), dim3(32, 8)>>>(qkv_w, bh, DM, 3 * DM, 1);

    // 2) fused GEMM1 + bias + RoPE -> q (prescaled, permuted), k (permuted), v
    gemm_qkv<<<dim3(3 * DM / 128, NTOK / 128), 256, GSMEM>>>(
        ah, bh, qkv_b, cosNK, sinNK, qh, kh, vh, DM);

    // 3) attention (fp16 1-term); writes GEMM2's A (fp16)
    attn_mma<<<dim3(SEGL / 128, NH, NSEGS), 256, ATT_SMEM>>>(qh, kh, vh, ah);

    // 4) prep GEMM2 weights (fp16, no permute)
    transpose_h_kernel<<<dim3(DM / 32, DM / 32), dim3(32, 8)>>>(proj_w, bh, DM, DM, 0);

    // 5) out = attn_out @ proj_w + proj_b  (fp16 1-term)
    gemm_mma<<<dim3(DM / 128, NTOK / 128), 256, GSMEM>>>(
        ah, bh, proj_b, out, DM, DM);
}

// round 15
// speedup vs baseline: 2.5799x; 1.0849x over previous
#include <cuda_runtime.h>
#include <cuda_fp16.h>
#include <cstdint>

// Problem constants (fixed by reference setup_inputs)
#define NTOK 16384
#define DM   1280
#define NH   16
#define HK   80
#define NSEGS 8
#define SEGL 2048

#define NEG_INF (__int_as_float(0xff800000))

// Scratch (allocation-free rule: __device__ globals)
__device__ __half g_ah[(size_t)NTOK * DM];                // GEMM A fp16 (hidden, then attn-out)
__device__ __half g_bh[(size_t)3 * DM * DM];              // W^T fp16 [N][K]
__device__ __half g_qh[(size_t)NTOK * DM];                // q (rope'd, prescaled, PERMUTED cols)
__device__ __half g_kh[(size_t)NTOK * DM];                // k (rope'd, PERMUTED cols)
__device__ __half g_vh[(size_t)NTOK * DM];                // v (natural cols)

// ---------------------------------------------------------------------------
// helpers
// ---------------------------------------------------------------------------
__device__ __forceinline__ uint32_t smem_u32(const void* p) {
    uint32_t a;
    asm("{ .reg .u64 t; cvta.to.shared.u64 t, %1; cvt.u32.u64 %0, t; }" : "=r"(a) : "l"(p));
    return a;
}
__device__ __forceinline__ void ldsm4(uint32_t* r, uint32_t addr) {
    asm volatile("ldmatrix.sync.aligned.m8n8.x4.shared.b16 {%0,%1,%2,%3}, [%4];"
                 : "=r"(r[0]), "=r"(r[1]), "=r"(r[2]), "=r"(r[3]) : "r"(addr));
}
__device__ __forceinline__ void ldsm4t(uint32_t* r, uint32_t addr) {
    asm volatile("ldmatrix.sync.aligned.m8n8.x4.trans.shared.b16 {%0,%1,%2,%3}, [%4];"
                 : "=r"(r[0]), "=r"(r[1]), "=r"(r[2]), "=r"(r[3]) : "r"(addr));
}
// fp16 mma
__device__ __forceinline__ void mma16816h(float* d, const uint32_t* a, uint32_t b0, uint32_t b1) {
    asm volatile("mma.sync.aligned.m16n8k16.row.col.f32.f16.f16.f32 "
                 "{%0,%1,%2,%3}, {%4,%5,%6,%7}, {%8,%9}, {%0,%1,%2,%3};"
                 : "+f"(d[0]), "+f"(d[1]), "+f"(d[2]), "+f"(d[3])
                 : "r"(a[0]), "r"(a[1]), "r"(a[2]), "r"(a[3]), "r"(b0), "r"(b1));
}
__device__ __forceinline__ uint32_t pack_h2(__half lo, __half hi) {
    __half2 v = {lo, hi};
    return *(uint32_t*)&v;
}
__device__ __forceinline__ void cpa16(uint32_t dst, const void* src) {
    asm volatile("cp.async.cg.shared.global [%0], [%1], 16;" :: "r"(dst), "l"(src));
}
#define CP_COMMIT() asm volatile("cp.async.commit_group;")
#define CP_WAIT0()  asm volatile("cp.async.wait_group 0;")
#define CP_WAIT1()  asm volatile("cp.async.wait_group 1;")
// FMA-pipe exp2 for t <= 0 (clamped), ~3e-6 rel error
__device__ __forceinline__ float exp2p(float t) {
    t = fmaxf(t, -126.f);
    const float z = t + 12582912.f;
    const int n = __float_as_int(z) - 0x4B400000;
    const float f = t - (z - 12582912.f);
    float r = 1.3333558146e-3f;
    r = fmaf(r, f, 9.6181291076e-3f);
    r = fmaf(r, f, 5.5504108664e-2f);
    r = fmaf(r, f, 2.4022650695e-1f);
    r = fmaf(r, f, 6.9314718055e-1f);
    r = fmaf(r, f, 1.0f);
    return __int_as_float(__float_as_int(r) + (n << 23));
}

// ---------------------------------------------------------------------------
// convert fp32 -> fp16, vectorized by 4
// ---------------------------------------------------------------------------
__global__ __launch_bounds__(256) void cvt_h_kernel(
    const float* __restrict__ in, __half* __restrict__ hi, int n4)
{
    const int i = blockIdx.x * blockDim.x + threadIdx.x;
    if (i >= n4) return;
    const float4 v = ((const float4*)in)[i];
    __half2 hp0 = {__float2half_rn(v.x), __float2half_rn(v.y)};
    __half2 hp1 = {__float2half_rn(v.z), __float2half_rn(v.w)};
    ((__half2*)hi)[i * 2 + 0] = hp0;
    ((__half2*)hi)[i * 2 + 1] = hp1;
}

// ---------------------------------------------------------------------------
// transpose: W[K][N] row-major -> WT [N][K] fp16.
// If permute!=0 (qkv weights): q/k output rows (orig < 2560) are remapped so
// RoPE pair (j, j+40) lands at adjacent permuted rows (2j, 2j+1) per head.
// ---------------------------------------------------------------------------
__global__ void transpose_h_kernel(
    const float* __restrict__ W, __half* __restrict__ bh, int Krows, int Ncols,
    int permute)
{
    __shared__ float t[32][33];
    const int bx = blockIdx.x * 32;
    const int by = blockIdx.y * 32;
    const int x = threadIdx.x, y = threadIdx.y;
#pragma unroll
    for (int i = 0; i < 32; i += 8)
        t[y + i][x] = W[(size_t)(by + y + i) * Ncols + bx + x];
    __syncthreads();
#pragma unroll
    for (int i = 0; i < 32; i += 8) {
        int r = bx + y + i;   // original output-feature index
        if (permute && r < 2 * DM) {
            const int head = r / HK;
            const int jp = r % HK;
            const int p = (jp < 40) ? (2 * jp) : (2 * (jp - 40) + 1);
            r = head * HK + p;
        }
        bh[(size_t)r * Krows + by + x] = __float2half_rn(t[x][y + i]);
    }
}

// ---------------------------------------------------------------------------
// GEMM mainloop (shared): fp16 1-term C = Ah @ Bh^T, 2-stage cp.async.
// ---------------------------------------------------------------------------
#define GP 40
#define BUFE (128 * GP)
#define GSMEM (4 * BUFE * 2)

#define GEMM_MAINLOOP(ACC)                                                       \
    const int tid = threadIdx.x;                                                 \
    const int lane = tid & 31;                                                   \
    const int warp = tid >> 5;                                                   \
    const int wm = warp >> 1;                                                    \
    const int wn = warp & 1;                                                     \
    const int m0 = blockIdx.y * 128;                                             \
    const int n0 = blockIdx.x * 128;                                             \
    const int r0 = tid >> 2;                                                     \
    const int sg = (tid & 3) * 8;                                                \
    const __half* pAh = Ah + (size_t)(m0 + r0) * Kd + sg;                        \
    const __half* pBh = Bh + (size_t)(n0 + r0) * Kd + sg;                        \
    const size_t rstep = (size_t)64 * Kd;                                        \
    const uint32_t uAsh = smem_u32(Ash);                                         \
    const uint32_t uBsh = smem_u32(Bsh);                                         \
    auto issue = [&](int k0, int stg) {                                          \
        const uint32_t o0 = (uint32_t)(stg * BUFE + r0 * GP + sg) * 2;           \
        const uint32_t o1 = (uint32_t)(stg * BUFE + (r0 + 64) * GP + sg) * 2;    \
        cpa16(uAsh + o0, pAh + k0);  cpa16(uAsh + o1, pAh + k0 + rstep);         \
        cpa16(uBsh + o0, pBh + k0);  cpa16(uBsh + o1, pBh + k0 + rstep);         \
        CP_COMMIT();                                                             \
    };                                                                           \
    const uint32_t aoff = (uint32_t)((wm * 32 + (lane & 15)) * GP + ((lane >> 4) << 3)) * 2; \
    const uint32_t boff = (uint32_t)((wn * 64 + (lane & 15)) * GP + ((lane >> 4) << 3)) * 2; \
    const int NT = Kd >> 5;                                                      \
    issue(0, 0);                                                                 \
    for (int t = 0; t < NT; ++t) {                                               \
        if (t + 1 < NT) { issue((t + 1) << 5, (t + 1) & 1); CP_WAIT1(); }        \
        else            { CP_WAIT0(); }                                          \
        __syncthreads();                                                         \
        const uint32_t bb = (uint32_t)((t & 1) * BUFE * 2);                      \
        _Pragma("unroll")                                                        \
        for (int ks = 0; ks < 2; ++ks) {                                         \
            const uint32_t kso = (uint32_t)(ks * 16 * 2);                        \
            uint32_t ahf[2][4];                                                  \
            _Pragma("unroll")                                                    \
            for (int t2 = 0; t2 < 2; ++t2)                                       \
                ldsm4(ahf[t2], uAsh + bb + aoff + kso + (uint32_t)(t2 * 16 * GP * 2)); \
            uint32_t bh4[4][4];                                                  \
            _Pragma("unroll")                                                    \
            for (int g = 0; g < 4; ++g)                                          \
                ldsm4(bh4[g], uBsh + bb + boff + kso + (uint32_t)(g * 16 * GP * 2)); \
            _Pragma("unroll")                                                    \
            for (int t2 = 0; t2 < 2; ++t2)                                       \
                _Pragma("unroll")                                                \
                for (int g = 0; g < 4; ++g)                                      \
                    _Pragma("unroll")                                            \
                    for (int h = 0; h < 2; ++h)                                  \
                        mma16816h(ACC[t2][g * 2 + h], ahf[t2], bh4[g][h], bh4[g][h + 2]); \
        }                                                                        \
        __syncthreads();                                                         \
    }

// GEMM2: fp32 out + bias
__global__ __launch_bounds__(256, 2) void gemm_mma(
    const __half* __restrict__ Ah, const __half* __restrict__ Bh,
    const float* __restrict__ bias, float* __restrict__ C, int N, int Kd)
{
    extern __shared__ __half smb[];
    __half* Ash = smb;
    __half* Bsh = Ash + 2 * BUFE;

    float acc[2][8][4];
#pragma unroll
    for (int a = 0; a < 2; a++)
#pragma unroll
        for (int b = 0; b < 8; b++)
#pragma unroll
            for (int c = 0; c < 4; c++) acc[a][b][c] = 0.f;

    GEMM_MAINLOOP(acc)

#pragma unroll
    for (int t2 = 0; t2 < 2; ++t2) {
        const int row = m0 + wm * 32 + t2 * 16 + (lane >> 2);
#pragma unroll
        for (int n8 = 0; n8 < 8; ++n8) {
            const int col = n0 + wn * 64 + n8 * 8 + (lane & 3) * 2;
            const float b0 = __ldg(bias + col);
            const float b1 = __ldg(bias + col + 1);
            float2 v0 = {acc[t2][n8][0] + b0, acc[t2][n8][1] + b1};
            float2 v1 = {acc[t2][n8][2] + b0, acc[t2][n8][3] + b1};
            *(float2*)(C + (size_t)row * N + col) = v0;
            *(float2*)(C + (size_t)(row + 8) * N + col) = v1;
        }
    }
}

// GEMM1: fused bias + RoPE + fp16 store to q (prescaled, permuted) / k / v.
__global__ __launch_bounds__(256, 2) void gemm_qkv(
    const __half* __restrict__ Ah, const __half* __restrict__ Bh,
    const float* __restrict__ bias,
    const float* __restrict__ cosNK, const float* __restrict__ sinNK,
    __half* __restrict__ qh, __half* __restrict__ kh, __half* __restrict__ vh,
    int Kd)
{
    extern __shared__ __half smb[];
    __half* Ash = smb;
    __half* Bsh = Ash + 2 * BUFE;

    float acc[2][8][4];
#pragma unroll
    for (int a = 0; a < 2; a++)
#pragma unroll
        for (int b = 0; b < 8; b++)
#pragma unroll
            for (int c = 0; c < 4; c++) acc[a][b][c] = 0.f;

    GEMM_MAINLOOP(acc)

    const float qs = 0.1118033988749895f * 1.4426950408889634f;  // scale*log2e
    const int region = n0 / DM;   // uniform per CTA (DM multiple of 128)

#pragma unroll
    for (int t2 = 0; t2 < 2; ++t2) {
        const int rowa = m0 + wm * 32 + t2 * 16 + (lane >> 2);
        const int rowb = rowa + 8;
#pragma unroll
        for (int n8 = 0; n8 < 8; ++n8) {
            const int c0 = n0 + wn * 64 + n8 * 8 + (lane & 3) * 2;
            const int pc = c0 - region * DM;      // col within region (even)
            if (region == 2) {
                const float b0 = __ldg(bias + c0);
                const float b1 = __ldg(bias + c0 + 1);
                __half2 va = {__float2half_rn(acc[t2][n8][0] + b0),
                              __float2half_rn(acc[t2][n8][1] + b1)};
                __half2 vb = {__float2half_rn(acc[t2][n8][2] + b0),
                              __float2half_rn(acc[t2][n8][3] + b1)};
                *(__half2*)(vh + (size_t)rowa * DM + pc) = va;
                *(__half2*)(vh + (size_t)rowb * DM + pc) = vb;
            } else {
                const int head = pc / HK;
                const int j = (pc % HK) >> 1;
                const int orig0 = region * DM + head * HK + j;
                const float b0 = __ldg(bias + orig0);
                const float b1 = __ldg(bias + orig0 + 40);
                const float ca = __ldg(cosNK + rowa * HK + j);
                const float sa = __ldg(sinNK + rowa * HK + j);
                const float cb = __ldg(cosNK + rowb * HK + j);
                const float sb = __ldg(sinNK + rowb * HK + j);
                float x0 = acc[t2][n8][0] + b0, x1 = acc[t2][n8][1] + b1;
                float y0 = acc[t2][n8][2] + b0, y1 = acc[t2][n8][3] + b1;
                float o0a = x0 * ca - x1 * sa, o1a = x1 * ca + x0 * sa;
                float o0b = y0 * cb - y1 * sb, o1b = y1 * cb + y0 * sb;
                __half* dst = (region == 0) ? qh : kh;
                if (region == 0) { o0a *= qs; o1a *= qs; o0b *= qs; o1b *= qs; }
                __half2 va = {__float2half_rn(o0a), __float2half_rn(o1a)};
                __half2 vb = {__float2half_rn(o0b), __float2half_rn(o1b)};
                *(__half2*)(dst + (size_t)rowa * DM + pc) = va;
                *(__half2*)(dst + (size_t)rowb * DM + pc) = vb;
            }
        }
    }
}

// ---------------------------------------------------------------------------
// Tensor-core flash attention, fp16 1-term, 2 CTAs/SM (reg-capped).
// Q fragments reloaded from resident smem each key-block to cut reg pressure.
// ---------------------------------------------------------------------------
#define AP 88
#define KVB (64 * AP)
#define QTB (128 * AP)
#define ATT_SMEM ((QTB + 4 * KVB) * 2)

__global__ __launch_bounds__(256, 2) void attn_mma(
    const __half* __restrict__ qh, const __half* __restrict__ kh,
    const __half* __restrict__ vh, __half* __restrict__ oh)
{
    extern __shared__ __half smb2[];
    __half* Qh = smb2;            // [128][AP]  (resident, never overwritten)
    __half* KV = Qh + QTB;        // [2 buf][2 arr][64][AP]  arr: K, V

    const int tid = threadIdx.x;
    const int lane = tid & 31;
    const int warp = tid >> 5;
    const int qt = blockIdx.x, head = blockIdx.y, seg = blockIdx.z;
    const int n0 = seg * SEGL + qt * 128;

    const uint32_t uKV = smem_u32(KV);

    auto issueKV = [&](int kb, int buf) {
        const int nk = seg * SEGL + kb * 64;
        const uint32_t bofs = (uint32_t)(buf * 2 * KVB) * 2;
#pragma unroll
        for (int i = 0; i < 3; ++i) {
            const int idx = tid + i * 256;
            if (idx < 640) {
                const int r = idx / 10, c = idx % 10;
                const uint32_t d = bofs + (uint32_t)(r * AP + c * 8) * 2 + uKV;
                const size_t g = (size_t)(nk + r) * DM + head * HK + c * 8;
                cpa16(d + 0 * KVB * 2, kh + g);
                cpa16(d + 1 * KVB * 2, vh + g);
            }
        }
        CP_COMMIT();
    };

    issueKV(0, 0);

    // load Q tile (pre-scaled fp16): 128 rows x 10 16B-groups
#pragma unroll
    for (int i = 0; i < 5; ++i) {
        const int idx = tid + i * 256;
        const int r = idx / 10, c = idx % 10;
        const size_t g = (size_t)(n0 + r) * DM + head * HK + c * 8;
        *(uint4*)(Qh + r * AP + c * 8) = *(const uint4*)(qh + g);
    }
    __syncthreads();

    const uint32_t uQh = smem_u32(Qh);
    const uint32_t qoff = (uint32_t)((warp * 16 + (lane & 15)) * AP + ((lane >> 4) << 3)) * 2;
    const uint32_t koff = (uint32_t)((lane & 15) * AP + ((lane >> 4) << 3)) * 2;
    const uint32_t voff = (uint32_t)((((lane & 7) + (((lane >> 3) & 1) << 3)) * AP) + ((lane >> 4) << 3)) * 2;

    float of[10][4];
#pragma unroll
    for (int t = 0; t < 10; t++)
#pragma unroll
        for (int j = 0; j < 4; j++) of[t][j] = 0.f;
    float m_a = -1e30f, m_b = -1e30f, l_a = 0.f, l_b = 0.f;

    for (int kb = 0; kb < SEGL / 64; ++kb) {
        CP_WAIT0();
        __syncthreads();
        if (kb + 1 < SEGL / 64) issueKV(kb + 1, (kb + 1) & 1);

        const uint32_t bb = (uint32_t)((kb & 1) * 2 * KVB) * 2;
        const uint32_t uKh = uKV + bb;
        const uint32_t uVh = uKh + KVB * 2;

        // ---- S = Q @ K^T (1-term fp16); Q frags reloaded per ks ----
        float s[8][4];
#pragma unroll
        for (int t = 0; t < 8; t++)
#pragma unroll
            for (int j = 0; j < 4; j++) s[t][j] = 0.f;

#pragma unroll
        for (int ks = 0; ks < 5; ++ks) {
            uint32_t qf[4];
            ldsm4(qf, uQh + qoff + (uint32_t)(ks * 16 * 2));
#pragma unroll
            for (int g = 0; g < 4; ++g) {
                uint32_t kf[4];
                const uint32_t ka = koff + (uint32_t)((g * 16 * AP + ks * 16) * 2);
                ldsm4(kf, uKh + ka);
#pragma unroll
                for (int h = 0; h < 2; ++h)
                    mma16816h(s[2 * g + h], qf, kf[h], kf[h + 2]);
            }
        }

        // ---- online softmax (exp2 domain) ----
        float rma = NEG_INF, rmb = NEG_INF;
#pragma unroll
        for (int t = 0; t < 8; t++) {
            rma = fmaxf(rma, fmaxf(s[t][0], s[t][1]));
            rmb = fmaxf(rmb, fmaxf(s[t][2], s[t][3]));
        }
        rma = fmaxf(rma, __shfl_xor_sync(0xffffffffu, rma, 1));
        rma = fmaxf(rma, __shfl_xor_sync(0xffffffffu, rma, 2));
        rmb = fmaxf(rmb, __shfl_xor_sync(0xffffffffu, rmb, 1));
        rmb = fmaxf(rmb, __shfl_xor_sync(0xffffffffu, rmb, 2));
        const float mna = fmaxf(m_a, rma), mnb = fmaxf(m_b, rmb);
        const float corra = exp2p(m_a - mna), corrb = exp2p(m_b - mnb);
        m_a = mna; m_b = mnb;

        float suma = 0.f, sumb = 0.f;
        uint32_t pha[8], phb[8];
#pragma unroll
        for (int t = 0; t < 8; t++) {
            const float p0 = exp2p(s[t][0] - m_a);
            const float p1 = exp2p(s[t][1] - m_a);
            const float p2 = exp2p(s[t][2] - m_b);
            const float p3 = exp2p(s[t][3] - m_b);
            suma += p0 + p1;
            sumb += p2 + p3;
            pha[t] = pack_h2(__float2half_rn(p0), __float2half_rn(p1));
            phb[t] = pack_h2(__float2half_rn(p2), __float2half_rn(p3));
        }
        suma += __shfl_xor_sync(0xffffffffu, suma, 1);
        suma += __shfl_xor_sync(0xffffffffu, suma, 2);
        sumb += __shfl_xor_sync(0xffffffffu, sumb, 1);
        sumb += __shfl_xor_sync(0xffffffffu, sumb, 2);
        l_a = l_a * corra + suma;
        l_b = l_b * corrb + sumb;
#pragma unroll
        for (int t = 0; t < 10; t++) {
            of[t][0] *= corra;
            of[t][1] *= corra;
            of[t][2] *= corrb;
            of[t][3] *= corrb;
        }

        // ---- O += P @ V (1-term fp16) ----
#pragma unroll
        for (int ks = 0; ks < 4; ++ks) {
            const uint32_t ah2[4] = {pha[2 * ks], phb[2 * ks], pha[2 * ks + 1], phb[2 * ks + 1]};
#pragma unroll
            for (int g = 0; g < 5; ++g) {
                uint32_t vf[4];
                const uint32_t va = voff + (uint32_t)((ks * 16 * AP + g * 16) * 2);
                ldsm4t(vf, uVh + va);
#pragma unroll
                for (int h = 0; h < 2; ++h)
                    mma16816h(of[2 * g + h], ah2, vf[2 * h], vf[2 * h + 1]);
            }
        }
    }

    // ---- write normalized output as fp16 (GEMM2 A operand) ----
    const float inva = 1.f / l_a, invb = 1.f / l_b;
    const int rowa = n0 + warp * 16 + (lane >> 2);
    const int rowb = rowa + 8;
#pragma unroll
    for (int t = 0; t < 10; t++) {
        const int col = head * HK + t * 8 + 2 * (lane & 3);
        __half2 vha = {__float2half_rn(of[t][0] * inva), __float2half_rn(of[t][1] * inva)};
        __half2 vhb = {__float2half_rn(of[t][2] * invb), __float2half_rn(of[t][3] * invb)};
        *(__half2*)(oh + (size_t)rowa * DM + col) = vha;
        *(__half2*)(oh + (size_t)rowb * DM + col) = vhb;
    }
}

// ---------------------------------------------------------------------------
// Launch
// ---------------------------------------------------------------------------
extern "C" void kernel_launch(void* const* d_in, const int* in_sizes, int n_in,
                              void* d_out, int out_size)
{
    const float* hidden = (const float*)d_in[0];
    const float* cosNK  = (const float*)d_in[1];
    const float* sinNK  = (const float*)d_in[2];
    const float* qkv_w  = (const float*)d_in[3];
    const float* qkv_b  = (const float*)d_in[4];
    const float* proj_w = (const float*)d_in[5];
    const float* proj_b = (const float*)d_in[6];
    float* out = (float*)d_out;

    __half *ah, *bh, *qh, *kh, *vh;
    cudaGetSymbolAddress((void**)&ah,  g_ah);
    cudaGetSymbolAddress((void**)&bh,  g_bh);
    cudaGetSymbolAddress((void**)&qh,  g_qh);
    cudaGetSymbolAddress((void**)&kh,  g_kh);
    cudaGetSymbolAddress((void**)&vh,  g_vh);

    cudaFuncSetAttribute(gemm_mma, cudaFuncAttributeMaxDynamicSharedMemorySize, GSMEM);
    cudaFuncSetAttribute(gemm_qkv, cudaFuncAttributeMaxDynamicSharedMemorySize, GSMEM);
    cudaFuncSetAttribute(attn_mma, cudaFuncAttributeMaxDynamicSharedMemorySize, ATT_SMEM);

    const int n4 = NTOK * DM / 4;

    // 1) prep GEMM1: convert hidden (fp16), transpose+permute qkv_w (fp16)
    cvt_h_kernel<<<(n4 + 255) / 256, 256>>>(hidden, ah, n4);
    transpose_h_kernel<<<dim3(3 * DM / 32, DM / 32), dim3(32, 8)>>>(qkv_w, bh, DM, 3 * DM, 1);

    // 2) fused GEMM1 + bias + RoPE -> q (prescaled, permuted), k (permuted), v
    gemm_qkv<<<dim3(3 * DM / 128, NTOK / 128), 256, GSMEM>>>(
        ah, bh, qkv_b, cosNK, sinNK, qh, kh, vh, DM);

    // 3) attention (fp16 1-term, 2 CTAs/SM); writes GEMM2's A (fp16)
    attn_mma<<<dim3(SEGL / 128, NH, NSEGS), 256, ATT_SMEM>>>(qh, kh, vh, ah);

    // 4) prep GEMM2 weights (fp16, no permute)
    transpose_h_kernel<<<dim3(DM / 32, DM / 32), dim3(32, 8)>>>(proj_w, bh, DM, DM, 0);

    // 5) out = attn_out @ proj_w + proj_b  (fp16 1-term)
    gemm_mma<<<dim3(DM / 128, NTOK / 128), 256, GSMEM>>>(
        ah, bh, proj_b, out, DM, DM);
}

// round 16
// speedup vs baseline: 2.6818x; 1.0395x over previous
#include <cuda_runtime.h>
#include <cuda_fp16.h>
#include <cstdint>

// Problem constants (fixed by reference setup_inputs)
#define NTOK 16384
#define DM   1280
#define NH   16
#define HK   80
#define NSEGS 8
#define SEGL 2048

#define NEG_INF (__int_as_float(0xff800000))

// Scratch (allocation-free rule: __device__ globals)
__device__ __half g_ah[(size_t)NTOK * DM];                // GEMM A fp16 (hidden, then attn-out)
__device__ __half g_bh[(size_t)3 * DM * DM];              // W^T fp16 [N][K]
__device__ __half g_qh[(size_t)NTOK * DM];                // q (rope'd, prescaled, PERMUTED cols)
__device__ __half g_kh[(size_t)NTOK * DM];                // k (rope'd, PERMUTED cols)
__device__ __half g_vh[(size_t)NTOK * DM];                // v (natural cols)

// ---------------------------------------------------------------------------
// helpers
// ---------------------------------------------------------------------------
__device__ __forceinline__ uint32_t smem_u32(const void* p) {
    uint32_t a;
    asm("{ .reg .u64 t; cvta.to.shared.u64 t, %1; cvt.u32.u64 %0, t; }" : "=r"(a) : "l"(p));
    return a;
}
__device__ __forceinline__ void ldsm4(uint32_t* r, uint32_t addr) {
    asm volatile("ldmatrix.sync.aligned.m8n8.x4.shared.b16 {%0,%1,%2,%3}, [%4];"
                 : "=r"(r[0]), "=r"(r[1]), "=r"(r[2]), "=r"(r[3]) : "r"(addr));
}
__device__ __forceinline__ void ldsm4t(uint32_t* r, uint32_t addr) {
    asm volatile("ldmatrix.sync.aligned.m8n8.x4.trans.shared.b16 {%0,%1,%2,%3}, [%4];"
                 : "=r"(r[0]), "=r"(r[1]), "=r"(r[2]), "=r"(r[3]) : "r"(addr));
}
// fp16 mma
__device__ __forceinline__ void mma16816h(float* d, const uint32_t* a, uint32_t b0, uint32_t b1) {
    asm volatile("mma.sync.aligned.m16n8k16.row.col.f32.f16.f16.f32 "
                 "{%0,%1,%2,%3}, {%4,%5,%6,%7}, {%8,%9}, {%0,%1,%2,%3};"
                 : "+f"(d[0]), "+f"(d[1]), "+f"(d[2]), "+f"(d[3])
                 : "r"(a[0]), "r"(a[1]), "r"(a[2]), "r"(a[3]), "r"(b0), "r"(b1));
}
__device__ __forceinline__ uint32_t pack_h2(__half lo, __half hi) {
    __half2 v = {lo, hi};
    return *(uint32_t*)&v;
}
__device__ __forceinline__ void cpa16(uint32_t dst, const void* src) {
    asm volatile("cp.async.cg.shared.global [%0], [%1], 16;" :: "r"(dst), "l"(src));
}
#define CP_COMMIT() asm volatile("cp.async.commit_group;")
#define CP_WAIT0()  asm volatile("cp.async.wait_group 0;")
#define CP_WAIT1()  asm volatile("cp.async.wait_group 1;")

// FMA-pipe exp2 for t <= 0 (clamped), ~3e-6 rel error (scalar; used for corr)
__device__ __forceinline__ float exp2p(float t) {
    t = fmaxf(t, -126.f);
    const float z = t + 12582912.f;
    const int n = __float_as_int(z) - 0x4B400000;
    const float f = t - (z - 12582912.f);
    float r = 1.3333558146e-3f;
    r = fmaf(r, f, 9.6181291076e-3f);
    r = fmaf(r, f, 5.5504108664e-2f);
    r = fmaf(r, f, 2.4022650695e-1f);
    r = fmaf(r, f, 6.9314718055e-1f);
    r = fmaf(r, f, 1.0f);
    return __int_as_float(__float_as_int(r) + (n << 23));
}

// packed f32x2 helpers (halve issue slots on the FMA pipe)
__device__ __forceinline__ uint64_t pack2f(float lo, float hi) {
    uint64_t r;
    asm("mov.b64 %0, {%1, %2};" : "=l"(r) : "f"(lo), "f"(hi));
    return r;
}
__device__ __forceinline__ void unpack2f(uint64_t v, float& lo, float& hi) {
    asm("mov.b64 {%0, %1}, %2;" : "=f"(lo), "=f"(hi) : "l"(v));
}
__device__ __forceinline__ uint64_t add2(uint64_t a, uint64_t b) {
    uint64_t d;
    asm("add.rn.f32x2 %0, %1, %2;" : "=l"(d) : "l"(a), "l"(b));
    return d;
}
__device__ __forceinline__ uint64_t fma2c(uint64_t a, uint64_t b, uint64_t c) {
    uint64_t d;
    asm("fma.rn.f32x2 %0, %1, %2, %3;" : "=l"(d) : "l"(a), "l"(b), "l"(c));
    return d;
}
#define PK2(x) ((((uint64_t)(x)) << 32) | (uint64_t)(x))
// exp2 of a pair, NO clamp (inputs in [-126, 0] guaranteed by softmax)
__device__ __forceinline__ void exp2pair(float t0, float t1, float& o0, float& o1) {
    const uint64_t tt = pack2f(t0, t1);
    const uint64_t zz = add2(tt, PK2(0x4B400000u));            // t + 12582912
    const uint64_t ww = add2(zz, PK2(0xCB400000u));            // z - 12582912
    const uint64_t ff = fma2c(ww, PK2(0xBF800000u), tt);       // f = t - w
    float z0, z1;
    unpack2f(zz, z0, z1);
    const int n0 = __float_as_int(z0) - 0x4B400000;
    const int n1 = __float_as_int(z1) - 0x4B400000;
    uint64_t rr = PK2(0x3AAEBD1Au);                            // 1.3333558e-3
    rr = fma2c(rr, ff, PK2(0x3C1D94FCu));                      // 9.6181291e-3
    rr = fma2c(rr, ff, PK2(0x3D6357CFu));                      // 5.5504109e-2
    rr = fma2c(rr, ff, PK2(0x3E75FDF0u));                      // 2.4022651e-1
    rr = fma2c(rr, ff, PK2(0x3F317218u));                      // 6.9314718e-1
    rr = fma2c(rr, ff, PK2(0x3F800000u));                      // 1.0
    float r0, r1;
    unpack2f(rr, r0, r1);
    o0 = __int_as_float(__float_as_int(r0) + (n0 << 23));
    o1 = __int_as_float(__float_as_int(r1) + (n1 << 23));
}

// ---------------------------------------------------------------------------
// convert fp32 -> fp16, vectorized by 4
// ---------------------------------------------------------------------------
__global__ __launch_bounds__(256) void cvt_h_kernel(
    const float* __restrict__ in, __half* __restrict__ hi, int n4)
{
    const int i = blockIdx.x * blockDim.x + threadIdx.x;
    if (i >= n4) return;
    const float4 v = ((const float4*)in)[i];
    __half2 hp0 = {__float2half_rn(v.x), __float2half_rn(v.y)};
    __half2 hp1 = {__float2half_rn(v.z), __float2half_rn(v.w)};
    ((__half2*)hi)[i * 2 + 0] = hp0;
    ((__half2*)hi)[i * 2 + 1] = hp1;
}

// ---------------------------------------------------------------------------
// transpose: W[K][N] row-major -> WT [N][K] fp16 (optional q/k RoPE permute)
// ---------------------------------------------------------------------------
__global__ void transpose_h_kernel(
    const float* __restrict__ W, __half* __restrict__ bh, int Krows, int Ncols,
    int permute)
{
    __shared__ float t[32][33];
    const int bx = blockIdx.x * 32;
    const int by = blockIdx.y * 32;
    const int x = threadIdx.x, y = threadIdx.y;
#pragma unroll
    for (int i = 0; i < 32; i += 8)
        t[y + i][x] = W[(size_t)(by + y + i) * Ncols + bx + x];
    __syncthreads();
#pragma unroll
    for (int i = 0; i < 32; i += 8) {
        int r = bx + y + i;
        if (permute && r < 2 * DM) {
            const int head = r / HK;
            const int jp = r % HK;
            const int p = (jp < 40) ? (2 * jp) : (2 * (jp - 40) + 1);
            r = head * HK + p;
        }
        bh[(size_t)r * Krows + by + x] = __float2half_rn(t[x][y + i]);
    }
}

// ---------------------------------------------------------------------------
// GEMM mainloop (shared): fp16 1-term C = Ah @ Bh^T, 2-stage cp.async.
// ---------------------------------------------------------------------------
#define GP 40
#define BUFE (128 * GP)
#define GSMEM (4 * BUFE * 2)

#define GEMM_MAINLOOP(ACC)                                                       \
    const int tid = threadIdx.x;                                                 \
    const int lane = tid & 31;                                                   \
    const int warp = tid >> 5;                                                   \
    const int wm = warp >> 1;                                                    \
    const int wn = warp & 1;                                                     \
    const int m0 = blockIdx.y * 128;                                             \
    const int n0 = blockIdx.x * 128;                                             \
    const int r0 = tid >> 2;                                                     \
    const int sg = (tid & 3) * 8;                                                \
    const __half* pAh = Ah + (size_t)(m0 + r0) * Kd + sg;                        \
    const __half* pBh = Bh + (size_t)(n0 + r0) * Kd + sg;                        \
    const size_t rstep = (size_t)64 * Kd;                                        \
    const uint32_t uAsh = smem_u32(Ash);                                         \
    const uint32_t uBsh = smem_u32(Bsh);                                         \
    auto issue = [&](int k0, int stg) {                                          \
        const uint32_t o0 = (uint32_t)(stg * BUFE + r0 * GP + sg) * 2;           \
        const uint32_t o1 = (uint32_t)(stg * BUFE + (r0 + 64) * GP + sg) * 2;    \
        cpa16(uAsh + o0, pAh + k0);  cpa16(uAsh + o1, pAh + k0 + rstep);         \
        cpa16(uBsh + o0, pBh + k0);  cpa16(uBsh + o1, pBh + k0 + rstep);         \
        CP_COMMIT();                                                             \
    };                                                                           \
    const uint32_t aoff = (uint32_t)((wm * 32 + (lane & 15)) * GP + ((lane >> 4) << 3)) * 2; \
    const uint32_t boff = (uint32_t)((wn * 64 + (lane & 15)) * GP + ((lane >> 4) << 3)) * 2; \
    const int NT = Kd >> 5;                                                      \
    issue(0, 0);                                                                 \
    for (int t = 0; t < NT; ++t) {                                               \
        if (t + 1 < NT) { issue((t + 1) << 5, (t + 1) & 1); CP_WAIT1(); }        \
        else            { CP_WAIT0(); }                                          \
        __syncthreads();                                                         \
        const uint32_t bb = (uint32_t)((t & 1) * BUFE * 2);                      \
        _Pragma("unroll")                                                        \
        for (int ks = 0; ks < 2; ++ks) {                                         \
            const uint32_t kso = (uint32_t)(ks * 16 * 2);                        \
            uint32_t ahf[2][4];                                                  \
            _Pragma("unroll")                                                    \
            for (int t2 = 0; t2 < 2; ++t2)                                       \
                ldsm4(ahf[t2], uAsh + bb + aoff + kso + (uint32_t)(t2 * 16 * GP * 2)); \
            uint32_t bh4[4][4];                                                  \
            _Pragma("unroll")                                                    \
            for (int g = 0; g < 4; ++g)                                          \
                ldsm4(bh4[g], uBsh + bb + boff + kso + (uint32_t)(g * 16 * GP * 2)); \
            _Pragma("unroll")                                                    \
            for (int t2 = 0; t2 < 2; ++t2)                                       \
                _Pragma("unroll")                                                \
                for (int g = 0; g < 4; ++g)                                      \
                    _Pragma("unroll")                                            \
                    for (int h = 0; h < 2; ++h)                                  \
                        mma16816h(ACC[t2][g * 2 + h], ahf[t2], bh4[g][h], bh4[g][h + 2]); \
        }                                                                        \
        __syncthreads();                                                         \
    }

// GEMM2: fp32 out + bias
__global__ __launch_bounds__(256, 2) void gemm_mma(
    const __half* __restrict__ Ah, const __half* __restrict__ Bh,
    const float* __restrict__ bias, float* __restrict__ C, int N, int Kd)
{
    extern __shared__ __half smb[];
    __half* Ash = smb;
    __half* Bsh = Ash + 2 * BUFE;

    float acc[2][8][4];
#pragma unroll
    for (int a = 0; a < 2; a++)
#pragma unroll
        for (int b = 0; b < 8; b++)
#pragma unroll
            for (int c = 0; c < 4; c++) acc[a][b][c] = 0.f;

    GEMM_MAINLOOP(acc)

#pragma unroll
    for (int t2 = 0; t2 < 2; ++t2) {
        const int row = m0 + wm * 32 + t2 * 16 + (lane >> 2);
#pragma unroll
        for (int n8 = 0; n8 < 8; ++n8) {
            const int col = n0 + wn * 64 + n8 * 8 + (lane & 3) * 2;
            const float b0 = __ldg(bias + col);
            const float b1 = __ldg(bias + col + 1);
            float2 v0 = {acc[t2][n8][0] + b0, acc[t2][n8][1] + b1};
            float2 v1 = {acc[t2][n8][2] + b0, acc[t2][n8][3] + b1};
            *(float2*)(C + (size_t)row * N + col) = v0;
            *(float2*)(C + (size_t)(row + 8) * N + col) = v1;
        }
    }
}

// GEMM1: fused bias + RoPE + fp16 store to q (prescaled, permuted) / k / v.
__global__ __launch_bounds__(256, 2) void gemm_qkv(
    const __half* __restrict__ Ah, const __half* __restrict__ Bh,
    const float* __restrict__ bias,
    const float* __restrict__ cosNK, const float* __restrict__ sinNK,
    __half* __restrict__ qh, __half* __restrict__ kh, __half* __restrict__ vh,
    int Kd)
{
    extern __shared__ __half smb[];
    __half* Ash = smb;
    __half* Bsh = Ash + 2 * BUFE;

    float acc[2][8][4];
#pragma unroll
    for (int a = 0; a < 2; a++)
#pragma unroll
        for (int b = 0; b < 8; b++)
#pragma unroll
            for (int c = 0; c < 4; c++) acc[a][b][c] = 0.f;

    GEMM_MAINLOOP(acc)

    const float qs = 0.1118033988749895f * 1.4426950408889634f;  // scale*log2e
    const int region = n0 / DM;

#pragma unroll
    for (int t2 = 0; t2 < 2; ++t2) {
        const int rowa = m0 + wm * 32 + t2 * 16 + (lane >> 2);
        const int rowb = rowa + 8;
#pragma unroll
        for (int n8 = 0; n8 < 8; ++n8) {
            const int c0 = n0 + wn * 64 + n8 * 8 + (lane & 3) * 2;
            const int pc = c0 - region * DM;
            if (region == 2) {
                const float b0 = __ldg(bias + c0);
                const float b1 = __ldg(bias + c0 + 1);
                __half2 va = {__float2half_rn(acc[t2][n8][0] + b0),
                              __float2half_rn(acc[t2][n8][1] + b1)};
                __half2 vb = {__float2half_rn(acc[t2][n8][2] + b0),
                              __float2half_rn(acc[t2][n8][3] + b1)};
                *(__half2*)(vh + (size_t)rowa * DM + pc) = va;
                *(__half2*)(vh + (size_t)rowb * DM + pc) = vb;
            } else {
                const int head = pc / HK;
                const int j = (pc % HK) >> 1;
                const int orig0 = region * DM + head * HK + j;
                const float b0 = __ldg(bias + orig0);
                const float b1 = __ldg(bias + orig0 + 40);
                const float ca = __ldg(cosNK + rowa * HK + j);
                const float sa = __ldg(sinNK + rowa * HK + j);
                const float cb = __ldg(cosNK + rowb * HK + j);
                const float sb = __ldg(sinNK + rowb * HK + j);
                float x0 = acc[t2][n8][0] + b0, x1 = acc[t2][n8][1] + b1;
                float y0 = acc[t2][n8][2] + b0, y1 = acc[t2][n8][3] + b1;
                float o0a = x0 * ca - x1 * sa, o1a = x1 * ca + x0 * sa;
                float o0b = y0 * cb - y1 * sb, o1b = y1 * cb + y0 * sb;
                __half* dst = (region == 0) ? qh : kh;
                if (region == 0) { o0a *= qs; o1a *= qs; o0b *= qs; o1b *= qs; }
                __half2 va = {__float2half_rn(o0a), __float2half_rn(o1a)};
                __half2 vb = {__float2half_rn(o0b), __float2half_rn(o1b)};
                *(__half2*)(dst + (size_t)rowa * DM + pc) = va;
                *(__half2*)(dst + (size_t)rowb * DM + pc) = vb;
            }
        }
    }
}

// ---------------------------------------------------------------------------
// Tensor-core flash attention, fp16 1-term, 2 CTAs/SM.
// Softmax: packed-f32x2 exp2, warp-voted rescale skip when max is stable.
// ---------------------------------------------------------------------------
#define AP 88
#define KVB (64 * AP)
#define QTB (128 * AP)
#define ATT_SMEM ((QTB + 4 * KVB) * 2)

__global__ __launch_bounds__(256, 2) void attn_mma(
    const __half* __restrict__ qh, const __half* __restrict__ kh,
    const __half* __restrict__ vh, __half* __restrict__ oh)
{
    extern __shared__ __half smb2[];
    __half* Qh = smb2;            // [128][AP]  (resident)
    __half* KV = Qh + QTB;        // [2 buf][2 arr][64][AP]

    const int tid = threadIdx.x;
    const int lane = tid & 31;
    const int warp = tid >> 5;
    const int qt = blockIdx.x, head = blockIdx.y, seg = blockIdx.z;
    const int n0 = seg * SEGL + qt * 128;

    const uint32_t uKV = smem_u32(KV);

    auto issueKV = [&](int kb, int buf) {
        const int nk = seg * SEGL + kb * 64;
        const uint32_t bofs = (uint32_t)(buf * 2 * KVB) * 2;
#pragma unroll
        for (int i = 0; i < 3; ++i) {
            const int idx = tid + i * 256;
            if (idx < 640) {
                const int r = idx / 10, c = idx % 10;
                const uint32_t d = bofs + (uint32_t)(r * AP + c * 8) * 2 + uKV;
                const size_t g = (size_t)(nk + r) * DM + head * HK + c * 8;
                cpa16(d + 0 * KVB * 2, kh + g);
                cpa16(d + 1 * KVB * 2, vh + g);
            }
        }
        CP_COMMIT();
    };

    issueKV(0, 0);

#pragma unroll
    for (int i = 0; i < 5; ++i) {
        const int idx = tid + i * 256;
        const int r = idx / 10, c = idx % 10;
        const size_t g = (size_t)(n0 + r) * DM + head * HK + c * 8;
        *(uint4*)(Qh + r * AP + c * 8) = *(const uint4*)(qh + g);
    }
    __syncthreads();

    const uint32_t uQh = smem_u32(Qh);
    const uint32_t qoff = (uint32_t)((warp * 16 + (lane & 15)) * AP + ((lane >> 4) << 3)) * 2;
    const uint32_t koff = (uint32_t)((lane & 15) * AP + ((lane >> 4) << 3)) * 2;
    const uint32_t voff = (uint32_t)((((lane & 7) + (((lane >> 3) & 1) << 3)) * AP) + ((lane >> 4) << 3)) * 2;

    float of[10][4];
#pragma unroll
    for (int t = 0; t < 10; t++)
#pragma unroll
        for (int j = 0; j < 4; j++) of[t][j] = 0.f;
    float m_a = -1e30f, m_b = -1e30f, l_a = 0.f, l_b = 0.f;

    for (int kb = 0; kb < SEGL / 64; ++kb) {
        CP_WAIT0();
        __syncthreads();
        if (kb + 1 < SEGL / 64) issueKV(kb + 1, (kb + 1) & 1);

        const uint32_t bb = (uint32_t)((kb & 1) * 2 * KVB) * 2;
        const uint32_t uKh = uKV + bb;
        const uint32_t uVh = uKh + KVB * 2;

        // ---- S = Q @ K^T (1-term fp16); Q frags reloaded per ks ----
        float s[8][4];
#pragma unroll
        for (int t = 0; t < 8; t++)
#pragma unroll
            for (int j = 0; j < 4; j++) s[t][j] = 0.f;

#pragma unroll
        for (int ks = 0; ks < 5; ++ks) {
            uint32_t qf[4];
            ldsm4(qf, uQh + qoff + (uint32_t)(ks * 16 * 2));
#pragma unroll
            for (int g = 0; g < 4; ++g) {
                uint32_t kf[4];
                const uint32_t ka = koff + (uint32_t)((g * 16 * AP + ks * 16) * 2);
                ldsm4(kf, uKh + ka);
#pragma unroll
                for (int h = 0; h < 2; ++h)
                    mma16816h(s[2 * g + h], qf, kf[h], kf[h + 2]);
            }
        }

        // ---- online softmax (exp2 domain, voted rescale-skip) ----
        float rma = NEG_INF, rmb = NEG_INF;
#pragma unroll
        for (int t = 0; t < 8; t++) {
            rma = fmaxf(rma, fmaxf(s[t][0], s[t][1]));
            rmb = fmaxf(rmb, fmaxf(s[t][2], s[t][3]));
        }
        rma = fmaxf(rma, __shfl_xor_sync(0xffffffffu, rma, 1));
        rma = fmaxf(rma, __shfl_xor_sync(0xffffffffu, rma, 2));
        rmb = fmaxf(rmb, __shfl_xor_sync(0xffffffffu, rmb, 1));
        rmb = fmaxf(rmb, __shfl_xor_sync(0xffffffffu, rmb, 2));
        const float mna = fmaxf(m_a, rma), mnb = fmaxf(m_b, rmb);

        const bool stable = (mna == m_a) && (mnb == m_b);
        if (!__all_sync(0xffffffffu, stable)) {
            const float corra = exp2p(m_a - mna), corrb = exp2p(m_b - mnb);
            m_a = mna; m_b = mnb;
            l_a *= corra; l_b *= corrb;
#pragma unroll
            for (int t = 0; t < 10; t++) {
                of[t][0] *= corra;
                of[t][1] *= corra;
                of[t][2] *= corrb;
                of[t][3] *= corrb;
            }
        }

        float suma = 0.f, sumb = 0.f;
        uint32_t pha[8], phb[8];
#pragma unroll
        for (int t = 0; t < 8; t++) {
            float p0, p1, p2, p3;
            exp2pair(s[t][0] - m_a, s[t][1] - m_a, p0, p1);
            exp2pair(s[t][2] - m_b, s[t][3] - m_b, p2, p3);
            suma += p0 + p1;
            sumb += p2 + p3;
            pha[t] = pack_h2(__float2half_rn(p0), __float2half_rn(p1));
            phb[t] = pack_h2(__float2half_rn(p2), __float2half_rn(p3));
        }
        suma += __shfl_xor_sync(0xffffffffu, suma, 1);
        suma += __shfl_xor_sync(0xffffffffu, suma, 2);
        sumb += __shfl_xor_sync(0xffffffffu, sumb, 1);
        sumb += __shfl_xor_sync(0xffffffffu, sumb, 2);
        l_a += suma;
        l_b += sumb;

        // ---- O += P @ V (1-term fp16) ----
#pragma unroll
        for (int ks = 0; ks < 4; ++ks) {
            const uint32_t ah2[4] = {pha[2 * ks], phb[2 * ks], pha[2 * ks + 1], phb[2 * ks + 1]};
#pragma unroll
            for (int g = 0; g < 5; ++g) {
                uint32_t vf[4];
                const uint32_t va = voff + (uint32_t)((ks * 16 * AP + g * 16) * 2);
                ldsm4t(vf, uVh + va);
#pragma unroll
                for (int h = 0; h < 2; ++h)
                    mma16816h(of[2 * g + h], ah2, vf[2 * h], vf[2 * h + 1]);
            }
        }
    }

    // ---- write normalized output as fp16 (GEMM2 A operand) ----
    const float inva = 1.f / l_a, invb = 1.f / l_b;
    const int rowa = n0 + warp * 16 + (lane >> 2);
    const int rowb = rowa + 8;
#pragma unroll
    for (int t = 0; t < 10; t++) {
        const int col = head * HK + t * 8 + 2 * (lane & 3);
        __half2 vha = {__float2half_rn(of[t][0] * inva), __float2half_rn(of[t][1] * inva)};
        __half2 vhb = {__float2half_rn(of[t][2] * invb), __float2half_rn(of[t][3] * invb)};
        *(__half2*)(oh + (size_t)rowa * DM + col) = vha;
        *(__half2*)(oh + (size_t)rowb * DM + col) = vhb;
    }
}

// ---------------------------------------------------------------------------
// Launch
// ---------------------------------------------------------------------------
extern "C" void kernel_launch(void* const* d_in, const int* in_sizes, int n_in,
                              void* d_out, int out_size)
{
    const float* hidden = (const float*)d_in[0];
    const float* cosNK  = (const float*)d_in[1];
    const float* sinNK  = (const float*)d_in[2];
    const float* qkv_w  = (const float*)d_in[3];
    const float* qkv_b  = (const float*)d_in[4];
    const float* proj_w = (const float*)d_in[5];
    const float* proj_b = (const float*)d_in[6];
    float* out = (float*)d_out;

    __half *ah, *bh, *qh, *kh, *vh;
    cudaGetSymbolAddress((void**)&ah,  g_ah);
    cudaGetSymbolAddress((void**)&bh,  g_bh);
    cudaGetSymbolAddress((void**)&qh,  g_qh);
    cudaGetSymbolAddress((void**)&kh,  g_kh);
    cudaGetSymbolAddress((void**)&vh,  g_vh);

    cudaFuncSetAttribute(gemm_mma, cudaFuncAttributeMaxDynamicSharedMemorySize, GSMEM);
    cudaFuncSetAttribute(gemm_qkv, cudaFuncAttributeMaxDynamicSharedMemorySize, GSMEM);
    cudaFuncSetAttribute(attn_mma, cudaFuncAttributeMaxDynamicSharedMemorySize, ATT_SMEM);

    const int n4 = NTOK * DM / 4;

    // 1) prep GEMM1: convert hidden (fp16), transpose+permute qkv_w (fp16)
    cvt_h_kernel<<<(n4 + 255) / 256, 256>>>(hidden, ah, n4);
    transpose_h_kernel<<<dim3(3 * DM / 32, DM / 32), dim3(32, 8)>>>(qkv_w, bh, DM, 3 * DM, 1);

    // 2) fused GEMM1 + bias + RoPE -> q (prescaled, permuted), k (permuted), v
    gemm_qkv<<<dim3(3 * DM / 128, NTOK / 128), 256, GSMEM>>>(
        ah, bh, qkv_b, cosNK, sinNK, qh, kh, vh, DM);

    // 3) attention (fp16 1-term, 2 CTAs/SM); writes GEMM2's A (fp16)
    attn_mma<<<dim3(SEGL / 128, NH, NSEGS), 256, ATT_SMEM>>>(qh, kh, vh, ah);

    // 4) prep GEMM2 weights (fp16, no permute)
    transpose_h_kernel<<<dim3(DM / 32, DM / 32), dim3(32, 8)>>>(proj_w, bh, DM, DM, 0);

    // 5) out = attn_out @ proj_w + proj_b  (fp16 1-term)
    gemm_mma<<<dim3(DM / 128, NTOK / 128), 256, GSMEM>>>(
        ah, bh, proj_b, out, DM, DM);
}

// round 17
// speedup vs baseline: 2.7189x; 1.0138x over previous
#include <cuda_runtime.h>
#include <cuda_fp16.h>
#include <cstdint>

// Problem constants (fixed by reference setup_inputs)
#define NTOK 16384
#define DM   1280
#define NH   16
#define HK   80
#define NSEGS 8
#define SEGL 2048

#define NEG_INF (__int_as_float(0xff800000))

// Scratch (allocation-free rule: __device__ globals)
__device__ __half g_ah[(size_t)NTOK * DM];                // GEMM A fp16 (hidden, then attn-out)
__device__ __half g_bh[(size_t)3 * DM * DM];              // W^T fp16 [N][K]
__device__ __half g_qh[(size_t)NTOK * DM];                // q (rope'd, prescaled, PERMUTED cols)
__device__ __half g_kh[(size_t)NTOK * DM];                // k (rope'd, PERMUTED cols)
__device__ __half g_vh[(size_t)NTOK * DM];                // v (natural cols)

// ---------------------------------------------------------------------------
// helpers
// ---------------------------------------------------------------------------
__device__ __forceinline__ uint32_t smem_u32(const void* p) {
    uint32_t a;
    asm("{ .reg .u64 t; cvta.to.shared.u64 t, %1; cvt.u32.u64 %0, t; }" : "=r"(a) : "l"(p));
    return a;
}
__device__ __forceinline__ void ldsm4(uint32_t* r, uint32_t addr) {
    asm volatile("ldmatrix.sync.aligned.m8n8.x4.shared.b16 {%0,%1,%2,%3}, [%4];"
                 : "=r"(r[0]), "=r"(r[1]), "=r"(r[2]), "=r"(r[3]) : "r"(addr));
}
__device__ __forceinline__ void ldsm4t(uint32_t* r, uint32_t addr) {
    asm volatile("ldmatrix.sync.aligned.m8n8.x4.trans.shared.b16 {%0,%1,%2,%3}, [%4];"
                 : "=r"(r[0]), "=r"(r[1]), "=r"(r[2]), "=r"(r[3]) : "r"(addr));
}
// fp16 mma
__device__ __forceinline__ void mma16816h(float* d, const uint32_t* a, uint32_t b0, uint32_t b1) {
    asm volatile("mma.sync.aligned.m16n8k16.row.col.f32.f16.f16.f32 "
                 "{%0,%1,%2,%3}, {%4,%5,%6,%7}, {%8,%9}, {%0,%1,%2,%3};"
                 : "+f"(d[0]), "+f"(d[1]), "+f"(d[2]), "+f"(d[3])
                 : "r"(a[0]), "r"(a[1]), "r"(a[2]), "r"(a[3]), "r"(b0), "r"(b1));
}
__device__ __forceinline__ uint32_t pack_h2(__half lo, __half hi) {
    __half2 v = {lo, hi};
    return *(uint32_t*)&v;
}
__device__ __forceinline__ void cpa16(uint32_t dst, const void* src) {
    asm volatile("cp.async.cg.shared.global [%0], [%1], 16;" :: "r"(dst), "l"(src));
}
#define CP_COMMIT() asm volatile("cp.async.commit_group;")
#define CP_WAIT0()  asm volatile("cp.async.wait_group 0;")
#define CP_WAIT1()  asm volatile("cp.async.wait_group 1;")

// FMA-pipe exp2 for t <= 0 (clamped), ~3e-6 rel error (scalar; used for corr)
__device__ __forceinline__ float exp2p(float t) {
    t = fmaxf(t, -126.f);
    const float z = t + 12582912.f;
    const int n = __float_as_int(z) - 0x4B400000;
    const float f = t - (z - 12582912.f);
    float r = 1.3333558146e-3f;
    r = fmaf(r, f, 9.6181291076e-3f);
    r = fmaf(r, f, 5.5504108664e-2f);
    r = fmaf(r, f, 2.4022650695e-1f);
    r = fmaf(r, f, 6.9314718055e-1f);
    r = fmaf(r, f, 1.0f);
    return __int_as_float(__float_as_int(r) + (n << 23));
}

// packed f32x2 helpers
__device__ __forceinline__ uint64_t pack2f(float lo, float hi) {
    uint64_t r;
    asm("mov.b64 %0, {%1, %2};" : "=l"(r) : "f"(lo), "f"(hi));
    return r;
}
__device__ __forceinline__ void unpack2f(uint64_t v, float& lo, float& hi) {
    asm("mov.b64 {%0, %1}, %2;" : "=f"(lo), "=f"(hi) : "l"(v));
}
__device__ __forceinline__ uint64_t add2(uint64_t a, uint64_t b) {
    uint64_t d;
    asm("add.rn.f32x2 %0, %1, %2;" : "=l"(d) : "l"(a), "l"(b));
    return d;
}
__device__ __forceinline__ uint64_t fma2c(uint64_t a, uint64_t b, uint64_t c) {
    uint64_t d;
    asm("fma.rn.f32x2 %0, %1, %2, %3;" : "=l"(d) : "l"(a), "l"(b), "l"(c));
    return d;
}
#define PK2(x) ((((uint64_t)(x)) << 32) | (uint64_t)(x))
// exp2 of a pair, NO clamp (inputs in [-126, 0] guaranteed by softmax)
__device__ __forceinline__ void exp2pair(float t0, float t1, float& o0, float& o1) {
    const uint64_t tt = pack2f(t0, t1);
    const uint64_t zz = add2(tt, PK2(0x4B400000u));
    const uint64_t ww = add2(zz, PK2(0xCB400000u));
    const uint64_t ff = fma2c(ww, PK2(0xBF800000u), tt);
    float z0, z1;
    unpack2f(zz, z0, z1);
    const int n0 = __float_as_int(z0) - 0x4B400000;
    const int n1 = __float_as_int(z1) - 0x4B400000;
    uint64_t rr = PK2(0x3AAEBD1Au);
    rr = fma2c(rr, ff, PK2(0x3C1D94FCu));
    rr = fma2c(rr, ff, PK2(0x3D6357CFu));
    rr = fma2c(rr, ff, PK2(0x3E75FDF0u));
    rr = fma2c(rr, ff, PK2(0x3F317218u));
    rr = fma2c(rr, ff, PK2(0x3F800000u));
    float r0, r1;
    unpack2f(rr, r0, r1);
    o0 = __int_as_float(__float_as_int(r0) + (n0 << 23));
    o1 = __int_as_float(__float_as_int(r1) + (n1 << 23));
}

// ---------------------------------------------------------------------------
// convert fp32 -> fp16, vectorized by 4
// ---------------------------------------------------------------------------
__global__ __launch_bounds__(256) void cvt_h_kernel(
    const float* __restrict__ in, __half* __restrict__ hi, int n4)
{
    const int i = blockIdx.x * blockDim.x + threadIdx.x;
    if (i >= n4) return;
    const float4 v = ((const float4*)in)[i];
    __half2 hp0 = {__float2half_rn(v.x), __float2half_rn(v.y)};
    __half2 hp1 = {__float2half_rn(v.z), __float2half_rn(v.w)};
    ((__half2*)hi)[i * 2 + 0] = hp0;
    ((__half2*)hi)[i * 2 + 1] = hp1;
}

// ---------------------------------------------------------------------------
// transpose: W[K][N] row-major -> WT [N][K] fp16 (optional q/k RoPE permute)
// ---------------------------------------------------------------------------
__global__ void transpose_h_kernel(
    const float* __restrict__ W, __half* __restrict__ bh, int Krows, int Ncols,
    int permute)
{
    __shared__ float t[32][33];
    const int bx = blockIdx.x * 32;
    const int by = blockIdx.y * 32;
    const int x = threadIdx.x, y = threadIdx.y;
#pragma unroll
    for (int i = 0; i < 32; i += 8)
        t[y + i][x] = W[(size_t)(by + y + i) * Ncols + bx + x];
    __syncthreads();
#pragma unroll
    for (int i = 0; i < 32; i += 8) {
        int r = bx + y + i;
        if (permute && r < 2 * DM) {
            const int head = r / HK;
            const int jp = r % HK;
            const int p = (jp < 40) ? (2 * jp) : (2 * (jp - 40) + 1);
            r = head * HK + p;
        }
        bh[(size_t)r * Krows + by + x] = __float2half_rn(t[x][y + i]);
    }
}

// ---------------------------------------------------------------------------
// GEMM mainloop (shared): fp16 1-term C = Ah @ Bh^T, 3-stage cp.async ring.
// ---------------------------------------------------------------------------
#define GP 40
#define BUFE (128 * GP)
#define NSTG 3
#define GSMEM (2 * NSTG * BUFE * 2)

#define GEMM_MAINLOOP(ACC)                                                       \
    const int tid = threadIdx.x;                                                 \
    const int lane = tid & 31;                                                   \
    const int warp = tid >> 5;                                                   \
    const int wm = warp >> 1;                                                    \
    const int wn = warp & 1;                                                     \
    const int m0 = blockIdx.y * 128;                                             \
    const int n0 = blockIdx.x * 128;                                             \
    const int r0 = tid >> 2;                                                     \
    const int sg = (tid & 3) * 8;                                                \
    const __half* pAh = Ah + (size_t)(m0 + r0) * Kd + sg;                        \
    const __half* pBh = Bh + (size_t)(n0 + r0) * Kd + sg;                        \
    const size_t rstep = (size_t)64 * Kd;                                        \
    const uint32_t uAsh = smem_u32(Ash);                                         \
    const uint32_t uBsh = smem_u32(Bsh);                                         \
    auto issue = [&](int k0, int stg) {                                          \
        const uint32_t o0 = (uint32_t)(stg * BUFE + r0 * GP + sg) * 2;           \
        const uint32_t o1 = (uint32_t)(stg * BUFE + (r0 + 64) * GP + sg) * 2;    \
        cpa16(uAsh + o0, pAh + k0);  cpa16(uAsh + o1, pAh + k0 + rstep);         \
        cpa16(uBsh + o0, pBh + k0);  cpa16(uBsh + o1, pBh + k0 + rstep);         \
        CP_COMMIT();                                                             \
    };                                                                           \
    const uint32_t aoff = (uint32_t)((wm * 32 + (lane & 15)) * GP + ((lane >> 4) << 3)) * 2; \
    const uint32_t boff = (uint32_t)((wn * 64 + (lane & 15)) * GP + ((lane >> 4) << 3)) * 2; \
    const int NT = Kd >> 5;                                                      \
    issue(0, 0);                                                                 \
    if (NT > 1) issue(32, 1);                                                    \
    int stg_ = 0;                                                                \
    for (int t = 0; t < NT; ++t) {                                               \
        if (t + 1 < NT) CP_WAIT1(); else CP_WAIT0();                             \
        __syncthreads();                                                         \
        if (t + 2 < NT) issue((t + 2) << 5, (stg_ + 2) % NSTG);                  \
        const uint32_t bb = (uint32_t)(stg_ * BUFE * 2);                         \
        _Pragma("unroll")                                                        \
        for (int ks = 0; ks < 2; ++ks) {                                         \
            const uint32_t kso = (uint32_t)(ks * 16 * 2);                        \
            uint32_t ahf[2][4];                                                  \
            _Pragma("unroll")                                                    \
            for (int t2 = 0; t2 < 2; ++t2)                                       \
                ldsm4(ahf[t2], uAsh + bb + aoff + kso + (uint32_t)(t2 * 16 * GP * 2)); \
            uint32_t bh4[4][4];                                                  \
            _Pragma("unroll")                                                    \
            for (int g = 0; g < 4; ++g)                                          \
                ldsm4(bh4[g], uBsh + bb + boff + kso + (uint32_t)(g * 16 * GP * 2)); \
            _Pragma("unroll")                                                    \
            for (int t2 = 0; t2 < 2; ++t2)                                       \
                _Pragma("unroll")                                                \
                for (int g = 0; g < 4; ++g)                                      \
                    _Pragma("unroll")                                            \
                    for (int h = 0; h < 2; ++h)                                  \
                        mma16816h(ACC[t2][g * 2 + h], ahf[t2], bh4[g][h], bh4[g][h + 2]); \
        }                                                                        \
        stg_ = (stg_ + 1) % NSTG;                                                \
    }

// GEMM2: fp32 out + bias
__global__ __launch_bounds__(256, 2) void gemm_mma(
    const __half* __restrict__ Ah, const __half* __restrict__ Bh,
    const float* __restrict__ bias, float* __restrict__ C, int N, int Kd)
{
    extern __shared__ __half smb[];
    __half* Ash = smb;
    __half* Bsh = Ash + NSTG * BUFE;

    float acc[2][8][4];
#pragma unroll
    for (int a = 0; a < 2; a++)
#pragma unroll
        for (int b = 0; b < 8; b++)
#pragma unroll
            for (int c = 0; c < 4; c++) acc[a][b][c] = 0.f;

    GEMM_MAINLOOP(acc)

#pragma unroll
    for (int t2 = 0; t2 < 2; ++t2) {
        const int row = m0 + wm * 32 + t2 * 16 + (lane >> 2);
#pragma unroll
        for (int n8 = 0; n8 < 8; ++n8) {
            const int col = n0 + wn * 64 + n8 * 8 + (lane & 3) * 2;
            const float b0 = __ldg(bias + col);
            const float b1 = __ldg(bias + col + 1);
            float2 v0 = {acc[t2][n8][0] + b0, acc[t2][n8][1] + b1};
            float2 v1 = {acc[t2][n8][2] + b0, acc[t2][n8][3] + b1};
            *(float2*)(C + (size_t)row * N + col) = v0;
            *(float2*)(C + (size_t)(row + 8) * N + col) = v1;
        }
    }
}

// GEMM1: fused bias + RoPE + fp16 store to q (prescaled, permuted) / k / v.
__global__ __launch_bounds__(256, 2) void gemm_qkv(
    const __half* __restrict__ Ah, const __half* __restrict__ Bh,
    const float* __restrict__ bias,
    const float* __restrict__ cosNK, const float* __restrict__ sinNK,
    __half* __restrict__ qh, __half* __restrict__ kh, __half* __restrict__ vh,
    int Kd)
{
    extern __shared__ __half smb[];
    __half* Ash = smb;
    __half* Bsh = Ash + NSTG * BUFE;

    float acc[2][8][4];
#pragma unroll
    for (int a = 0; a < 2; a++)
#pragma unroll
        for (int b = 0; b < 8; b++)
#pragma unroll
            for (int c = 0; c < 4; c++) acc[a][b][c] = 0.f;

    GEMM_MAINLOOP(acc)

    const float qs = 0.1118033988749895f * 1.4426950408889634f;  // scale*log2e
    const int region = n0 / DM;

#pragma unroll
    for (int t2 = 0; t2 < 2; ++t2) {
        const int rowa = m0 + wm * 32 + t2 * 16 + (lane >> 2);
        const int rowb = rowa + 8;
#pragma unroll
        for (int n8 = 0; n8 < 8; ++n8) {
            const int c0 = n0 + wn * 64 + n8 * 8 + (lane & 3) * 2;
            const int pc = c0 - region * DM;
            if (region == 2) {
                const float b0 = __ldg(bias + c0);
                const float b1 = __ldg(bias + c0 + 1);
                __half2 va = {__float2half_rn(acc[t2][n8][0] + b0),
                              __float2half_rn(acc[t2][n8][1] + b1)};
                __half2 vb = {__float2half_rn(acc[t2][n8][2] + b0),
                              __float2half_rn(acc[t2][n8][3] + b1)};
                *(__half2*)(vh + (size_t)rowa * DM + pc) = va;
                *(__half2*)(vh + (size_t)rowb * DM + pc) = vb;
            } else {
                const int head = pc / HK;
                const int j = (pc % HK) >> 1;
                const int orig0 = region * DM + head * HK + j;
                const float b0 = __ldg(bias + orig0);
                const float b1 = __ldg(bias + orig0 + 40);
                const float ca = __ldg(cosNK + rowa * HK + j);
                const float sa = __ldg(sinNK + rowa * HK + j);
                const float cb = __ldg(cosNK + rowb * HK + j);
                const float sb = __ldg(sinNK + rowb * HK + j);
                float x0 = acc[t2][n8][0] + b0, x1 = acc[t2][n8][1] + b1;
                float y0 = acc[t2][n8][2] + b0, y1 = acc[t2][n8][3] + b1;
                float o0a = x0 * ca - x1 * sa, o1a = x1 * ca + x0 * sa;
                float o0b = y0 * cb - y1 * sb, o1b = y1 * cb + y0 * sb;
                __half* dst = (region == 0) ? qh : kh;
                if (region == 0) { o0a *= qs; o1a *= qs; o0b *= qs; o1b *= qs; }
                __half2 va = {__float2half_rn(o0a), __float2half_rn(o1a)};
                __half2 vb = {__float2half_rn(o0b), __float2half_rn(o1b)};
                *(__half2*)(dst + (size_t)rowa * DM + pc) = va;
                *(__half2*)(dst + (size_t)rowb * DM + pc) = vb;
            }
        }
    }
}

// ---------------------------------------------------------------------------
// Tensor-core flash attention, fp16 1-term, 2 CTAs/SM, 3-buffer KV ring.
// ---------------------------------------------------------------------------
#define AP 88
#define KVB (64 * AP)
#define QTB (128 * AP)
#define NKBUF 3
#define ATT_SMEM ((QTB + 2 * NKBUF * KVB) * 2)

__global__ __launch_bounds__(256, 2) void attn_mma(
    const __half* __restrict__ qh, const __half* __restrict__ kh,
    const __half* __restrict__ vh, __half* __restrict__ oh)
{
    extern __shared__ __half smb2[];
    __half* Qh = smb2;            // [128][AP]  (resident)
    __half* KV = Qh + QTB;        // [NKBUF][2 arr][64][AP]

    const int tid = threadIdx.x;
    const int lane = tid & 31;
    const int warp = tid >> 5;
    const int qt = blockIdx.x, head = blockIdx.y, seg = blockIdx.z;
    const int n0 = seg * SEGL + qt * 128;

    const uint32_t uKV = smem_u32(KV);

    auto issueKV = [&](int kb, int buf) {
        const int nk = seg * SEGL + kb * 64;
        const uint32_t bofs = (uint32_t)(buf * 2 * KVB) * 2;
#pragma unroll
        for (int i = 0; i < 3; ++i) {
            const int idx = tid + i * 256;
            if (idx < 640) {
                const int r = idx / 10, c = idx % 10;
                const uint32_t d = bofs + (uint32_t)(r * AP + c * 8) * 2 + uKV;
                const size_t g = (size_t)(nk + r) * DM + head * HK + c * 8;
                cpa16(d + 0 * KVB * 2, kh + g);
                cpa16(d + 1 * KVB * 2, vh + g);
            }
        }
        CP_COMMIT();
    };

    issueKV(0, 0);
    issueKV(1, 1);

#pragma unroll
    for (int i = 0; i < 5; ++i) {
        const int idx = tid + i * 256;
        const int r = idx / 10, c = idx % 10;
        const size_t g = (size_t)(n0 + r) * DM + head * HK + c * 8;
        *(uint4*)(Qh + r * AP + c * 8) = *(const uint4*)(qh + g);
    }
    __syncthreads();

    const uint32_t uQh = smem_u32(Qh);
    const uint32_t qoff = (uint32_t)((warp * 16 + (lane & 15)) * AP + ((lane >> 4) << 3)) * 2;
    const uint32_t koff = (uint32_t)((lane & 15) * AP + ((lane >> 4) << 3)) * 2;
    const uint32_t voff = (uint32_t)((((lane & 7) + (((lane >> 3) & 1) << 3)) * AP) + ((lane >> 4) << 3)) * 2;

    float of[10][4];
#pragma unroll
    for (int t = 0; t < 10; t++)
#pragma unroll
        for (int j = 0; j < 4; j++) of[t][j] = 0.f;
    float m_a = -1e30f, m_b = -1e30f, l_a = 0.f, l_b = 0.f;

    int buf = 0;
    for (int kb = 0; kb < SEGL / 64; ++kb) {
        if (kb + 1 < SEGL / 64) CP_WAIT1(); else CP_WAIT0();
        __syncthreads();
        if (kb + 2 < SEGL / 64) issueKV(kb + 2, (buf + 2) % NKBUF);

        const uint32_t bb = (uint32_t)(buf * 2 * KVB) * 2;
        const uint32_t uKh = uKV + bb;
        const uint32_t uVh = uKh + KVB * 2;

        // ---- S = Q @ K^T (1-term fp16); Q frags reloaded per ks ----
        float s[8][4];
#pragma unroll
        for (int t = 0; t < 8; t++)
#pragma unroll
            for (int j = 0; j < 4; j++) s[t][j] = 0.f;

#pragma unroll
        for (int ks = 0; ks < 5; ++ks) {
            uint32_t qf[4];
            ldsm4(qf, uQh + qoff + (uint32_t)(ks * 16 * 2));
#pragma unroll
            for (int g = 0; g < 4; ++g) {
                uint32_t kf[4];
                const uint32_t ka = koff + (uint32_t)((g * 16 * AP + ks * 16) * 2);
                ldsm4(kf, uKh + ka);
#pragma unroll
                for (int h = 0; h < 2; ++h)
                    mma16816h(s[2 * g + h], qf, kf[h], kf[h + 2]);
            }
        }

        // ---- online softmax (exp2 domain, voted rescale-skip) ----
        float rma = NEG_INF, rmb = NEG_INF;
#pragma unroll
        for (int t = 0; t < 8; t++) {
            rma = fmaxf(rma, fmaxf(s[t][0], s[t][1]));
            rmb = fmaxf(rmb, fmaxf(s[t][2], s[t][3]));
        }
        rma = fmaxf(rma, __shfl_xor_sync(0xffffffffu, rma, 1));
        rma = fmaxf(rma, __shfl_xor_sync(0xffffffffu, rma, 2));
        rmb = fmaxf(rmb, __shfl_xor_sync(0xffffffffu, rmb, 1));
        rmb = fmaxf(rmb, __shfl_xor_sync(0xffffffffu, rmb, 2));
        const float mna = fmaxf(m_a, rma), mnb = fmaxf(m_b, rmb);

        const bool stable = (mna == m_a) && (mnb == m_b);
        if (!__all_sync(0xffffffffu, stable)) {
            const float corra = exp2p(m_a - mna), corrb = exp2p(m_b - mnb);
            m_a = mna; m_b = mnb;
            l_a *= corra; l_b *= corrb;
#pragma unroll
            for (int t = 0; t < 10; t++) {
                of[t][0] *= corra;
                of[t][1] *= corra;
                of[t][2] *= corrb;
                of[t][3] *= corrb;
            }
        }

        float suma = 0.f, sumb = 0.f;
        uint32_t pha[8], phb[8];
#pragma unroll
        for (int t = 0; t < 8; t++) {
            float p0, p1, p2, p3;
            exp2pair(s[t][0] - m_a, s[t][1] - m_a, p0, p1);
            exp2pair(s[t][2] - m_b, s[t][3] - m_b, p2, p3);
            suma += p0 + p1;
            sumb += p2 + p3;
            pha[t] = pack_h2(__float2half_rn(p0), __float2half_rn(p1));
            phb[t] = pack_h2(__float2half_rn(p2), __float2half_rn(p3));
        }
        suma += __shfl_xor_sync(0xffffffffu, suma, 1);
        suma += __shfl_xor_sync(0xffffffffu, suma, 2);
        sumb += __shfl_xor_sync(0xffffffffu, sumb, 1);
        sumb += __shfl_xor_sync(0xffffffffu, sumb, 2);
        l_a += suma;
        l_b += sumb;

        // ---- O += P @ V (1-term fp16) ----
#pragma unroll
        for (int ks = 0; ks < 4; ++ks) {
            const uint32_t ah2[4] = {pha[2 * ks], phb[2 * ks], pha[2 * ks + 1], phb[2 * ks + 1]};
#pragma unroll
            for (int g = 0; g < 5; ++g) {
                uint32_t vf[4];
                const uint32_t va = voff + (uint32_t)((ks * 16 * AP + g * 16) * 2);
                ldsm4t(vf, uVh + va);
#pragma unroll
                for (int h = 0; h < 2; ++h)
                    mma16816h(of[2 * g + h], ah2, vf[2 * h], vf[2 * h + 1]);
            }
        }
        buf = (buf + 1) % NKBUF;
    }

    // ---- write normalized output as fp16 (GEMM2 A operand) ----
    const float inva = 1.f / l_a, invb = 1.f / l_b;
    const int rowa = n0 + warp * 16 + (lane >> 2);
    const int rowb = rowa + 8;
#pragma unroll
    for (int t = 0; t < 10; t++) {
        const int col = head * HK + t * 8 + 2 * (lane & 3);
        __half2 vha = {__float2half_rn(of[t][0] * inva), __float2half_rn(of[t][1] * inva)};
        __half2 vhb = {__float2half_rn(of[t][2] * invb), __float2half_rn(of[t][3] * invb)};
        *(__half2*)(oh + (size_t)rowa * DM + col) = vha;
        *(__half2*)(oh + (size_t)rowb * DM + col) = vhb;
    }
}

// ---------------------------------------------------------------------------
// Launch
// ---------------------------------------------------------------------------
extern "C" void kernel_launch(void* const* d_in, const int* in_sizes, int n_in,
                              void* d_out, int out_size)
{
    const float* hidden = (const float*)d_in[0];
    const float* cosNK  = (const float*)d_in[1];
    const float* sinNK  = (const float*)d_in[2];
    const float* qkv_w  = (const float*)d_in[3];
    const float* qkv_b  = (const float*)d_in[4];
    const float* proj_w = (const float*)d_in[5];
    const float* proj_b = (const float*)d_in[6];
    float* out = (float*)d_out;

    __half *ah, *bh, *qh, *kh, *vh;
    cudaGetSymbolAddress((void**)&ah,  g_ah);
    cudaGetSymbolAddress((void**)&bh,  g_bh);
    cudaGetSymbolAddress((void**)&qh,  g_qh);
    cudaGetSymbolAddress((void**)&kh,  g_kh);
    cudaGetSymbolAddress((void**)&vh,  g_vh);

    cudaFuncSetAttribute(gemm_mma, cudaFuncAttributeMaxDynamicSharedMemorySize, GSMEM);
    cudaFuncSetAttribute(gemm_qkv, cudaFuncAttributeMaxDynamicSharedMemorySize, GSMEM);
    cudaFuncSetAttribute(attn_mma, cudaFuncAttributeMaxDynamicSharedMemorySize, ATT_SMEM);

    const int n4 = NTOK * DM / 4;

    // 1) prep GEMM1: convert hidden (fp16), transpose+permute qkv_w (fp16)
    cvt_h_kernel<<<(n4 + 255) / 256, 256>>>(hidden, ah, n4);
    transpose_h_kernel<<<dim3(3 * DM / 32, DM / 32), dim3(32, 8)>>>(qkv_w, bh, DM, 3 * DM, 1);

    // 2) fused GEMM1 + bias + RoPE -> q (prescaled, permuted), k (permuted), v
    gemm_qkv<<<dim3(3 * DM / 128, NTOK / 128), 256, GSMEM>>>(
        ah, bh, qkv_b, cosNK, sinNK, qh, kh, vh, DM);

    // 3) attention (fp16 1-term, 2 CTAs/SM, 3-buf ring); writes GEMM2's A
    attn_mma<<<dim3(SEGL / 128, NH, NSEGS), 256, ATT_SMEM>>>(qh, kh, vh, ah);

    // 4) prep GEMM2 weights (fp16, no permute)
    transpose_h_kernel<<<dim3(DM / 32, DM / 32), dim3(32, 8)>>>(proj_w, bh, DM, DM, 0);

    // 5) out = attn_out @ proj_w + proj_b  (fp16 1-term)
    gemm_mma<<<dim3(DM / 128, NTOK / 128), 256, GSMEM>>>(
        ah, bh, proj_b, out, DM, DM);
}